// round 2
// baseline (speedup 1.0000x reference)
#include <cuda_runtime.h>
#include <cuda_bf16.h>
#include <math.h>

// Problem sizes (fixed by the reference)
#define BSZ 2048
#define GG  64
#define DD  512
#define DD2 (DD * DD)

// ---------------------------------------------------------------------------
// Scratch (device globals: allocation-free, graph-capturable)
// g_L : per-gaussian Cholesky factor L, COLUMN-major  (L(i,j) at j*D+i, i>=j)
// g_W : per-gaussian V = (L^T)^{-1}, ROW-major        (V(d,n) at d*D+n, d<=n)
// ---------------------------------------------------------------------------
__device__ __align__(16) float g_L[GG * DD2];      // 64 MB
__device__ __align__(16) float g_W[GG * DD2];      // 64 MB
__device__ __align__(16) float g_u[GG * DD];       // u_g = mu_g^T V_g
__device__ __align__(16) float g_dist[BSZ * GG];   // dist[b][g]

// ---------------------------------------------------------------------------
// Kernel 1: Cholesky, one block per gaussian.
// Left-looking, column-major. 1024 threads: (row = tid&511, half = tid>>9)
// split the dot product over j into even/odd halves, combined via shared mem.
// ---------------------------------------------------------------------------
__global__ __launch_bounds__(1024, 1)
void cholesky_kernel(const float* __restrict__ covs)
{
    const int g = blockIdx.x;
    float* a = g_L + (size_t)g * DD2;
    const float* c = covs + (size_t)g * DD2;
    const int tid  = threadIdx.x;
    const int row  = tid & 511;
    const int half = tid >> 9;

    // copy cov -> a (symmetric, so col-major == row-major copy)
    for (int idx = tid; idx < DD2; idx += 1024) a[idx] = c[idx];
    __syncthreads();

    __shared__ float s1[DD];
    __shared__ float sdiag;

    for (int k = 0; k < DD; ++k) {
        const int i = k + row;
        float s = 0.f;
        if (i < DD) {
            #pragma unroll 4
            for (int j = half; j < k; j += 2)
                s += a[j * DD + i] * a[j * DD + k];
        }
        if (half == 1 && i < DD) s1[row] = s;
        __syncthreads();

        float tot = 0.f;
        if (half == 0 && i < DD) {
            tot = s + s1[row];
            if (row == 0) sdiag = sqrtf(a[k * DD + k] - tot);
        }
        __syncthreads();

        if (half == 0 && i < DD) {
            if (row == 0) a[k * DD + k] = sdiag;
            else          a[k * DD + i] = (a[k * DD + i] - tot) * (1.0f / sdiag);
        }
        __syncthreads();
    }
}

// ---------------------------------------------------------------------------
// Kernel 2: V = (L^T)^{-1} (upper triangular), one block per gaussian.
// Backward substitution: V(i,j) = -(sum_{k=i+1}^{j} L(k,i) * V(k,j)) / L(i,i)
// Thread (j = tid&511) owns column j; k-sum split across half = tid>>9.
// L column i is staged in shared each step (coalesced load).
// V stored ROW-major -> both the V(k,j) reads and V(i,j) writes are coalesced.
// Also writes explicit zeros below the diagonal (GEMM reads full tiles).
// ---------------------------------------------------------------------------
__global__ __launch_bounds__(1024, 1)
void trinv_kernel()
{
    const int g = blockIdx.x;
    const float* a = g_L + (size_t)g * DD2;   // column-major L
    float* W = g_W + (size_t)g * DD2;         // row-major V
    const int tid  = threadIdx.x;
    const int j    = tid & 511;
    const int half = tid >> 9;

    __shared__ float shL[DD];
    __shared__ float spart[DD];

    if (half == 0) W[j * DD + j] = 1.0f / a[j * DD + j];
    __syncthreads();

    for (int i = DD - 1; i >= 0; --i) {
        // stage column i of L (rows i..D-1): shL[k-i] = L(k,i)
        for (int k = i + tid; k < DD; k += 1024) shL[k - i] = a[i * DD + k];
        __syncthreads();

        float s = 0.f;
        if (j > i) {
            #pragma unroll 4
            for (int k = i + 1 + half; k <= j; k += 2)
                s += shL[k - i] * W[k * DD + j];
        }
        if (half == 1 && j > i) spart[j] = s;
        __syncthreads();

        if (half == 0) {
            if (j > i)      W[i * DD + j] = -(s + spart[j]) * (1.0f / shL[0]);
            else if (j < i) W[i * DD + j] = 0.f;
        }
        __syncthreads();
    }
}

// ---------------------------------------------------------------------------
// Kernel 3: u_g[n] = sum_{d<=n} mu_g[d] * V_g(d,n).  64 blocks x 512 threads.
// ---------------------------------------------------------------------------
__global__ __launch_bounds__(512, 2)
void u_kernel(const float* __restrict__ mus)
{
    const int g = blockIdx.x;
    const int n = threadIdx.x;
    const float* W  = g_W + (size_t)g * DD2;
    const float* mu = mus + (size_t)g * DD;
    float s = 0.f;
    #pragma unroll 4
    for (int d = 0; d <= n; ++d) s += mu[d] * W[d * DD + n];
    g_u[g * DD + n] = s;
}

// ---------------------------------------------------------------------------
// Kernel 4: triangular GEMM + fused dist epilogue.
// Block = (g, b-tile of 128). Loops n-tiles of 64; for each n-tile the k-loop
// runs only d < n0+64 (V upper triangular -> half the dense flops).
// 256 threads, micro-tile 8(b) x 4(n). dist written once per (b,g): no atomics.
// ---------------------------------------------------------------------------
#define TB 128
#define TN 64
#define TK 16

__global__ __launch_bounds__(256, 2)
void gemm_dist_kernel(const float* __restrict__ X)
{
    const int g  = blockIdx.x;
    const int b0 = blockIdx.y * TB;
    const float* W = g_W + (size_t)g * DD2;

    __shared__ __align__(16) float Xs[TK][TB + 4];   // 132 stride
    __shared__ __align__(16) float Vs[TK][TN + 4];   // 68 stride
    __shared__ float red[TB][17];

    const int tx = threadIdx.x & 15;   // n group (4 cols each)
    const int ty = threadIdx.x >> 4;   // b group (8 rows each)

    float distacc[8];
    #pragma unroll
    for (int r = 0; r < 8; ++r) distacc[r] = 0.f;

    for (int nt = 0; nt < DD / TN; ++nt) {
        const int n0   = nt * TN;
        const int kend = n0 + TN;          // triangular bound
        float acc[8][4];
        #pragma unroll
        for (int r = 0; r < 8; ++r)
            #pragma unroll
            for (int cc = 0; cc < 4; ++cc) acc[r][cc] = 0.f;

        for (int k0 = 0; k0 < kend; k0 += TK) {
            // --- load X tile (transposed): Xs[kk][bb] = X[b0+bb][k0+kk]
            #pragma unroll
            for (int f = 0; f < 2; ++f) {
                const int q  = threadIdx.x + 256 * f;   // 0..511 float4 slots
                const int bb = q >> 2;                  // 0..127
                const int k4 = q & 3;                   // 0..3
                float4 v = *(const float4*)(X + (size_t)(b0 + bb) * DD + k0 + k4 * 4);
                Xs[k4 * 4 + 0][bb] = v.x;
                Xs[k4 * 4 + 1][bb] = v.y;
                Xs[k4 * 4 + 2][bb] = v.z;
                Xs[k4 * 4 + 3][bb] = v.w;
            }
            // --- load V tile: Vs[kk][nn] = W[(k0+kk)*D + n0+nn]
            {
                const int q  = threadIdx.x;   // 0..255 float4 slots
                const int kk = q >> 4;        // 0..15
                const int n4 = q & 15;        // 0..15
                float4 w = *(const float4*)(W + (size_t)(k0 + kk) * DD + n0 + n4 * 4);
                *(float4*)&Vs[kk][n4 * 4] = w;
            }
            __syncthreads();

            #pragma unroll
            for (int kk = 0; kk < TK; ++kk) {
                float4 xa = *(const float4*)&Xs[kk][ty * 8];
                float4 xb = *(const float4*)&Xs[kk][ty * 8 + 4];
                float4 vv = *(const float4*)&Vs[kk][tx * 4];
                float xr[8] = {xa.x, xa.y, xa.z, xa.w, xb.x, xb.y, xb.z, xb.w};
                float vn[4] = {vv.x, vv.y, vv.z, vv.w};
                #pragma unroll
                for (int r = 0; r < 8; ++r)
                    #pragma unroll
                    for (int cc = 0; cc < 4; ++cc)
                        acc[r][cc] += xr[r] * vn[cc];
            }
            __syncthreads();
        }

        // --- fused epilogue: dist += (z - u)^2 over this n-tile
        float4 uu = *(const float4*)&g_u[g * DD + n0 + tx * 4];
        float un[4] = {uu.x, uu.y, uu.z, uu.w};
        #pragma unroll
        for (int r = 0; r < 8; ++r)
            #pragma unroll
            for (int cc = 0; cc < 4; ++cc) {
                float dz = acc[r][cc] - un[cc];
                distacc[r] += dz * dz;
            }
    }

    // reduce partial dist across the 16 tx groups
    #pragma unroll
    for (int r = 0; r < 8; ++r) red[ty * 8 + r][tx] = distacc[r];
    __syncthreads();
    if (threadIdx.x < TB) {
        float s = 0.f;
        #pragma unroll
        for (int cc = 0; cc < 16; ++cc) s += red[threadIdx.x][cc];
        g_dist[(size_t)(b0 + threadIdx.x) * GG + g] = s;
    }
}

// ---------------------------------------------------------------------------
// Kernel 5: out = -mean_b( min_g relu(dist[b,g]) ) / 10000
// ---------------------------------------------------------------------------
__global__ __launch_bounds__(256, 1)
void reduce_kernel(float* __restrict__ out)
{
    __shared__ float sh[256];
    float s = 0.f;
    for (int b = threadIdx.x; b < BSZ; b += 256) {
        const float* row = g_dist + (size_t)b * GG;
        float m = fmaxf(row[0], 0.f);
        #pragma unroll 8
        for (int gi = 1; gi < GG; ++gi)
            m = fminf(m, fmaxf(row[gi], 0.f));
        s += m;
    }
    sh[threadIdx.x] = s;
    __syncthreads();
    for (int off = 128; off > 0; off >>= 1) {
        if (threadIdx.x < off) sh[threadIdx.x] += sh[threadIdx.x + off];
        __syncthreads();
    }
    if (threadIdx.x == 0)
        out[0] = -sh[0] / ((float)BSZ * 10000.0f);
}

// ---------------------------------------------------------------------------
extern "C" void kernel_launch(void* const* d_in, const int* in_sizes, int n_in,
                              void* d_out, int out_size)
{
    const float* X    = nullptr;
    const float* mus  = nullptr;
    const float* covs = nullptr;
    for (int i = 0; i < n_in; ++i) {
        if      (in_sizes[i] == BSZ * DD)      X    = (const float*)d_in[i];
        else if (in_sizes[i] == GG * DD)       mus  = (const float*)d_in[i];
        else if (in_sizes[i] == GG * DD * DD)  covs = (const float*)d_in[i];
    }

    cholesky_kernel<<<GG, 1024>>>(covs);
    trinv_kernel<<<GG, 1024>>>();
    u_kernel<<<GG, 512>>>(mus);
    gemm_dist_kernel<<<dim3(GG, BSZ / TB), 256>>>(X);
    reduce_kernel<<<1, 256>>>((float*)d_out);
}

// round 3
// speedup vs baseline: 3.0624x; 3.0624x over previous
#include <cuda_runtime.h>
#include <cuda_bf16.h>
#include <math.h>

// Problem sizes (fixed by the reference)
#define BSZ 2048
#define GG  64
#define DD  512
#define DD2 (DD * DD)
#define NB  32

// ---------------------------------------------------------------------------
// Scratch (device globals: allocation-free, graph-capturable)
// g_L : per-gaussian Cholesky factor L, COLUMN-major  (L(i,j) at j*DD+i, i>=j)
//       NOTE: viewed row-major this is U = L^T:  U[a][b] = g_L[a*DD+b]  (b>=a valid)
// g_W : per-gaussian V = U^{-1} = (L^T)^{-1}, ROW-major, zeros below diagonal
// ---------------------------------------------------------------------------
__device__ __align__(16) float g_L[GG * DD2];              // 64 MB
__device__ __align__(16) float g_W[GG * DD2];              // 64 MB
__device__ __align__(16) float g_Dinv[GG * 16 * NB * NB];  // 4 MB: per-g diag-block inverses
__device__ __align__(16) float g_u[GG * DD];               // u_g = mu_g^T V_g
__device__ __align__(16) float g_dist[BSZ * GG];           // dist[b][g]

// ---------------------------------------------------------------------------
// Kernel 1: BLOCKED Cholesky. One CTA per gaussian, 256 threads, NB=32 panels.
//   phase A: warp 0 factors the 32x32 diagonal block in shared
//   phase B: panel solve, 2 register-resident rows per thread (fully unrolled)
//   phase C: rank-32 SYRK trailing update, 64x64 tiles x (4x4 micro), lower
//            triangle only, panel staged transposed in shared (Pt).
// Dynamic smem: s11[32][33] + rdiag[32] + Pt[32][516]  = 70,400 bytes
// ---------------------------------------------------------------------------
#define CHOL_SMEM ((32*33 + 32 + 32*516) * 4)

__global__ __launch_bounds__(256, 1)
void cholesky_blocked(const float* __restrict__ covs)
{
    extern __shared__ float sm[];
    float (*s11)[33]  = (float(*)[33])sm;
    float* rdiag      = sm + 32 * 33;
    float (*Pt)[516]  = (float(*)[516])(sm + 32 * 33 + 32);

    const int g   = blockIdx.x;
    float* a      = g_L + (size_t)g * DD2;      // col-major L
    const float* c = covs + (size_t)g * DD2;
    const int tid = threadIdx.x;

    // full copy (cov is symmetric, so col-major == row-major copy)
    for (int idx = tid; idx < DD2 / 4; idx += 256)
        ((float4*)a)[idx] = ((const float4*)c)[idx];
    __syncthreads();

    for (int p = 0; p < DD / NB; ++p) {
        const int base = p * NB;
        const int r = DD - base - NB;          // trailing size (multiple of 32)

        // ---- load diagonal block into shared (full 32x32; only lower used)
        for (int q = tid; q < NB * NB; q += 256) {
            int i = q & 31, j = q >> 5;
            s11[i][j] = a[(size_t)(base + j) * DD + (base + i)];
        }
        __syncthreads();

        // ---- phase A: factor diag block with warp 0
        if (tid < 32) {
            const int lane = tid;
            for (int k = 0; k < NB; ++k) {
                if (lane == k) {
                    float d = sqrtf(s11[k][k]);
                    s11[k][k] = d;
                    rdiag[k] = 1.0f / d;
                }
                __syncwarp();
                float lik = 0.f;
                if (lane > k) {
                    lik = s11[lane][k] * rdiag[k];
                    s11[lane][k] = lik;
                }
                __syncwarp();
                if (lane > k) {
                    for (int j = k + 1; j <= lane; ++j)
                        s11[lane][j] -= lik * s11[j][k];
                }
                __syncwarp();
            }
        }
        __syncthreads();

        // write factored diag block back (lower incl diag)
        for (int q = tid; q < NB * NB; q += 256) {
            int i = q & 31, j = q >> 5;
            if (i >= j) a[(size_t)(base + j) * DD + (base + i)] = s11[i][j];
        }

        // ---- phase B: panel solve  L21 = A21 * L11^{-T}
        // row r_loc of trailing: x_j = (a_j - sum_{k<j} x_k * L11[j][k]) / L11[j][j]
        if (r > 0) {
            float x0[NB], x1[NB];
            const int r0 = tid, r1 = tid + 256;     // local row indices
            const bool v0 = (r0 < r), v1 = (r1 < r);
            const int gr0 = base + NB + r0;
            const int gr1 = base + NB + r1;
            #pragma unroll
            for (int j = 0; j < NB; ++j) {
                x0[j] = v0 ? a[(size_t)(base + j) * DD + gr0] : 0.f;
                x1[j] = v1 ? a[(size_t)(base + j) * DD + gr1] : 0.f;
            }
            #pragma unroll
            for (int j = 0; j < NB; ++j) {
                float s0 = x0[j], s1 = x1[j];
                #pragma unroll
                for (int k = 0; k < j; ++k) {
                    float l = s11[j][k];
                    s0 -= x0[k] * l;
                    s1 -= x1[k] * l;
                }
                float rd = rdiag[j];
                x0[j] = s0 * rd;
                x1[j] = s1 * rd;
            }
            #pragma unroll
            for (int j = 0; j < NB; ++j) {
                if (v0) { a[(size_t)(base + j) * DD + gr0] = x0[j]; Pt[j][r0] = x0[j]; }
                if (v1) { a[(size_t)(base + j) * DD + gr1] = x1[j]; Pt[j][r1] = x1[j]; }
            }
        }
        __syncthreads();

        // ---- phase C: trailing update  A22 -= L21 * L21^T (lower triangle)
        if (r > 0) {
            const int m  = (r + 63) >> 6;       // 64-tiles
            const int tx = tid & 15;            // row direction (4 rows each)
            const int ty = tid >> 4;            // col direction (4 cols each)
            for (int ti = 0; ti < m; ++ti)
            for (int tj = 0; tj <= ti; ++tj) {
                const int gi = ti * 64 + tx * 4;   // local trailing row
                const int gj = tj * 64 + ty * 4;   // local trailing col
                float acc[4][4];
                #pragma unroll
                for (int ii = 0; ii < 4; ++ii)
                    #pragma unroll
                    for (int jj = 0; jj < 4; ++jj) acc[ii][jj] = 0.f;
                #pragma unroll
                for (int k = 0; k < NB; ++k) {
                    float4 pi = *(const float4*)&Pt[k][gi];
                    float4 pj = *(const float4*)&Pt[k][gj];
                    float pr[4] = {pi.x, pi.y, pi.z, pi.w};
                    float pc[4] = {pj.x, pj.y, pj.z, pj.w};
                    #pragma unroll
                    for (int ii = 0; ii < 4; ++ii)
                        #pragma unroll
                        for (int jj = 0; jj < 4; ++jj)
                            acc[ii][jj] += pr[ii] * pc[jj];
                }
                if (gi < r) {
                    #pragma unroll
                    for (int jj = 0; jj < 4; ++jj) {
                        const int colg = gj + jj;
                        if (colg < r) {
                            float* pc2 = a + (size_t)(base + NB + colg) * DD
                                           + (base + NB + gi);
                            float4 cv = *(float4*)pc2;
                            cv.x -= acc[0][jj]; cv.y -= acc[1][jj];
                            cv.z -= acc[2][jj]; cv.w -= acc[3][jj];
                            *(float4*)pc2 = cv;
                        }
                    }
                }
            }
        }
        __syncthreads();
    }
}

// ---------------------------------------------------------------------------
// Kernel 2a: invert the 16 diagonal 32x32 blocks of U = L^T (upper triangular).
// One warp per (g, d). Column c of the inverse solved by lane c (upper-tri
// inverse is upper: entries t<=c only). All deps are within-lane via its own
// smem column, so no cross-lane sync needed inside the solve.
// ---------------------------------------------------------------------------
__global__ __launch_bounds__(128, 8)
void diaginv_kernel()
{
    __shared__ float su[4][NB][NB + 1];
    __shared__ float sx[4][NB][NB + 1];

    const int g = blockIdx.x;
    const int w = threadIdx.x >> 5;
    const int d = blockIdx.y * 4 + w;
    const int cc = threadIdx.x & 31;
    const float* U = g_L + (size_t)g * DD2;     // row-major view of U
    const int b0 = d * NB;

    for (int rr = 0; rr < NB; ++rr)
        su[w][rr][cc] = U[(size_t)(b0 + rr) * DD + (b0 + cc)];
    __syncwarp();

    for (int t = cc; t >= 0; --t) {
        float s = (t == cc) ? 1.f : 0.f;
        for (int ss = t + 1; ss <= cc; ++ss)
            s -= su[w][t][ss] * sx[w][ss][cc];
        sx[w][t][cc] = s / su[w][t][t];
    }
    __syncwarp();

    float* dst = g_Dinv + ((size_t)g * 16 + d) * NB * NB;
    for (int t = 0; t < NB; ++t)
        dst[t * NB + cc] = (t <= cc) ? sx[w][t][cc] : 0.f;
}

// ---------------------------------------------------------------------------
// Kernel 2b: blocked triangular inverse, one CTA per (g, block-column j).
// V[j][j] = Dinv[jj];  for i=j-1..0:  V[i][j] = -Dinv[ii] * sum_{k=i+1..j} U[i][k] V[k][j]
// Block-column held in shared (Vs); 32x32 GEMMs from shared with LDS.128 on U.
// Dynamic smem: Vs[512][36] + Us[32][36] + Ts[32][33] = 82,560 bytes
// ---------------------------------------------------------------------------
#define T2_SMEM ((512*36 + 32*36 + 32*33) * 4)

__global__ __launch_bounds__(128)
void trinv_col_kernel()
{
    extern __shared__ float sm2[];
    float (*Vs)[36] = (float(*)[36])sm2;
    float (*Us)[36] = (float(*)[36])(sm2 + 512 * 36);
    float (*Ts)[33] = (float(*)[33])(sm2 + 512 * 36 + 32 * 36);

    const int g = blockIdx.x;
    const int j = blockIdx.y;
    const float* U = g_L + (size_t)g * DD2;     // row-major view of U
    float* W = g_W + (size_t)g * DD2;
    const int tid = threadIdx.x;
    const int cc  = tid & 31;
    const int q   = tid >> 5;                   // warp id: rows q*8 .. q*8+7

    // diag block: V[j][j] = Dinv[j]
    {
        const float* din = g_Dinv + ((size_t)g * 16 + j) * NB * NB;
        #pragma unroll
        for (int t8 = 0; t8 < 8; ++t8) {
            int t = q * 8 + t8;
            Vs[j * NB + t][cc] = din[t * NB + cc];
        }
    }
    __syncthreads();

    for (int i = j - 1; i >= 0; --i) {
        float acc[8];
        #pragma unroll
        for (int r8 = 0; r8 < 8; ++r8) acc[r8] = 0.f;

        for (int k = i + 1; k <= j; ++k) {
            // stage U[i][k] (32x32) into Us
            const float* ub = U + (size_t)(i * NB) * DD + k * NB;
            for (int l = tid; l < NB * NB / 4; l += 128) {
                int rr = l >> 3, t4 = l & 7;
                *(float4*)&Us[rr][t4 * 4] = *(const float4*)&ub[(size_t)rr * DD + t4 * 4];
            }
            __syncthreads();
            #pragma unroll
            for (int t4 = 0; t4 < 8; ++t4) {
                float v0 = Vs[k * NB + t4 * 4 + 0][cc];
                float v1 = Vs[k * NB + t4 * 4 + 1][cc];
                float v2 = Vs[k * NB + t4 * 4 + 2][cc];
                float v3 = Vs[k * NB + t4 * 4 + 3][cc];
                #pragma unroll
                for (int r8 = 0; r8 < 8; ++r8) {
                    float4 u4 = *(const float4*)&Us[q * 8 + r8][t4 * 4];
                    acc[r8] += u4.x * v0 + u4.y * v1 + u4.z * v2 + u4.w * v3;
                }
            }
            __syncthreads();
        }

        // Ts = T; stage Dinv[i]; compute V[i][j] = -Dinv[ii] * T
        #pragma unroll
        for (int r8 = 0; r8 < 8; ++r8) Ts[q * 8 + r8][cc] = acc[r8];
        {
            const float* din = g_Dinv + ((size_t)g * 16 + i) * NB * NB;
            for (int l = tid; l < NB * NB / 4; l += 128) {
                int rr = l >> 3, t4 = l & 7;
                *(float4*)&Us[rr][t4 * 4] = *(const float4*)&din[rr * NB + t4 * 4];
            }
        }
        __syncthreads();

        float acc2[8];
        #pragma unroll
        for (int r8 = 0; r8 < 8; ++r8) acc2[r8] = 0.f;
        #pragma unroll
        for (int t4 = 0; t4 < 8; ++t4) {
            float v0 = Ts[t4 * 4 + 0][cc];
            float v1 = Ts[t4 * 4 + 1][cc];
            float v2 = Ts[t4 * 4 + 2][cc];
            float v3 = Ts[t4 * 4 + 3][cc];
            #pragma unroll
            for (int r8 = 0; r8 < 8; ++r8) {
                float4 u4 = *(const float4*)&Us[q * 8 + r8][t4 * 4];
                acc2[r8] += u4.x * v0 + u4.y * v1 + u4.z * v2 + u4.w * v3;
            }
        }
        #pragma unroll
        for (int r8 = 0; r8 < 8; ++r8) Vs[i * NB + q * 8 + r8][cc] = -acc2[r8];
        __syncthreads();
    }

    // write out block-column j (rows 0..(j+1)*32-1) + explicit zeros below
    const int ncol = j * NB + cc;
    for (int row = q; row < (j + 1) * NB; row += 4)
        W[(size_t)row * DD + ncol] = Vs[row][cc];
    for (int row = (j + 1) * NB + q; row < DD; row += 4)
        W[(size_t)row * DD + ncol] = 0.f;
}

// ---------------------------------------------------------------------------
// Kernel 3: u_g[n] = sum_{d<=n} mu_g[d] * V_g(d,n).
// ---------------------------------------------------------------------------
__global__ __launch_bounds__(512, 2)
void u_kernel(const float* __restrict__ mus)
{
    const int g = blockIdx.x;
    const int n = threadIdx.x;
    const float* W  = g_W + (size_t)g * DD2;
    const float* mu = mus + (size_t)g * DD;
    float s = 0.f;
    #pragma unroll 4
    for (int d = 0; d <= n; ++d) s += mu[d] * W[d * DD + n];
    g_u[g * DD + n] = s;
}

// ---------------------------------------------------------------------------
// Kernel 4: triangular GEMM + fused dist epilogue (unchanged from R2).
// ---------------------------------------------------------------------------
#define TB 128
#define TN 64
#define TK 16

__global__ __launch_bounds__(256, 2)
void gemm_dist_kernel(const float* __restrict__ X)
{
    const int g  = blockIdx.x;
    const int b0 = blockIdx.y * TB;
    const float* W = g_W + (size_t)g * DD2;

    __shared__ __align__(16) float Xs[TK][TB + 4];
    __shared__ __align__(16) float Vs[TK][TN + 4];
    __shared__ float red[TB][17];

    const int tx = threadIdx.x & 15;
    const int ty = threadIdx.x >> 4;

    float distacc[8];
    #pragma unroll
    for (int r = 0; r < 8; ++r) distacc[r] = 0.f;

    for (int nt = 0; nt < DD / TN; ++nt) {
        const int n0   = nt * TN;
        const int kend = n0 + TN;
        float acc[8][4];
        #pragma unroll
        for (int r = 0; r < 8; ++r)
            #pragma unroll
            for (int cc = 0; cc < 4; ++cc) acc[r][cc] = 0.f;

        for (int k0 = 0; k0 < kend; k0 += TK) {
            #pragma unroll
            for (int f = 0; f < 2; ++f) {
                const int q  = threadIdx.x + 256 * f;
                const int bb = q >> 2;
                const int k4 = q & 3;
                float4 v = *(const float4*)(X + (size_t)(b0 + bb) * DD + k0 + k4 * 4);
                Xs[k4 * 4 + 0][bb] = v.x;
                Xs[k4 * 4 + 1][bb] = v.y;
                Xs[k4 * 4 + 2][bb] = v.z;
                Xs[k4 * 4 + 3][bb] = v.w;
            }
            {
                const int q  = threadIdx.x;
                const int kk = q >> 4;
                const int n4 = q & 15;
                float4 w = *(const float4*)(W + (size_t)(k0 + kk) * DD + n0 + n4 * 4);
                *(float4*)&Vs[kk][n4 * 4] = w;
            }
            __syncthreads();

            #pragma unroll
            for (int kk = 0; kk < TK; ++kk) {
                float4 xa = *(const float4*)&Xs[kk][ty * 8];
                float4 xb = *(const float4*)&Xs[kk][ty * 8 + 4];
                float4 vv = *(const float4*)&Vs[kk][tx * 4];
                float xr[8] = {xa.x, xa.y, xa.z, xa.w, xb.x, xb.y, xb.z, xb.w};
                float vn[4] = {vv.x, vv.y, vv.z, vv.w};
                #pragma unroll
                for (int r = 0; r < 8; ++r)
                    #pragma unroll
                    for (int cc = 0; cc < 4; ++cc)
                        acc[r][cc] += xr[r] * vn[cc];
            }
            __syncthreads();
        }

        float4 uu = *(const float4*)&g_u[g * DD + n0 + tx * 4];
        float un[4] = {uu.x, uu.y, uu.z, uu.w};
        #pragma unroll
        for (int r = 0; r < 8; ++r)
            #pragma unroll
            for (int cc = 0; cc < 4; ++cc) {
                float dz = acc[r][cc] - un[cc];
                distacc[r] += dz * dz;
            }
    }

    #pragma unroll
    for (int r = 0; r < 8; ++r) red[ty * 8 + r][tx] = distacc[r];
    __syncthreads();
    if (threadIdx.x < TB) {
        float s = 0.f;
        #pragma unroll
        for (int cc = 0; cc < 16; ++cc) s += red[threadIdx.x][cc];
        g_dist[(size_t)(b0 + threadIdx.x) * GG + g] = s;
    }
}

// ---------------------------------------------------------------------------
// Kernel 5: out = -mean_b( min_g relu(dist[b,g]) ) / 10000
// ---------------------------------------------------------------------------
__global__ __launch_bounds__(256, 1)
void reduce_kernel(float* __restrict__ out)
{
    __shared__ float sh[256];
    float s = 0.f;
    for (int b = threadIdx.x; b < BSZ; b += 256) {
        const float* row = g_dist + (size_t)b * GG;
        float m = fmaxf(row[0], 0.f);
        #pragma unroll 8
        for (int gi = 1; gi < GG; ++gi)
            m = fminf(m, fmaxf(row[gi], 0.f));
        s += m;
    }
    sh[threadIdx.x] = s;
    __syncthreads();
    for (int off = 128; off > 0; off >>= 1) {
        if (threadIdx.x < off) sh[threadIdx.x] += sh[threadIdx.x + off];
        __syncthreads();
    }
    if (threadIdx.x == 0)
        out[0] = -sh[0] / ((float)BSZ * 10000.0f);
}

// ---------------------------------------------------------------------------
extern "C" void kernel_launch(void* const* d_in, const int* in_sizes, int n_in,
                              void* d_out, int out_size)
{
    const float* X    = nullptr;
    const float* mus  = nullptr;
    const float* covs = nullptr;
    for (int i = 0; i < n_in; ++i) {
        if      (in_sizes[i] == BSZ * DD)      X    = (const float*)d_in[i];
        else if (in_sizes[i] == GG * DD)       mus  = (const float*)d_in[i];
        else if (in_sizes[i] == GG * DD * DD)  covs = (const float*)d_in[i];
    }

    static bool attr_done = false;
    if (!attr_done) {
        cudaFuncSetAttribute(cholesky_blocked,
                             cudaFuncAttributeMaxDynamicSharedMemorySize, CHOL_SMEM);
        cudaFuncSetAttribute(trinv_col_kernel,
                             cudaFuncAttributeMaxDynamicSharedMemorySize, T2_SMEM);
        attr_done = true;
    }

    cholesky_blocked<<<GG, 256, CHOL_SMEM>>>(covs);
    diaginv_kernel<<<dim3(GG, 4), 128>>>();
    trinv_col_kernel<<<dim3(GG, 16), 128, T2_SMEM>>>();
    u_kernel<<<GG, 512>>>(mus);
    gemm_dist_kernel<<<dim3(GG, BSZ / TB), 256>>>(X);
    reduce_kernel<<<1, 256>>>((float*)d_out);
}

// round 4
// speedup vs baseline: 3.2171x; 1.0505x over previous
#include <cuda_runtime.h>
#include <cuda_bf16.h>
#include <math.h>

// Problem sizes (fixed by the reference)
#define BSZ 2048
#define GG  64
#define DD  512
#define DD2 (DD * DD)
#define NB  32

// ---------------------------------------------------------------------------
// Scratch (device globals: allocation-free, graph-capturable)
// g_L : per-gaussian Cholesky factor L, COLUMN-major  (L(i,j) at j*DD+i, i>=j)
//       Row-major view of the same buffer is U = L^T (valid at a*DD+b, b>=a).
// g_W : per-gaussian V = U^{-1} = (L^T)^{-1}, ROW-major, zeros below diagonal
// ---------------------------------------------------------------------------
__device__ __align__(16) float g_L[GG * DD2];              // 64 MB
__device__ __align__(16) float g_W[GG * DD2];              // 64 MB
__device__ __align__(16) float g_Dinv[GG * 16 * NB * NB];  // 4 MB
__device__ __align__(16) float g_u[GG * DD];
__device__ __align__(16) float g_dist[BSZ * GG];

// ---------------------------------------------------------------------------
// Kernel 0: copy covs -> g_L (full copy; symmetric so layout-agnostic)
// ---------------------------------------------------------------------------
__global__ __launch_bounds__(256)
void copy_cov(const float* __restrict__ c)
{
    const size_t n = (size_t)GG * DD2 / 4;
    for (size_t i = (size_t)blockIdx.x * blockDim.x + threadIdx.x; i < n;
         i += (size_t)gridDim.x * blockDim.x)
        ((float4*)g_L)[i] = ((const float4*)c)[i];
}

// ---------------------------------------------------------------------------
// Kernel 1a: panel step p. One CTA per gaussian.
//   - warp 0 factors the 32x32 diagonal block (in shared)
//   - all 256 threads do the panel solve L21 = A21 * L11^{-T}
//     (2 register-resident 32-vectors per thread, fully unrolled)
// ---------------------------------------------------------------------------
__global__ __launch_bounds__(256)
void chol_panel(int base, int r)
{
    __shared__ float s11[NB][NB + 1];
    __shared__ float rdiag[NB];

    const int g   = blockIdx.x;
    float* a      = g_L + (size_t)g * DD2;
    const int tid = threadIdx.x;

    // load diagonal block
    for (int q = tid; q < NB * NB; q += 256) {
        int i = q & 31, j = q >> 5;
        s11[i][j] = a[(size_t)(base + j) * DD + (base + i)];
    }
    __syncthreads();

    // factor with warp 0
    if (tid < 32) {
        const int lane = tid;
        for (int k = 0; k < NB; ++k) {
            if (lane == k) {
                float d = sqrtf(s11[k][k]);
                s11[k][k] = d;
                rdiag[k] = 1.0f / d;
            }
            __syncwarp();
            float lik = 0.f;
            if (lane > k) {
                lik = s11[lane][k] * rdiag[k];
                s11[lane][k] = lik;
            }
            __syncwarp();
            if (lane > k) {
                for (int j = k + 1; j <= lane; ++j)
                    s11[lane][j] -= lik * s11[j][k];
            }
            __syncwarp();
        }
    }
    __syncthreads();

    // write back lower diag block
    for (int q = tid; q < NB * NB; q += 256) {
        int i = q & 31, j = q >> 5;
        if (i >= j) a[(size_t)(base + j) * DD + (base + i)] = s11[i][j];
    }

    // panel solve
    if (r > 0) {
        float x0[NB], x1[NB];
        const int r0 = tid, r1 = tid + 256;
        const bool v0 = (r0 < r), v1 = (r1 < r);
        const int gr0 = base + NB + r0;
        const int gr1 = base + NB + r1;
        #pragma unroll
        for (int j = 0; j < NB; ++j) {
            x0[j] = v0 ? a[(size_t)(base + j) * DD + gr0] : 0.f;
            x1[j] = v1 ? a[(size_t)(base + j) * DD + gr1] : 0.f;
        }
        #pragma unroll
        for (int j = 0; j < NB; ++j) {
            float s0 = x0[j], s1 = x1[j];
            #pragma unroll
            for (int k = 0; k < j; ++k) {
                float l = s11[j][k];
                s0 -= x0[k] * l;
                s1 -= x1[k] * l;
            }
            float rd = rdiag[j];
            x0[j] = s0 * rd;
            x1[j] = s1 * rd;
        }
        #pragma unroll
        for (int j = 0; j < NB; ++j) {
            if (v0) a[(size_t)(base + j) * DD + gr0] = x0[j];
            if (v1) a[(size_t)(base + j) * DD + gr1] = x1[j];
        }
    }
}

// ---------------------------------------------------------------------------
// Kernel 1b: SYRK trailing update for panel step p, grid-wide.
// Block (g, t) handles one 64x64 lower tile (ti,tj) of A22 -= L21 * L21^T.
// Diagonal tiles write their full square (upper junk is never read).
// ---------------------------------------------------------------------------
__global__ __launch_bounds__(256)
void chol_syrk(int base, int r)
{
    __shared__ float Pi[NB][68];
    __shared__ float Pj[NB][68];

    const int g = blockIdx.x;
    const int t = blockIdx.y;
    // linear lower-tile index -> (ti, tj), tj <= ti
    int ti = (int)((sqrtf(8.f * t + 1.f) - 1.f) * 0.5f);
    while ((ti + 1) * (ti + 2) / 2 <= t) ++ti;
    while (ti * (ti + 1) / 2 > t) --ti;
    const int tj = t - ti * (ti + 1) / 2;

    const int gi = ti * 64;
    const int gj = tj * 64;
    float* a = g_L + (size_t)g * DD2;
    const int tid = threadIdx.x;

    // stage panel rows [gi, gi+64) and [gj, gj+64) transposed into shared
    #pragma unroll
    for (int f = 0; f < 2; ++f) {
        const int s   = tid + 256 * f;     // 0..511
        const int col = s >> 4;            // 0..31
        const int r4  = s & 15;            // 0..15
        {
            const int row = gi + r4 * 4;
            float4 v = make_float4(0.f, 0.f, 0.f, 0.f);
            if (row < r)
                v = *(const float4*)(a + (size_t)(base + col) * DD + base + NB + row);
            *(float4*)&Pi[col][r4 * 4] = v;
        }
        {
            const int row = gj + r4 * 4;
            float4 v = make_float4(0.f, 0.f, 0.f, 0.f);
            if (row < r)
                v = *(const float4*)(a + (size_t)(base + col) * DD + base + NB + row);
            *(float4*)&Pj[col][r4 * 4] = v;
        }
    }
    __syncthreads();

    const int tx = tid & 15;   // row micro (4 rows)
    const int ty = tid >> 4;   // col micro (4 cols)
    float acc[4][4];
    #pragma unroll
    for (int ii = 0; ii < 4; ++ii)
        #pragma unroll
        for (int jj = 0; jj < 4; ++jj) acc[ii][jj] = 0.f;

    #pragma unroll
    for (int k = 0; k < NB; ++k) {
        float4 pi = *(const float4*)&Pi[k][tx * 4];
        float4 pj = *(const float4*)&Pj[k][ty * 4];
        float pr[4] = {pi.x, pi.y, pi.z, pi.w};
        float pc[4] = {pj.x, pj.y, pj.z, pj.w};
        #pragma unroll
        for (int ii = 0; ii < 4; ++ii)
            #pragma unroll
            for (int jj = 0; jj < 4; ++jj)
                acc[ii][jj] += pr[ii] * pc[jj];
    }

    const int rowb = gi + tx * 4;
    if (rowb < r) {
        #pragma unroll
        for (int jj = 0; jj < 4; ++jj) {
            const int colg = gj + ty * 4 + jj;
            if (colg < r) {
                float* p = a + (size_t)(base + NB + colg) * DD + base + NB + rowb;
                float4 cv = *(float4*)p;
                cv.x -= acc[0][jj]; cv.y -= acc[1][jj];
                cv.z -= acc[2][jj]; cv.w -= acc[3][jj];
                *(float4*)p = cv;
            }
        }
    }
}

// ---------------------------------------------------------------------------
// Kernel 2a: invert the 16 diagonal 32x32 blocks of U = L^T. One warp per (g,d).
// ---------------------------------------------------------------------------
__global__ __launch_bounds__(128, 8)
void diaginv_kernel()
{
    __shared__ float su[4][NB][NB + 1];
    __shared__ float sx[4][NB][NB + 1];

    const int g = blockIdx.x;
    const int w = threadIdx.x >> 5;
    const int d = blockIdx.y * 4 + w;
    const int cc = threadIdx.x & 31;
    const float* U = g_L + (size_t)g * DD2;   // row-major view of U
    const int b0 = d * NB;

    for (int rr = 0; rr < NB; ++rr)
        su[w][rr][cc] = U[(size_t)(b0 + rr) * DD + (b0 + cc)];
    __syncwarp();

    for (int t = cc; t >= 0; --t) {
        float s = (t == cc) ? 1.f : 0.f;
        for (int ss = t + 1; ss <= cc; ++ss)
            s -= su[w][t][ss] * sx[w][ss][cc];
        sx[w][t][cc] = s / su[w][t][t];
    }
    __syncwarp();

    float* dst = g_Dinv + ((size_t)g * 16 + d) * NB * NB;
    for (int t = 0; t < NB; ++t)
        dst[t * NB + cc] = (t <= cc) ? sx[w][t][cc] : 0.f;
}

// ---------------------------------------------------------------------------
// Kernel 2b: blocked triangular inverse, one CTA per (g, block-column j).
// 256 threads (8 warps x 4 rows). Fused u computation at the end.
// Dynamic smem: Vs[512][36] + Us[32][36] + Ts[32][33] = 82,560 bytes
// ---------------------------------------------------------------------------
#define T2_SMEM ((512*36 + 32*36 + 32*33) * 4)

__global__ __launch_bounds__(256)
void trinv_col_kernel(const float* __restrict__ mus)
{
    extern __shared__ float sm2[];
    float (*Vs)[36] = (float(*)[36])sm2;
    float (*Us)[36] = (float(*)[36])(sm2 + 512 * 36);
    float (*Ts)[33] = (float(*)[33])(sm2 + 512 * 36 + 32 * 36);

    const int g = blockIdx.x;
    const int j = blockIdx.y;
    const float* U = g_L + (size_t)g * DD2;   // row-major view of U
    float* W = g_W + (size_t)g * DD2;
    const int tid = threadIdx.x;
    const int cc  = tid & 31;
    const int q   = tid >> 5;                 // warp id 0..7: rows q*4..q*4+3

    // diag block: V[j][j] = Dinv[j]
    {
        const float* din = g_Dinv + ((size_t)g * 16 + j) * NB * NB;
        #pragma unroll
        for (int t4 = 0; t4 < 4; ++t4) {
            int t = q * 4 + t4;
            Vs[j * NB + t][cc] = din[t * NB + cc];
        }
    }
    __syncthreads();

    for (int i = j - 1; i >= 0; --i) {
        float acc[4];
        #pragma unroll
        for (int r4 = 0; r4 < 4; ++r4) acc[r4] = 0.f;

        for (int k = i + 1; k <= j; ++k) {
            // stage U[i][k] (32x32): one float4 per thread
            const float* ub = U + (size_t)(i * NB) * DD + k * NB;
            {
                const int rr = tid >> 3, t4 = tid & 7;
                *(float4*)&Us[rr][t4 * 4] = *(const float4*)&ub[(size_t)rr * DD + t4 * 4];
            }
            __syncthreads();
            #pragma unroll
            for (int t4 = 0; t4 < 8; ++t4) {
                float v0 = Vs[k * NB + t4 * 4 + 0][cc];
                float v1 = Vs[k * NB + t4 * 4 + 1][cc];
                float v2 = Vs[k * NB + t4 * 4 + 2][cc];
                float v3 = Vs[k * NB + t4 * 4 + 3][cc];
                #pragma unroll
                for (int r4 = 0; r4 < 4; ++r4) {
                    float4 u4 = *(const float4*)&Us[q * 4 + r4][t4 * 4];
                    acc[r4] += u4.x * v0 + u4.y * v1 + u4.z * v2 + u4.w * v3;
                }
            }
            __syncthreads();
        }

        // Ts = T; stage Dinv[i]; V[i][j] = -Dinv[ii] * T
        #pragma unroll
        for (int r4 = 0; r4 < 4; ++r4) Ts[q * 4 + r4][cc] = acc[r4];
        {
            const float* din = g_Dinv + ((size_t)g * 16 + i) * NB * NB;
            const int rr = tid >> 3, t4 = tid & 7;
            *(float4*)&Us[rr][t4 * 4] = *(const float4*)&din[rr * NB + t4 * 4];
        }
        __syncthreads();

        float acc2[4];
        #pragma unroll
        for (int r4 = 0; r4 < 4; ++r4) acc2[r4] = 0.f;
        #pragma unroll
        for (int t4 = 0; t4 < 8; ++t4) {
            float v0 = Ts[t4 * 4 + 0][cc];
            float v1 = Ts[t4 * 4 + 1][cc];
            float v2 = Ts[t4 * 4 + 2][cc];
            float v3 = Ts[t4 * 4 + 3][cc];
            #pragma unroll
            for (int r4 = 0; r4 < 4; ++r4) {
                float4 u4 = *(const float4*)&Us[q * 4 + r4][t4 * 4];
                acc2[r4] += u4.x * v0 + u4.y * v1 + u4.z * v2 + u4.w * v3;
            }
        }
        #pragma unroll
        for (int r4 = 0; r4 < 4; ++r4) Vs[i * NB + q * 4 + r4][cc] = -acc2[r4];
        __syncthreads();
    }

    // write out block-column j + explicit zeros below diagonal
    const int ncol = j * NB + cc;
    for (int row = q; row < (j + 1) * NB; row += 8)
        W[(size_t)row * DD + ncol] = Vs[row][cc];
    for (int row = (j + 1) * NB + q; row < DD; row += 8)
        W[(size_t)row * DD + ncol] = 0.f;

    // fused u: u[ncol] = sum_{row < (j+1)*NB} mu[row] * V[row][ncol]
    {
        const float* mu = mus + (size_t)g * DD;
        float s = 0.f;
        for (int row = q; row < (j + 1) * NB; row += 8)
            s += mu[row] * Vs[row][cc];
        Us[q][cc] = s;
        __syncthreads();
        if (q == 0) {
            float tot = 0.f;
            #pragma unroll
            for (int w8 = 0; w8 < 8; ++w8) tot += Us[w8][cc];
            g_u[(size_t)g * DD + ncol] = tot;
        }
    }
}

// ---------------------------------------------------------------------------
// Kernel 4: triangular GEMM + fused dist epilogue.
// 128(B) x 128(N) tile, 256 threads, 8x8 micro, TK=8, double-buffered smem
// with ONE __syncthreads per k-step.
// ---------------------------------------------------------------------------
__global__ __launch_bounds__(256, 2)
void gemm_dist_kernel(const float* __restrict__ X)
{
    const int g  = blockIdx.x;
    const int b0 = blockIdx.y * 128;
    const float* W = g_W + (size_t)g * DD2;

    __shared__ __align__(16) float Xs[2][8][132];
    __shared__ __align__(16) float Vs[2][8][132];
    __shared__ float red[128][17];

    const int tid = threadIdx.x;
    const int tx  = tid & 15;    // n micro group (8 cols)
    const int ty  = tid >> 4;    // b micro group (8 rows)

    // load-thread mapping
    const int xbb = tid >> 1, xk4 = tid & 1;       // X: row, k-float4
    const int vkk = tid >> 5, vn4 = tid & 31;      // V: k-row, n-float4
    const float* Xp = X + (size_t)(b0 + xbb) * DD + xk4 * 4;

    float dist[8];
    #pragma unroll
    for (int r = 0; r < 8; ++r) dist[r] = 0.f;

    for (int nt = 0; nt < 4; ++nt) {
        const int n0 = nt * 128;
        const int nsteps = (nt + 1) * 16;          // kend = n0+128, TK=8
        const float* Vp = W + (size_t)vkk * DD + n0 + vn4 * 4;

        float acc[8][8];
        #pragma unroll
        for (int r = 0; r < 8; ++r)
            #pragma unroll
            for (int c = 0; c < 8; ++c) acc[r][c] = 0.f;

        // preload step 0 into buffer 0
        {
            float4 v = *(const float4*)(Xp);
            Xs[0][xk4 * 4 + 0][xbb] = v.x;
            Xs[0][xk4 * 4 + 1][xbb] = v.y;
            Xs[0][xk4 * 4 + 2][xbb] = v.z;
            Xs[0][xk4 * 4 + 3][xbb] = v.w;
            float4 w = *(const float4*)(Vp);
            *(float4*)&Vs[0][vkk][vn4 * 4] = w;
        }
        __syncthreads();

        for (int s = 0; s < nsteps; ++s) {
            const int cur = s & 1;
            float4 nx, nv;
            const bool more = (s + 1 < nsteps);
            if (more) {
                nx = *(const float4*)(Xp + (s + 1) * 8);
                nv = *(const float4*)(Vp + (size_t)(s + 1) * 8 * DD);
            }

            #pragma unroll
            for (int kk = 0; kk < 8; ++kk) {
                float4 xa = *(const float4*)&Xs[cur][kk][ty * 8];
                float4 xb = *(const float4*)&Xs[cur][kk][ty * 8 + 4];
                float4 va = *(const float4*)&Vs[cur][kk][tx * 8];
                float4 vb = *(const float4*)&Vs[cur][kk][tx * 8 + 4];
                float xr[8] = {xa.x, xa.y, xa.z, xa.w, xb.x, xb.y, xb.z, xb.w};
                float vc[8] = {va.x, va.y, va.z, va.w, vb.x, vb.y, vb.z, vb.w};
                #pragma unroll
                for (int r = 0; r < 8; ++r)
                    #pragma unroll
                    for (int c = 0; c < 8; ++c)
                        acc[r][c] += xr[r] * vc[c];
            }

            if (more) {
                const int nxt = 1 - cur;
                Xs[nxt][xk4 * 4 + 0][xbb] = nx.x;
                Xs[nxt][xk4 * 4 + 1][xbb] = nx.y;
                Xs[nxt][xk4 * 4 + 2][xbb] = nx.z;
                Xs[nxt][xk4 * 4 + 3][xbb] = nx.w;
                *(float4*)&Vs[nxt][vkk][vn4 * 4] = nv;
                __syncthreads();
            }
        }

        // fused epilogue: dist += (z - u)^2
        float4 ua = *(const float4*)&g_u[(size_t)g * DD + n0 + tx * 8];
        float4 ub = *(const float4*)&g_u[(size_t)g * DD + n0 + tx * 8 + 4];
        float un[8] = {ua.x, ua.y, ua.z, ua.w, ub.x, ub.y, ub.z, ub.w};
        #pragma unroll
        for (int r = 0; r < 8; ++r)
            #pragma unroll
            for (int c = 0; c < 8; ++c) {
                float dz = acc[r][c] - un[c];
                dist[r] += dz * dz;
            }
        __syncthreads();   // before next nt's preload overwrites buffers
    }

    // reduce partial dist across the 16 tx groups
    #pragma unroll
    for (int r = 0; r < 8; ++r) red[ty * 8 + r][tx] = dist[r];
    __syncthreads();
    if (tid < 128) {
        float s = 0.f;
        #pragma unroll
        for (int c = 0; c < 16; ++c) s += red[tid][c];
        g_dist[(size_t)(b0 + tid) * GG + g] = s;
    }
}

// ---------------------------------------------------------------------------
// Kernel 5: out = -mean_b( min_g relu(dist[b,g]) ) / 10000
// ---------------------------------------------------------------------------
__global__ __launch_bounds__(256, 1)
void reduce_kernel(float* __restrict__ out)
{
    __shared__ float sh[256];
    float s = 0.f;
    for (int b = threadIdx.x; b < BSZ; b += 256) {
        const float* row = g_dist + (size_t)b * GG;
        float m = fmaxf(row[0], 0.f);
        #pragma unroll 8
        for (int gi = 1; gi < GG; ++gi)
            m = fminf(m, fmaxf(row[gi], 0.f));
        s += m;
    }
    sh[threadIdx.x] = s;
    __syncthreads();
    for (int off = 128; off > 0; off >>= 1) {
        if (threadIdx.x < off) sh[threadIdx.x] += sh[threadIdx.x + off];
        __syncthreads();
    }
    if (threadIdx.x == 0)
        out[0] = -sh[0] / ((float)BSZ * 10000.0f);
}

// ---------------------------------------------------------------------------
extern "C" void kernel_launch(void* const* d_in, const int* in_sizes, int n_in,
                              void* d_out, int out_size)
{
    const float* X    = nullptr;
    const float* mus  = nullptr;
    const float* covs = nullptr;
    for (int i = 0; i < n_in; ++i) {
        if      (in_sizes[i] == BSZ * DD)      X    = (const float*)d_in[i];
        else if (in_sizes[i] == GG * DD)       mus  = (const float*)d_in[i];
        else if (in_sizes[i] == GG * DD * DD)  covs = (const float*)d_in[i];
    }

    static bool attr_done = false;
    if (!attr_done) {
        cudaFuncSetAttribute(trinv_col_kernel,
                             cudaFuncAttributeMaxDynamicSharedMemorySize, T2_SMEM);
        attr_done = true;
    }

    copy_cov<<<1024, 256>>>(covs);
    for (int p = 0; p < DD / NB; ++p) {
        const int base = p * NB;
        const int r = DD - base - NB;
        chol_panel<<<GG, 256>>>(base, r);
        if (r > 0) {
            const int m = (r + 63) / 64;
            chol_syrk<<<dim3(GG, m * (m + 1) / 2), 256>>>(base, r);
        }
    }
    diaginv_kernel<<<dim3(GG, 4), 128>>>();
    trinv_col_kernel<<<dim3(GG, 16), 256, T2_SMEM>>>(mus);
    gemm_dist_kernel<<<dim3(GG, BSZ / 128), 256>>>(X);
    reduce_kernel<<<1, 256>>>((float*)d_out);
}

// round 5
// speedup vs baseline: 3.3756x; 1.0493x over previous
#include <cuda_runtime.h>
#include <cuda_bf16.h>
#include <math.h>

// Problem sizes (fixed by the reference)
#define BSZ 2048
#define GG  64
#define DD  512
#define DD2 (DD * DD)
#define NB  32

// ---------------------------------------------------------------------------
// Scratch (device globals)
// g_L : per-gaussian Cholesky factor L, COLUMN-major (i>=j at j*DD+i).
//       Row-major view of the same buffer is U = L^T (valid at a*DD+b, b>=a).
// g_W : per-gaussian V = U^{-1}, ROW-major, zeros below diagonal.
// ---------------------------------------------------------------------------
__device__ __align__(16) float g_L[GG * DD2];              // 64 MB
__device__ __align__(16) float g_W[GG * DD2];              // 64 MB
__device__ __align__(16) float g_Dinv[GG * 16 * NB * NB];  // 4 MB
__device__ __align__(16) float g_u[GG * DD];
__device__ __align__(16) float g_dist[BSZ * GG];

#define CLUSTER_SYNC() do { \
    asm volatile("barrier.cluster.arrive.aligned;" ::: "memory"); \
    asm volatile("barrier.cluster.wait.aligned;"   ::: "memory"); \
} while (0)

// ---------------------------------------------------------------------------
// Kernel 0: copy covs -> g_L
// ---------------------------------------------------------------------------
__global__ __launch_bounds__(256)
void copy_cov(const float* __restrict__ c)
{
    const size_t n = (size_t)GG * DD2 / 4;
    for (size_t i = (size_t)blockIdx.x * blockDim.x + threadIdx.x; i < n;
         i += (size_t)gridDim.x * blockDim.x)
        ((float4*)g_L)[i] = ((const float4*)c)[i];
}

// ---------------------------------------------------------------------------
// Kernel 1: FUSED blocked Cholesky. Cluster of 4 CTAs per gaussian.
// Per panel step p:
//   - every CTA redundantly loads+factors the 32x32 diag block in smem
//   - CTA 0 writes the factored diag back
//   - each CTA solves its quarter of the panel rows (1 reg-resident row/thr)
//   - cluster sync  (panel visible cluster-wide)
//   - each CTA computes its share of the 64x64 lower SYRK tiles
//   - cluster sync  (trailing update visible for next step)
// ---------------------------------------------------------------------------
__global__ __launch_bounds__(256) __cluster_dims__(4, 1, 1)
void chol_fused()
{
    __shared__ float s11[NB][NB + 1];
    __shared__ float rdiag[NB];
    __shared__ __align__(16) float Pi[NB][68];
    __shared__ __align__(16) float Pj[NB][68];

    const int g = blockIdx.x >> 2;
    unsigned crank;
    asm("mov.u32 %0, %%cluster_ctarank;" : "=r"(crank));
    float* a = g_L + (size_t)g * DD2;
    const int tid = threadIdx.x;

    for (int p = 0; p < DD / NB; ++p) {
        const int base = p * NB;
        const int r = DD - base - NB;

        // ---- load diag block (redundant in every CTA)
        for (int q = tid; q < NB * NB; q += 256) {
            int i = q & 31, j = q >> 5;
            s11[i][j] = a[(size_t)(base + j) * DD + (base + i)];
        }
        __syncthreads();

        // ---- factor diag block with warp 0
        if (tid < 32) {
            const int lane = tid;
            for (int k = 0; k < NB; ++k) {
                if (lane == k) {
                    float v = s11[k][k];
                    float rs = rsqrtf(v);
                    s11[k][k] = v * rs;
                    rdiag[k] = rs;
                }
                __syncwarp();
                float lik = 0.f;
                if (lane > k) {
                    lik = s11[lane][k] * rdiag[k];
                    s11[lane][k] = lik;
                }
                __syncwarp();
                if (lane > k) {
                    for (int j = k + 1; j <= lane; ++j)
                        s11[lane][j] -= lik * s11[j][k];
                }
                __syncwarp();
            }
        }
        __syncthreads();

        // ---- CTA 0 writes factored diag back (lower incl diag)
        if (crank == 0) {
            for (int q = tid; q < NB * NB; q += 256) {
                int i = q & 31, j = q >> 5;
                if (i >= j) a[(size_t)(base + j) * DD + (base + i)] = s11[i][j];
            }
        }

        // ---- panel solve: my quarter of the rows, 1 row per thread
        if (r > 0) {
            const int chunk = (r + 3) >> 2;
            const int row = (int)crank * chunk + tid;
            if (row < r && tid < chunk) {
                const int gr = base + NB + row;
                float x[NB];
                #pragma unroll
                for (int j = 0; j < NB; ++j)
                    x[j] = a[(size_t)(base + j) * DD + gr];
                #pragma unroll
                for (int j = 0; j < NB; ++j) {
                    float s = x[j];
                    #pragma unroll
                    for (int k = 0; k < j; ++k)
                        s -= x[k] * s11[j][k];
                    x[j] = s * rdiag[j];
                }
                #pragma unroll
                for (int j = 0; j < NB; ++j)
                    a[(size_t)(base + j) * DD + gr] = x[j];
            }
        }
        CLUSTER_SYNC();

        // ---- SYRK trailing update: my share of the lower 64x64 tiles
        if (r > 0) {
            const int m = (r + 63) >> 6;
            const int ntiles = m * (m + 1) / 2;
            for (int t = (int)crank; t < ntiles; t += 4) {
                int ti = (int)((sqrtf(8.f * t + 1.f) - 1.f) * 0.5f);
                while ((ti + 1) * (ti + 2) / 2 <= t) ++ti;
                while (ti * (ti + 1) / 2 > t) --ti;
                const int tj = t - ti * (ti + 1) / 2;
                const int gi = ti * 64;
                const int gj = tj * 64;

                // stage panel rows [gi,gi+64) and [gj,gj+64) transposed
                #pragma unroll
                for (int f = 0; f < 2; ++f) {
                    const int s   = tid + 256 * f;
                    const int col = s >> 4;
                    const int r4  = s & 15;
                    {
                        const int row = gi + r4 * 4;
                        float4 v = make_float4(0.f, 0.f, 0.f, 0.f);
                        if (row < r)
                            v = *(const float4*)(a + (size_t)(base + col) * DD + base + NB + row);
                        *(float4*)&Pi[col][r4 * 4] = v;
                    }
                    {
                        const int row = gj + r4 * 4;
                        float4 v = make_float4(0.f, 0.f, 0.f, 0.f);
                        if (row < r)
                            v = *(const float4*)(a + (size_t)(base + col) * DD + base + NB + row);
                        *(float4*)&Pj[col][r4 * 4] = v;
                    }
                }
                __syncthreads();

                const int tx = tid & 15;
                const int ty = tid >> 4;
                float acc[4][4];
                #pragma unroll
                for (int ii = 0; ii < 4; ++ii)
                    #pragma unroll
                    for (int jj = 0; jj < 4; ++jj) acc[ii][jj] = 0.f;

                #pragma unroll
                for (int k = 0; k < NB; ++k) {
                    float4 pi = *(const float4*)&Pi[k][tx * 4];
                    float4 pj = *(const float4*)&Pj[k][ty * 4];
                    float pr[4] = {pi.x, pi.y, pi.z, pi.w};
                    float pc[4] = {pj.x, pj.y, pj.z, pj.w};
                    #pragma unroll
                    for (int ii = 0; ii < 4; ++ii)
                        #pragma unroll
                        for (int jj = 0; jj < 4; ++jj)
                            acc[ii][jj] += pr[ii] * pc[jj];
                }

                const int rowb = gi + tx * 4;
                if (rowb < r) {
                    #pragma unroll
                    for (int jj = 0; jj < 4; ++jj) {
                        const int colg = gj + ty * 4 + jj;
                        if (colg < r) {
                            float* pp = a + (size_t)(base + NB + colg) * DD + base + NB + rowb;
                            float4 cv = *(float4*)pp;
                            cv.x -= acc[0][jj]; cv.y -= acc[1][jj];
                            cv.z -= acc[2][jj]; cv.w -= acc[3][jj];
                            *(float4*)pp = cv;
                        }
                    }
                }
                __syncthreads();   // smem reuse across t iterations
            }
        }
        CLUSTER_SYNC();
    }
}

// ---------------------------------------------------------------------------
// Kernel 2a: invert the 16 diagonal 32x32 blocks of U = L^T. One warp per (g,d).
// ---------------------------------------------------------------------------
__global__ __launch_bounds__(128, 8)
void diaginv_kernel()
{
    __shared__ float su[4][NB][NB + 1];
    __shared__ float sx[4][NB][NB + 1];

    const int g = blockIdx.x;
    const int w = threadIdx.x >> 5;
    const int d = blockIdx.y * 4 + w;
    const int cc = threadIdx.x & 31;
    const float* U = g_L + (size_t)g * DD2;   // row-major view of U
    const int b0 = d * NB;

    for (int rr = 0; rr < NB; ++rr)
        su[w][rr][cc] = U[(size_t)(b0 + rr) * DD + (b0 + cc)];
    __syncwarp();

    for (int t = cc; t >= 0; --t) {
        float s = (t == cc) ? 1.f : 0.f;
        for (int ss = t + 1; ss <= cc; ++ss)
            s -= su[w][t][ss] * sx[w][ss][cc];
        sx[w][t][cc] = s / su[w][t][t];
    }
    __syncwarp();

    float* dst = g_Dinv + ((size_t)g * 16 + d) * NB * NB;
    for (int t = 0; t < NB; ++t)
        dst[t * NB + cc] = (t <= cc) ? sx[w][t][cc] : 0.f;
}

// ---------------------------------------------------------------------------
// Kernel 2b: blocked triangular inverse, one CTA per (g, block-column j).
// Fused u computation. Dynamic smem = 82,560 bytes.
// ---------------------------------------------------------------------------
#define T2_SMEM ((512*36 + 32*36 + 32*33) * 4)

__global__ __launch_bounds__(256)
void trinv_col_kernel(const float* __restrict__ mus)
{
    extern __shared__ float sm2[];
    float (*Vs)[36] = (float(*)[36])sm2;
    float (*Us)[36] = (float(*)[36])(sm2 + 512 * 36);
    float (*Ts)[33] = (float(*)[33])(sm2 + 512 * 36 + 32 * 36);

    const int g = blockIdx.x;
    const int j = blockIdx.y;
    const float* U = g_L + (size_t)g * DD2;
    float* W = g_W + (size_t)g * DD2;
    const int tid = threadIdx.x;
    const int cc  = tid & 31;
    const int q   = tid >> 5;

    {
        const float* din = g_Dinv + ((size_t)g * 16 + j) * NB * NB;
        #pragma unroll
        for (int t4 = 0; t4 < 4; ++t4) {
            int t = q * 4 + t4;
            Vs[j * NB + t][cc] = din[t * NB + cc];
        }
    }
    __syncthreads();

    for (int i = j - 1; i >= 0; --i) {
        float acc[4];
        #pragma unroll
        for (int r4 = 0; r4 < 4; ++r4) acc[r4] = 0.f;

        for (int k = i + 1; k <= j; ++k) {
            const float* ub = U + (size_t)(i * NB) * DD + k * NB;
            {
                const int rr = tid >> 3, t4 = tid & 7;
                *(float4*)&Us[rr][t4 * 4] = *(const float4*)&ub[(size_t)rr * DD + t4 * 4];
            }
            __syncthreads();
            #pragma unroll
            for (int t4 = 0; t4 < 8; ++t4) {
                float v0 = Vs[k * NB + t4 * 4 + 0][cc];
                float v1 = Vs[k * NB + t4 * 4 + 1][cc];
                float v2 = Vs[k * NB + t4 * 4 + 2][cc];
                float v3 = Vs[k * NB + t4 * 4 + 3][cc];
                #pragma unroll
                for (int r4 = 0; r4 < 4; ++r4) {
                    float4 u4 = *(const float4*)&Us[q * 4 + r4][t4 * 4];
                    acc[r4] += u4.x * v0 + u4.y * v1 + u4.z * v2 + u4.w * v3;
                }
            }
            __syncthreads();
        }

        #pragma unroll
        for (int r4 = 0; r4 < 4; ++r4) Ts[q * 4 + r4][cc] = acc[r4];
        {
            const float* din = g_Dinv + ((size_t)g * 16 + i) * NB * NB;
            const int rr = tid >> 3, t4 = tid & 7;
            *(float4*)&Us[rr][t4 * 4] = *(const float4*)&din[rr * NB + t4 * 4];
        }
        __syncthreads();

        float acc2[4];
        #pragma unroll
        for (int r4 = 0; r4 < 4; ++r4) acc2[r4] = 0.f;
        #pragma unroll
        for (int t4 = 0; t4 < 8; ++t4) {
            float v0 = Ts[t4 * 4 + 0][cc];
            float v1 = Ts[t4 * 4 + 1][cc];
            float v2 = Ts[t4 * 4 + 2][cc];
            float v3 = Ts[t4 * 4 + 3][cc];
            #pragma unroll
            for (int r4 = 0; r4 < 4; ++r4) {
                float4 u4 = *(const float4*)&Us[q * 4 + r4][t4 * 4];
                acc2[r4] += u4.x * v0 + u4.y * v1 + u4.z * v2 + u4.w * v3;
            }
        }
        #pragma unroll
        for (int r4 = 0; r4 < 4; ++r4) Vs[i * NB + q * 4 + r4][cc] = -acc2[r4];
        __syncthreads();
    }

    const int ncol = j * NB + cc;
    for (int row = q; row < (j + 1) * NB; row += 8)
        W[(size_t)row * DD + ncol] = Vs[row][cc];
    for (int row = (j + 1) * NB + q; row < DD; row += 8)
        W[(size_t)row * DD + ncol] = 0.f;

    {
        const float* mu = mus + (size_t)g * DD;
        float s = 0.f;
        for (int row = q; row < (j + 1) * NB; row += 8)
            s += mu[row] * Vs[row][cc];
        Us[q][cc] = s;
        __syncthreads();
        if (q == 0) {
            float tot = 0.f;
            #pragma unroll
            for (int w8 = 0; w8 < 8; ++w8) tot += Us[w8][cc];
            g_u[(size_t)g * DD + ncol] = tot;
        }
    }
}

// ---------------------------------------------------------------------------
// Kernel 4: triangular GEMM + fused dist epilogue. (unchanged from R4)
// ---------------------------------------------------------------------------
__global__ __launch_bounds__(256, 2)
void gemm_dist_kernel(const float* __restrict__ X)
{
    const int g  = blockIdx.x;
    const int b0 = blockIdx.y * 128;
    const float* W = g_W + (size_t)g * DD2;

    __shared__ __align__(16) float Xs[2][8][132];
    __shared__ __align__(16) float Vs[2][8][132];
    __shared__ float red[128][17];

    const int tid = threadIdx.x;
    const int tx  = tid & 15;
    const int ty  = tid >> 4;

    const int xbb = tid >> 1, xk4 = tid & 1;
    const int vkk = tid >> 5, vn4 = tid & 31;
    const float* Xp = X + (size_t)(b0 + xbb) * DD + xk4 * 4;

    float dist[8];
    #pragma unroll
    for (int r = 0; r < 8; ++r) dist[r] = 0.f;

    for (int nt = 0; nt < 4; ++nt) {
        const int n0 = nt * 128;
        const int nsteps = (nt + 1) * 16;
        const float* Vp = W + (size_t)vkk * DD + n0 + vn4 * 4;

        float acc[8][8];
        #pragma unroll
        for (int r = 0; r < 8; ++r)
            #pragma unroll
            for (int c = 0; c < 8; ++c) acc[r][c] = 0.f;

        {
            float4 v = *(const float4*)(Xp);
            Xs[0][xk4 * 4 + 0][xbb] = v.x;
            Xs[0][xk4 * 4 + 1][xbb] = v.y;
            Xs[0][xk4 * 4 + 2][xbb] = v.z;
            Xs[0][xk4 * 4 + 3][xbb] = v.w;
            float4 w = *(const float4*)(Vp);
            *(float4*)&Vs[0][vkk][vn4 * 4] = w;
        }
        __syncthreads();

        for (int s = 0; s < nsteps; ++s) {
            const int cur = s & 1;
            float4 nx, nv;
            const bool more = (s + 1 < nsteps);
            if (more) {
                nx = *(const float4*)(Xp + (s + 1) * 8);
                nv = *(const float4*)(Vp + (size_t)(s + 1) * 8 * DD);
            }

            #pragma unroll
            for (int kk = 0; kk < 8; ++kk) {
                float4 xa = *(const float4*)&Xs[cur][kk][ty * 8];
                float4 xb = *(const float4*)&Xs[cur][kk][ty * 8 + 4];
                float4 va = *(const float4*)&Vs[cur][kk][tx * 8];
                float4 vb = *(const float4*)&Vs[cur][kk][tx * 8 + 4];
                float xr[8] = {xa.x, xa.y, xa.z, xa.w, xb.x, xb.y, xb.z, xb.w};
                float vc[8] = {va.x, va.y, va.z, va.w, vb.x, vb.y, vb.z, vb.w};
                #pragma unroll
                for (int r = 0; r < 8; ++r)
                    #pragma unroll
                    for (int c = 0; c < 8; ++c)
                        acc[r][c] += xr[r] * vc[c];
            }

            if (more) {
                const int nxt = 1 - cur;
                Xs[nxt][xk4 * 4 + 0][xbb] = nx.x;
                Xs[nxt][xk4 * 4 + 1][xbb] = nx.y;
                Xs[nxt][xk4 * 4 + 2][xbb] = nx.z;
                Xs[nxt][xk4 * 4 + 3][xbb] = nx.w;
                *(float4*)&Vs[nxt][vkk][vn4 * 4] = nv;
                __syncthreads();
            }
        }

        float4 ua = *(const float4*)&g_u[(size_t)g * DD + n0 + tx * 8];
        float4 ub = *(const float4*)&g_u[(size_t)g * DD + n0 + tx * 8 + 4];
        float un[8] = {ua.x, ua.y, ua.z, ua.w, ub.x, ub.y, ub.z, ub.w};
        #pragma unroll
        for (int r = 0; r < 8; ++r)
            #pragma unroll
            for (int c = 0; c < 8; ++c) {
                float dz = acc[r][c] - un[c];
                dist[r] += dz * dz;
            }
        __syncthreads();
    }

    #pragma unroll
    for (int r = 0; r < 8; ++r) red[ty * 8 + r][tx] = dist[r];
    __syncthreads();
    if (tid < 128) {
        float s = 0.f;
        #pragma unroll
        for (int c = 0; c < 16; ++c) s += red[tid][c];
        g_dist[(size_t)(b0 + tid) * GG + g] = s;
    }
}

// ---------------------------------------------------------------------------
// Kernel 5: out = -mean_b( min_g relu(dist[b,g]) ) / 10000
// ---------------------------------------------------------------------------
__global__ __launch_bounds__(256, 1)
void reduce_kernel(float* __restrict__ out)
{
    __shared__ float sh[256];
    float s = 0.f;
    for (int b = threadIdx.x; b < BSZ; b += 256) {
        const float* row = g_dist + (size_t)b * GG;
        float m = fmaxf(row[0], 0.f);
        #pragma unroll 8
        for (int gi = 1; gi < GG; ++gi)
            m = fminf(m, fmaxf(row[gi], 0.f));
        s += m;
    }
    sh[threadIdx.x] = s;
    __syncthreads();
    for (int off = 128; off > 0; off >>= 1) {
        if (threadIdx.x < off) sh[threadIdx.x] += sh[threadIdx.x + off];
        __syncthreads();
    }
    if (threadIdx.x == 0)
        out[0] = -sh[0] / ((float)BSZ * 10000.0f);
}

// ---------------------------------------------------------------------------
extern "C" void kernel_launch(void* const* d_in, const int* in_sizes, int n_in,
                              void* d_out, int out_size)
{
    const float* X    = nullptr;
    const float* mus  = nullptr;
    const float* covs = nullptr;
    for (int i = 0; i < n_in; ++i) {
        if      (in_sizes[i] == BSZ * DD)      X    = (const float*)d_in[i];
        else if (in_sizes[i] == GG * DD)       mus  = (const float*)d_in[i];
        else if (in_sizes[i] == GG * DD * DD)  covs = (const float*)d_in[i];
    }

    static bool attr_done = false;
    if (!attr_done) {
        cudaFuncSetAttribute(trinv_col_kernel,
                             cudaFuncAttributeMaxDynamicSharedMemorySize, T2_SMEM);
        attr_done = true;
    }

    copy_cov<<<1024, 256>>>(covs);
    chol_fused<<<GG * 4, 256>>>();
    diaginv_kernel<<<dim3(GG, 4), 128>>>();
    trinv_col_kernel<<<dim3(GG, 16), 256, T2_SMEM>>>(mus);
    gemm_dist_kernel<<<dim3(GG, BSZ / 128), 256>>>(X);
    reduce_kernel<<<1, 256>>>((float*)d_out);
}

// round 7
// speedup vs baseline: 4.5461x; 1.3467x over previous
#include <cuda_runtime.h>
#include <cuda_bf16.h>
#include <math.h>
#include <stdint.h>

// Problem sizes (fixed by the reference)
#define BSZ 2048
#define GG  64
#define DD  512
#define DD2 (DD * DD)
#define NB  32

// ---------------------------------------------------------------------------
// Scratch (device globals)
// ---------------------------------------------------------------------------
__device__ __align__(16) float g_L[GG * DD2];              // L col-major / U row-major
__device__ __align__(16) float g_W[GG * DD2];              // V = U^{-1}, row-major
__device__ __align__(16) float g_Dinv[GG * 16 * NB * NB];
__device__ __align__(16) float g_u[GG * DD];
__device__ __align__(16) float g_dist[BSZ * GG];
__device__ __align__(16) __nv_bfloat16 g_Xhi[BSZ * DD];
__device__ __align__(16) __nv_bfloat16 g_Xlo[BSZ * DD];
__device__ __align__(16) __nv_bfloat16 g_Wthi[GG * DD2];   // Wt[n][k] = V[k][n]
__device__ __align__(16) __nv_bfloat16 g_Wtlo[GG * DD2];

#define CLUSTER_SYNC() do { \
    asm volatile("barrier.cluster.arrive.aligned;" ::: "memory"); \
    asm volatile("barrier.cluster.wait.aligned;"   ::: "memory"); \
} while (0)

// ---------------------------------------------------------------------------
// mma.sync helpers (portable sm_80+ tensor-core path; tcgen05 needs sm_103a
// target which this toolchain does not emit)
// ---------------------------------------------------------------------------
__device__ __forceinline__ void ldmx4(uint32_t* r, uint32_t addr) {
    asm volatile("ldmatrix.sync.aligned.m8n8.x4.shared.b16 {%0,%1,%2,%3}, [%4];"
                 : "=r"(r[0]), "=r"(r[1]), "=r"(r[2]), "=r"(r[3]) : "r"(addr));
}
__device__ __forceinline__ void mma16816(float* d, const uint32_t* a, const uint32_t* b) {
    asm volatile(
        "mma.sync.aligned.m16n8k16.row.col.f32.bf16.bf16.f32 "
        "{%0,%1,%2,%3}, {%4,%5,%6,%7}, {%8,%9}, {%0,%1,%2,%3};"
        : "+f"(d[0]), "+f"(d[1]), "+f"(d[2]), "+f"(d[3])
        : "r"(a[0]), "r"(a[1]), "r"(a[2]), "r"(a[3]), "r"(b[0]), "r"(b[1]));
}

// ---------------------------------------------------------------------------
// Kernel 0: copy covs -> g_L
// ---------------------------------------------------------------------------
__global__ __launch_bounds__(256)
void copy_cov(const float* __restrict__ c)
{
    const size_t n = (size_t)GG * DD2 / 4;
    for (size_t i = (size_t)blockIdx.x * blockDim.x + threadIdx.x; i < n;
         i += (size_t)gridDim.x * blockDim.x)
        ((float4*)g_L)[i] = ((const float4*)c)[i];
}

// ---------------------------------------------------------------------------
// Kernel 1: fused blocked Cholesky, cluster of 2 CTAs per gaussian
// (128 CTAs -> one wave; 148 = 2 x 74 packs perfectly).
// ---------------------------------------------------------------------------
__global__ __launch_bounds__(256) __cluster_dims__(2, 1, 1)
void chol_fused()
{
    __shared__ float s11[NB][NB + 1];
    __shared__ float rdiag[NB];
    __shared__ __align__(16) float Pi[NB][68];
    __shared__ __align__(16) float Pj[NB][68];

    const int g = blockIdx.x >> 1;
    unsigned crank;
    asm("mov.u32 %0, %%cluster_ctarank;" : "=r"(crank));
    float* a = g_L + (size_t)g * DD2;
    const int tid = threadIdx.x;

    for (int p = 0; p < DD / NB; ++p) {
        const int base = p * NB;
        const int r = DD - base - NB;

        for (int q = tid; q < NB * NB; q += 256) {
            int i = q & 31, j = q >> 5;
            s11[i][j] = a[(size_t)(base + j) * DD + (base + i)];
        }
        __syncthreads();

        if (tid < 32) {
            const int lane = tid;
            for (int k = 0; k < NB; ++k) {
                if (lane == k) {
                    float v = s11[k][k];
                    float rs = rsqrtf(v);
                    s11[k][k] = v * rs;
                    rdiag[k] = rs;
                }
                __syncwarp();
                float lik = 0.f;
                if (lane > k) {
                    lik = s11[lane][k] * rdiag[k];
                    s11[lane][k] = lik;
                }
                __syncwarp();
                if (lane > k) {
                    for (int j = k + 1; j <= lane; ++j)
                        s11[lane][j] -= lik * s11[j][k];
                }
                __syncwarp();
            }
        }
        __syncthreads();

        if (crank == 0) {
            for (int q = tid; q < NB * NB; q += 256) {
                int i = q & 31, j = q >> 5;
                if (i >= j) a[(size_t)(base + j) * DD + (base + i)] = s11[i][j];
            }
        }

        if (r > 0) {
            const int chunk = (r + 1) >> 1;
            const int row = (int)crank * chunk + tid;
            if (row < r && tid < chunk) {
                const int gr = base + NB + row;
                float x[NB];
                #pragma unroll
                for (int j = 0; j < NB; ++j)
                    x[j] = a[(size_t)(base + j) * DD + gr];
                #pragma unroll
                for (int j = 0; j < NB; ++j) {
                    float s = x[j];
                    #pragma unroll
                    for (int k = 0; k < j; ++k)
                        s -= x[k] * s11[j][k];
                    x[j] = s * rdiag[j];
                }
                #pragma unroll
                for (int j = 0; j < NB; ++j)
                    a[(size_t)(base + j) * DD + gr] = x[j];
            }
        }
        CLUSTER_SYNC();

        if (r > 0) {
            const int m = (r + 63) >> 6;
            const int ntiles = m * (m + 1) / 2;
            for (int t = (int)crank; t < ntiles; t += 2) {
                int ti = (int)((sqrtf(8.f * t + 1.f) - 1.f) * 0.5f);
                while ((ti + 1) * (ti + 2) / 2 <= t) ++ti;
                while (ti * (ti + 1) / 2 > t) --ti;
                const int tj = t - ti * (ti + 1) / 2;
                const int gi = ti * 64;
                const int gj = tj * 64;

                #pragma unroll
                for (int f = 0; f < 2; ++f) {
                    const int s   = tid + 256 * f;
                    const int col = s >> 4;
                    const int r4  = s & 15;
                    {
                        const int row = gi + r4 * 4;
                        float4 v = make_float4(0.f, 0.f, 0.f, 0.f);
                        if (row < r)
                            v = *(const float4*)(a + (size_t)(base + col) * DD + base + NB + row);
                        *(float4*)&Pi[col][r4 * 4] = v;
                    }
                    {
                        const int row = gj + r4 * 4;
                        float4 v = make_float4(0.f, 0.f, 0.f, 0.f);
                        if (row < r)
                            v = *(const float4*)(a + (size_t)(base + col) * DD + base + NB + row);
                        *(float4*)&Pj[col][r4 * 4] = v;
                    }
                }
                __syncthreads();

                const int tx = tid & 15;
                const int ty = tid >> 4;
                float acc[4][4];
                #pragma unroll
                for (int ii = 0; ii < 4; ++ii)
                    #pragma unroll
                    for (int jj = 0; jj < 4; ++jj) acc[ii][jj] = 0.f;

                #pragma unroll
                for (int k = 0; k < NB; ++k) {
                    float4 pi = *(const float4*)&Pi[k][tx * 4];
                    float4 pj = *(const float4*)&Pj[k][ty * 4];
                    float pr[4] = {pi.x, pi.y, pi.z, pi.w};
                    float pc[4] = {pj.x, pj.y, pj.z, pj.w};
                    #pragma unroll
                    for (int ii = 0; ii < 4; ++ii)
                        #pragma unroll
                        for (int jj = 0; jj < 4; ++jj)
                            acc[ii][jj] += pr[ii] * pc[jj];
                }

                const int rowb = gi + tx * 4;
                if (rowb < r) {
                    #pragma unroll
                    for (int jj = 0; jj < 4; ++jj) {
                        const int colg = gj + ty * 4 + jj;
                        if (colg < r) {
                            float* pp = a + (size_t)(base + NB + colg) * DD + base + NB + rowb;
                            float4 cv = *(float4*)pp;
                            cv.x -= acc[0][jj]; cv.y -= acc[1][jj];
                            cv.z -= acc[2][jj]; cv.w -= acc[3][jj];
                            *(float4*)pp = cv;
                        }
                    }
                }
                __syncthreads();
            }
        }
        CLUSTER_SYNC();
    }
}

// ---------------------------------------------------------------------------
// Kernel 2a: invert 16 diagonal 32x32 blocks of U = L^T. One warp per (g,d).
// ---------------------------------------------------------------------------
__global__ __launch_bounds__(128, 8)
void diaginv_kernel()
{
    __shared__ float su[4][NB][NB + 1];
    __shared__ float sx[4][NB][NB + 1];

    const int g = blockIdx.x;
    const int w = threadIdx.x >> 5;
    const int d = blockIdx.y * 4 + w;
    const int cc = threadIdx.x & 31;
    const float* U = g_L + (size_t)g * DD2;
    const int b0 = d * NB;

    for (int rr = 0; rr < NB; ++rr)
        su[w][rr][cc] = U[(size_t)(b0 + rr) * DD + (b0 + cc)];
    __syncwarp();

    for (int t = cc; t >= 0; --t) {
        float s = (t == cc) ? 1.f : 0.f;
        for (int ss = t + 1; ss <= cc; ++ss)
            s -= su[w][t][ss] * sx[w][ss][cc];
        sx[w][t][cc] = s / su[w][t][t];
    }
    __syncwarp();

    float* dst = g_Dinv + ((size_t)g * 16 + d) * NB * NB;
    for (int t = 0; t < NB; ++t)
        dst[t * NB + cc] = (t <= cc) ? sx[w][t][cc] : 0.f;
}

// ---------------------------------------------------------------------------
// Kernel 2b: blocked triangular inverse + fused u. One CTA per (g, block-col).
// ---------------------------------------------------------------------------
#define T2_SMEM ((512*36 + 32*36 + 32*33) * 4)

__global__ __launch_bounds__(256)
void trinv_col_kernel(const float* __restrict__ mus)
{
    extern __shared__ float sm2[];
    float (*Vs)[36] = (float(*)[36])sm2;
    float (*Us)[36] = (float(*)[36])(sm2 + 512 * 36);
    float (*Ts)[33] = (float(*)[33])(sm2 + 512 * 36 + 32 * 36);

    const int g = blockIdx.x;
    const int j = blockIdx.y;
    const float* U = g_L + (size_t)g * DD2;
    float* W = g_W + (size_t)g * DD2;
    const int tid = threadIdx.x;
    const int cc  = tid & 31;
    const int q   = tid >> 5;

    {
        const float* din = g_Dinv + ((size_t)g * 16 + j) * NB * NB;
        #pragma unroll
        for (int t4 = 0; t4 < 4; ++t4) {
            int t = q * 4 + t4;
            Vs[j * NB + t][cc] = din[t * NB + cc];
        }
    }
    __syncthreads();

    for (int i = j - 1; i >= 0; --i) {
        float acc[4];
        #pragma unroll
        for (int r4 = 0; r4 < 4; ++r4) acc[r4] = 0.f;

        for (int k = i + 1; k <= j; ++k) {
            const float* ub = U + (size_t)(i * NB) * DD + k * NB;
            {
                const int rr = tid >> 3, t4 = tid & 7;
                *(float4*)&Us[rr][t4 * 4] = *(const float4*)&ub[(size_t)rr * DD + t4 * 4];
            }
            __syncthreads();
            #pragma unroll
            for (int t4 = 0; t4 < 8; ++t4) {
                float v0 = Vs[k * NB + t4 * 4 + 0][cc];
                float v1 = Vs[k * NB + t4 * 4 + 1][cc];
                float v2 = Vs[k * NB + t4 * 4 + 2][cc];
                float v3 = Vs[k * NB + t4 * 4 + 3][cc];
                #pragma unroll
                for (int r4 = 0; r4 < 4; ++r4) {
                    float4 u4 = *(const float4*)&Us[q * 4 + r4][t4 * 4];
                    acc[r4] += u4.x * v0 + u4.y * v1 + u4.z * v2 + u4.w * v3;
                }
            }
            __syncthreads();
        }

        #pragma unroll
        for (int r4 = 0; r4 < 4; ++r4) Ts[q * 4 + r4][cc] = acc[r4];
        {
            const float* din = g_Dinv + ((size_t)g * 16 + i) * NB * NB;
            const int rr = tid >> 3, t4 = tid & 7;
            *(float4*)&Us[rr][t4 * 4] = *(const float4*)&din[rr * NB + t4 * 4];
        }
        __syncthreads();

        float acc2[4];
        #pragma unroll
        for (int r4 = 0; r4 < 4; ++r4) acc2[r4] = 0.f;
        #pragma unroll
        for (int t4 = 0; t4 < 8; ++t4) {
            float v0 = Ts[t4 * 4 + 0][cc];
            float v1 = Ts[t4 * 4 + 1][cc];
            float v2 = Ts[t4 * 4 + 2][cc];
            float v3 = Ts[t4 * 4 + 3][cc];
            #pragma unroll
            for (int r4 = 0; r4 < 4; ++r4) {
                float4 u4 = *(const float4*)&Us[q * 4 + r4][t4 * 4];
                acc2[r4] += u4.x * v0 + u4.y * v1 + u4.z * v2 + u4.w * v3;
            }
        }
        #pragma unroll
        for (int r4 = 0; r4 < 4; ++r4) Vs[i * NB + q * 4 + r4][cc] = -acc2[r4];
        __syncthreads();
    }

    const int ncol = j * NB + cc;
    for (int row = q; row < (j + 1) * NB; row += 8)
        W[(size_t)row * DD + ncol] = Vs[row][cc];
    for (int row = (j + 1) * NB + q; row < DD; row += 8)
        W[(size_t)row * DD + ncol] = 0.f;

    {
        const float* mu = mus + (size_t)g * DD;
        float s = 0.f;
        for (int row = q; row < (j + 1) * NB; row += 8)
            s += mu[row] * Vs[row][cc];
        Us[q][cc] = s;
        __syncthreads();
        if (q == 0) {
            float tot = 0.f;
            #pragma unroll
            for (int w8 = 0; w8 < 8; ++w8) tot += Us[w8][cc];
            g_u[(size_t)g * DD + ncol] = tot;
        }
    }
}

// ---------------------------------------------------------------------------
// Kernel 3a: split X into bf16 hi/lo.
// ---------------------------------------------------------------------------
__global__ __launch_bounds__(256)
void split_x(const float* __restrict__ X)
{
    const int n = BSZ * DD / 4;
    for (int i = blockIdx.x * 256 + threadIdx.x; i < n; i += gridDim.x * 256) {
        float4 v = ((const float4*)X)[i];
        float f[4] = {v.x, v.y, v.z, v.w};
        __nv_bfloat16 h[4], l[4];
        #pragma unroll
        for (int j = 0; j < 4; ++j) {
            h[j] = __float2bfloat16(f[j]);
            l[j] = __float2bfloat16(f[j] - __bfloat162float(h[j]));
        }
        ((uint2*)g_Xhi)[i] = *(uint2*)h;
        ((uint2*)g_Xlo)[i] = *(uint2*)l;
    }
}

// ---------------------------------------------------------------------------
// Kernel 3b: transpose+split W -> Wt_hi/Wt_lo (Wt[n][k] = W[k][n]).
// ---------------------------------------------------------------------------
__global__ __launch_bounds__(256)
void wtrans_kernel()
{
    __shared__ float ts[64][65];
    const int g  = blockIdx.x;
    const int k0 = blockIdx.y * 64;
    const int n0 = blockIdx.z * 64;
    const float* W = g_W + (size_t)g * DD2;
    const int tid = threadIdx.x;

    #pragma unroll
    for (int i = 0; i < 4; ++i) {
        const int slot = tid + 256 * i;
        const int r = slot >> 4, c4 = slot & 15;
        float4 v = *(const float4*)&W[(size_t)(k0 + r) * DD + n0 + c4 * 4];
        ts[r][c4 * 4 + 0] = v.x; ts[r][c4 * 4 + 1] = v.y;
        ts[r][c4 * 4 + 2] = v.z; ts[r][c4 * 4 + 3] = v.w;
    }
    __syncthreads();

    __nv_bfloat16* hi = g_Wthi + (size_t)g * DD2;
    __nv_bfloat16* lo = g_Wtlo + (size_t)g * DD2;
    #pragma unroll
    for (int i = 0; i < 4; ++i) {
        const int slot = tid + 256 * i;
        const int r = slot >> 4, c4 = slot & 15;
        __nv_bfloat16 h[4], l[4];
        #pragma unroll
        for (int j = 0; j < 4; ++j) {
            float f = ts[c4 * 4 + j][r];
            h[j] = __float2bfloat16(f);
            l[j] = __float2bfloat16(f - __bfloat162float(h[j]));
        }
        const size_t off = (size_t)(n0 + r) * DD + k0 + c4 * 4;
        *(uint2*)(hi + off) = *(uint2*)h;
        *(uint2*)(lo + off) = *(uint2*)l;
    }
}

// ---------------------------------------------------------------------------
// Kernel 4: bf16-split GEMM via mma.sync + fused dist epilogue.
// CTA: 128(b) x 128(n), 8 warps (4m x 2n), warp tile 32x64.
// Smem rows: [hi 16 bf16 | lo 16 bf16 | pad 8] = 40 bf16 = 80B (16B-aligned,
// ldmatrix conflict-free: 20*r mod 32 distinct over 8 rows).
// z = Xhi*Whi + Xhi*Wlo + Xlo*Whi, fp32 accum; triangular k per 128-col tile.
// ---------------------------------------------------------------------------
#define PITCH 40

__global__ __launch_bounds__(256)
void mma_dist_kernel()
{
    __shared__ __align__(16) __nv_bfloat16 As[2][128][PITCH];
    __shared__ __align__(16) __nv_bfloat16 Bs[2][128][PITCH];
    __shared__ float sU[512];
    __shared__ float red[128][2];

    const int tid  = threadIdx.x;
    const int lane = tid & 31;
    const int wid  = tid >> 5;
    const int wm   = wid >> 1;     // 0..3  (m band of 32)
    const int wn   = wid & 1;      // 0..1  (n band of 64)
    const int g    = blockIdx.y;
    const int b0   = blockIdx.x * 128;

    for (int c = tid; c < 512; c += 256) sU[c] = g_u[(size_t)g * DD + c];

    const __nv_bfloat16* Xh = g_Xhi + (size_t)b0 * DD;
    const __nv_bfloat16* Xl = g_Xlo + (size_t)b0 * DD;
    const __nv_bfloat16* Wh = g_Wthi + (size_t)g * DD2;
    const __nv_bfloat16* Wl = g_Wtlo + (size_t)g * DD2;

    const int lrow = tid >> 1;     // 0..127 (load row)
    const int lch  = tid & 1;      // k chunk (8 bf16)

    const uint32_t aS = (uint32_t)__cvta_generic_to_shared(&As[0][0][0]);
    const uint32_t bS = (uint32_t)__cvta_generic_to_shared(&Bs[0][0][0]);

    // ldmatrix source addresses (constant per thread, + buffer offset)
    const int arow = wm * 32 + (lane & 15);
    const int acol = (lane >> 4) * 8;
    const int bgrp = lane >> 3, bidx = lane & 7;
    const int brow = (bgrp >> 1) * 8 + bidx;
    const int bcol = (bgrp & 1) * 8;
    const uint32_t bufStride = 128 * PITCH * 2;   // bytes per buffer

    float distacc[4] = {0.f, 0.f, 0.f, 0.f};

    for (int nt = 0; nt < 4; ++nt) {
        const int n0 = nt * 128;
        const int nsteps = (nt + 1) * 8;          // k16 stages (kend = n0+128)

        float acc[2][8][4];
        #pragma unroll
        for (int mt = 0; mt < 2; ++mt)
            #pragma unroll
            for (int j = 0; j < 8; ++j)
                #pragma unroll
                for (int e = 0; e < 4; ++e) acc[mt][j][e] = 0.f;

        // stage 0: global -> smem buf0
        {
            const size_t oA = (size_t)lrow * DD + lch * 8;
            const size_t oB = (size_t)(n0 + lrow) * DD + lch * 8;
            *(uint4*)&As[0][lrow][lch * 8]      = *(const uint4*)(Xh + oA);
            *(uint4*)&As[0][lrow][16 + lch * 8] = *(const uint4*)(Xl + oA);
            *(uint4*)&Bs[0][lrow][lch * 8]      = *(const uint4*)(Wh + oB);
            *(uint4*)&Bs[0][lrow][16 + lch * 8] = *(const uint4*)(Wl + oB);
        }
        __syncthreads();

        for (int s = 0; s < nsteps; ++s) {
            const int cur = s & 1;
            const bool more = (s + 1 < nsteps);
            uint4 pAh, pAl, pBh, pBl;
            if (more) {
                const int k0 = (s + 1) * 16;
                const size_t oA = (size_t)lrow * DD + k0 + lch * 8;
                const size_t oB = (size_t)(n0 + lrow) * DD + k0 + lch * 8;
                pAh = *(const uint4*)(Xh + oA);
                pAl = *(const uint4*)(Xl + oA);
                pBh = *(const uint4*)(Wh + oB);
                pBl = *(const uint4*)(Wl + oB);
            }

            // A fragments (both m16 tiles, hi+lo)
            uint32_t ah[2][4], al[2][4];
            #pragma unroll
            for (int mt = 0; mt < 2; ++mt) {
                uint32_t ad = aS + cur * bufStride
                            + (uint32_t)(((arow + mt * 16) * PITCH + acol) * 2);
                ldmx4(ah[mt], ad);
                ldmx4(al[mt], ad + 32);   // +16 bf16 = lo half
            }

            #pragma unroll
            for (int nb = 0; nb < 4; ++nb) {
                uint32_t bh[4], bl[4];
                uint32_t bd = bS + cur * bufStride
                            + (uint32_t)(((wn * 64 + nb * 16 + brow) * PITCH + bcol) * 2);
                ldmx4(bh, bd);
                ldmx4(bl, bd + 32);
                #pragma unroll
                for (int mt = 0; mt < 2; ++mt) {
                    #pragma unroll
                    for (int h = 0; h < 2; ++h) {
                        float* d = acc[mt][nb * 2 + h];
                        mma16816(d, ah[mt], &bh[h * 2]);
                        mma16816(d, ah[mt], &bl[h * 2]);
                        mma16816(d, al[mt], &bh[h * 2]);
                    }
                }
            }

            if (more) {
                const int nxt = cur ^ 1;
                *(uint4*)&As[nxt][lrow][lch * 8]      = pAh;
                *(uint4*)&As[nxt][lrow][16 + lch * 8] = pAl;
                *(uint4*)&Bs[nxt][lrow][lch * 8]      = pBh;
                *(uint4*)&Bs[nxt][lrow][16 + lch * 8] = pBl;
                __syncthreads();
            }
        }

        // fold (z-u)^2 into distacc
        #pragma unroll
        for (int mt = 0; mt < 2; ++mt)
            #pragma unroll
            for (int j = 0; j < 8; ++j) {
                const int coln = n0 + wn * 64 + j * 8 + (lane & 3) * 2;
                const float u0 = sU[coln], u1 = sU[coln + 1];
                float z0 = acc[mt][j][0] - u0, z1 = acc[mt][j][1] - u1;
                float z2 = acc[mt][j][2] - u0, z3 = acc[mt][j][3] - u1;
                distacc[mt * 2 + 0] += z0 * z0 + z1 * z1;
                distacc[mt * 2 + 1] += z2 * z2 + z3 * z3;
            }
        __syncthreads();   // before next nt's stage-0 preload
    }

    // reduce over the 4 lanes sharing a row (lane&3), then across wn via smem
    #pragma unroll
    for (int i = 0; i < 4; ++i) {
        distacc[i] += __shfl_xor_sync(0xffffffff, distacc[i], 1);
        distacc[i] += __shfl_xor_sync(0xffffffff, distacc[i], 2);
    }
    if ((lane & 3) == 0) {
        const int r = lane >> 2;                 // 0..7
        red[wm * 32 + r][wn]      = distacc[0];
        red[wm * 32 + r + 8][wn]  = distacc[1];
        red[wm * 32 + r + 16][wn] = distacc[2];
        red[wm * 32 + r + 24][wn] = distacc[3];
    }
    __syncthreads();
    if (tid < 128)
        g_dist[(size_t)(b0 + tid) * GG + g] = red[tid][0] + red[tid][1];
}

// ---------------------------------------------------------------------------
// Kernel 5: out = -mean_b( min_g relu(dist[b,g]) ) / 10000
// ---------------------------------------------------------------------------
__global__ __launch_bounds__(256, 1)
void reduce_kernel(float* __restrict__ out)
{
    __shared__ float sh[256];
    float s = 0.f;
    for (int b = threadIdx.x; b < BSZ; b += 256) {
        const float* row = g_dist + (size_t)b * GG;
        float m = fmaxf(row[0], 0.f);
        #pragma unroll 8
        for (int gi = 1; gi < GG; ++gi)
            m = fminf(m, fmaxf(row[gi], 0.f));
        s += m;
    }
    sh[threadIdx.x] = s;
    __syncthreads();
    for (int off = 128; off > 0; off >>= 1) {
        if (threadIdx.x < off) sh[threadIdx.x] += sh[threadIdx.x + off];
        __syncthreads();
    }
    if (threadIdx.x == 0)
        out[0] = -sh[0] / ((float)BSZ * 10000.0f);
}

// ---------------------------------------------------------------------------
extern "C" void kernel_launch(void* const* d_in, const int* in_sizes, int n_in,
                              void* d_out, int out_size)
{
    const float* X    = nullptr;
    const float* mus  = nullptr;
    const float* covs = nullptr;
    for (int i = 0; i < n_in; ++i) {
        if      (in_sizes[i] == BSZ * DD)      X    = (const float*)d_in[i];
        else if (in_sizes[i] == GG * DD)       mus  = (const float*)d_in[i];
        else if (in_sizes[i] == GG * DD * DD)  covs = (const float*)d_in[i];
    }

    static bool attr_done = false;
    if (!attr_done) {
        cudaFuncSetAttribute(trinv_col_kernel,
                             cudaFuncAttributeMaxDynamicSharedMemorySize, T2_SMEM);
        attr_done = true;
    }

    copy_cov<<<1024, 256>>>(covs);
    split_x<<<512, 256>>>(X);
    chol_fused<<<GG * 2, 256>>>();
    diaginv_kernel<<<dim3(GG, 4), 128>>>();
    trinv_col_kernel<<<dim3(GG, 16), 256, T2_SMEM>>>(mus);
    wtrans_kernel<<<dim3(GG, 8, 8), 256>>>();
    mma_dist_kernel<<<dim3(BSZ / 128, GG), 256>>>();
    reduce_kernel<<<1, 256>>>((float*)d_out);
}

// round 8
// speedup vs baseline: 4.7425x; 1.0432x over previous
#include <cuda_runtime.h>
#include <cuda_bf16.h>
#include <math.h>
#include <stdint.h>

// Problem sizes (fixed by the reference)
#define BSZ 2048
#define GG  64
#define DD  512
#define DD2 (DD * DD)
#define NB  32

// ---------------------------------------------------------------------------
// Scratch (device globals)
// g_L : per-gaussian Cholesky factor L, COLUMN-major (i>=j at j*DD+i).
//       Row-major view is U = L^T (valid at a*DD+b, b>=a).
// g_Wt*: transposed bf16-split inverse: Wt[n][k] = V[k][n], V = U^{-1}.
// ---------------------------------------------------------------------------
__device__ __align__(16) float g_L[GG * DD2];
__device__ __align__(16) float g_Dinv[GG * 16 * NB * NB];
__device__ __align__(16) float g_u[GG * DD];
__device__ __align__(16) float g_dist[BSZ * GG];
__device__ __align__(16) __nv_bfloat16 g_Xhi[BSZ * DD];
__device__ __align__(16) __nv_bfloat16 g_Xlo[BSZ * DD];
__device__ __align__(16) __nv_bfloat16 g_Wthi[GG * DD2];
__device__ __align__(16) __nv_bfloat16 g_Wtlo[GG * DD2];

#define CLUSTER_SYNC() do { \
    asm volatile("barrier.cluster.arrive.aligned;" ::: "memory"); \
    asm volatile("barrier.cluster.wait.aligned;"   ::: "memory"); \
} while (0)

// ---------------------------------------------------------------------------
// mma.sync / cp.async helpers (portable sm_80+ path)
// ---------------------------------------------------------------------------
__device__ __forceinline__ void ldmx4(uint32_t* r, uint32_t addr) {
    asm volatile("ldmatrix.sync.aligned.m8n8.x4.shared.b16 {%0,%1,%2,%3}, [%4];"
                 : "=r"(r[0]), "=r"(r[1]), "=r"(r[2]), "=r"(r[3]) : "r"(addr));
}
__device__ __forceinline__ void mma16816(float* d, const uint32_t* a, const uint32_t* b) {
    asm volatile(
        "mma.sync.aligned.m16n8k16.row.col.f32.bf16.bf16.f32 "
        "{%0,%1,%2,%3}, {%4,%5,%6,%7}, {%8,%9}, {%0,%1,%2,%3};"
        : "+f"(d[0]), "+f"(d[1]), "+f"(d[2]), "+f"(d[3])
        : "r"(a[0]), "r"(a[1]), "r"(a[2]), "r"(a[3]), "r"(b[0]), "r"(b[1]));
}
__device__ __forceinline__ void cp16(uint32_t s, const void* g) {
    asm volatile("cp.async.ca.shared.global [%0], [%1], 16;" :: "r"(s), "l"(g));
}

// ---------------------------------------------------------------------------
// Kernel 1: fused blocked Cholesky, cluster of 2 CTAs per gaussian.
// p=0 reads covs directly (symmetric => same indexing); no separate copy pass.
// SYRK iterates tile-rows per CTA: Pi staged once per row, Pj per tile.
// ---------------------------------------------------------------------------
__global__ __launch_bounds__(256) __cluster_dims__(2, 1, 1)
void chol_fused(const float* __restrict__ covs)
{
    __shared__ float s11[NB][NB + 1];
    __shared__ float rdiag[NB];
    __shared__ __align__(16) float Pi[NB][68];
    __shared__ __align__(16) float Pj[NB][68];

    const int g = blockIdx.x >> 1;
    unsigned crank;
    asm("mov.u32 %0, %%cluster_ctarank;" : "=r"(crank));
    float* a = g_L + (size_t)g * DD2;
    const float* cv = covs + (size_t)g * DD2;
    const int tid = threadIdx.x;

    for (int p = 0; p < DD / NB; ++p) {
        const int base = p * NB;
        const int r = DD - base - NB;
        const float* src = (p == 0) ? cv : a;   // unfactored data source

        // ---- load diag block
        for (int q = tid; q < NB * NB; q += 256) {
            int i = q & 31, j = q >> 5;
            s11[i][j] = src[(size_t)(base + j) * DD + (base + i)];
        }
        __syncthreads();

        // ---- factor diag with warp 0
        if (tid < 32) {
            const int lane = tid;
            for (int k = 0; k < NB; ++k) {
                if (lane == k) {
                    float v = s11[k][k];
                    float rs = rsqrtf(v);
                    s11[k][k] = v * rs;
                    rdiag[k] = rs;
                }
                __syncwarp();
                float lik = 0.f;
                if (lane > k) {
                    lik = s11[lane][k] * rdiag[k];
                    s11[lane][k] = lik;
                }
                __syncwarp();
                if (lane > k) {
                    for (int j = k + 1; j <= lane; ++j)
                        s11[lane][j] -= lik * s11[j][k];
                }
                __syncwarp();
            }
        }
        __syncthreads();

        if (crank == 0) {
            for (int q = tid; q < NB * NB; q += 256) {
                int i = q & 31, j = q >> 5;
                if (i >= j) a[(size_t)(base + j) * DD + (base + i)] = s11[i][j];
            }
        }

        // ---- panel solve: my half of rows, 1 reg-resident row per thread
        if (r > 0) {
            const int chunk = (r + 1) >> 1;
            const int row = (int)crank * chunk + tid;
            if (row < r && tid < chunk) {
                const int gr = base + NB + row;
                float x[NB];
                #pragma unroll
                for (int j = 0; j < NB; ++j)
                    x[j] = src[(size_t)(base + j) * DD + gr];
                #pragma unroll
                for (int j = 0; j < NB; ++j) {
                    float s = x[j];
                    #pragma unroll
                    for (int k = 0; k < j; ++k)
                        s -= x[k] * s11[j][k];
                    x[j] = s * rdiag[j];
                }
                #pragma unroll
                for (int j = 0; j < NB; ++j)
                    a[(size_t)(base + j) * DD + gr] = x[j];
            }
        }
        CLUSTER_SYNC();

        // ---- SYRK: tile-rows assigned by parity; Pi staged once per row
        if (r > 0) {
            const int m = (r + 63) >> 6;
            for (int ti = (int)crank; ti < m; ti += 2) {
                const int gi = ti * 64;
                // stage Pi (panel rows gi..gi+63, transposed), from a
                #pragma unroll
                for (int f = 0; f < 2; ++f) {
                    const int s   = tid + 256 * f;
                    const int col = s >> 4;
                    const int r4  = s & 15;
                    const int row = gi + r4 * 4;
                    float4 v = make_float4(0.f, 0.f, 0.f, 0.f);
                    if (row < r)
                        v = *(const float4*)(a + (size_t)(base + col) * DD + base + NB + row);
                    *(float4*)&Pi[col][r4 * 4] = v;
                }

                for (int tj = 0; tj <= ti; ++tj) {
                    const int gj = tj * 64;
                    #pragma unroll
                    for (int f = 0; f < 2; ++f) {
                        const int s   = tid + 256 * f;
                        const int col = s >> 4;
                        const int r4  = s & 15;
                        const int row = gj + r4 * 4;
                        float4 v = make_float4(0.f, 0.f, 0.f, 0.f);
                        if (row < r)
                            v = *(const float4*)(a + (size_t)(base + col) * DD + base + NB + row);
                        *(float4*)&Pj[col][r4 * 4] = v;
                    }
                    __syncthreads();

                    const int tx = tid & 15;
                    const int ty = tid >> 4;
                    float acc[4][4];
                    #pragma unroll
                    for (int ii = 0; ii < 4; ++ii)
                        #pragma unroll
                        for (int jj = 0; jj < 4; ++jj) acc[ii][jj] = 0.f;

                    #pragma unroll
                    for (int k = 0; k < NB; ++k) {
                        float4 pi = *(const float4*)&Pi[k][tx * 4];
                        float4 pj = *(const float4*)&Pj[k][ty * 4];
                        float pr[4] = {pi.x, pi.y, pi.z, pi.w};
                        float pc[4] = {pj.x, pj.y, pj.z, pj.w};
                        #pragma unroll
                        for (int ii = 0; ii < 4; ++ii)
                            #pragma unroll
                            for (int jj = 0; jj < 4; ++jj)
                                acc[ii][jj] += pr[ii] * pc[jj];
                    }

                    const int rowb = gi + tx * 4;
                    if (rowb < r) {
                        #pragma unroll
                        for (int jj = 0; jj < 4; ++jj) {
                            const int colg = gj + ty * 4 + jj;
                            if (colg < r) {
                                const size_t off = (size_t)(base + NB + colg) * DD + base + NB + rowb;
                                float4 cvv = *(const float4*)(src + off);
                                cvv.x -= acc[0][jj]; cvv.y -= acc[1][jj];
                                cvv.z -= acc[2][jj]; cvv.w -= acc[3][jj];
                                *(float4*)(a + off) = cvv;
                            }
                        }
                    }
                    __syncthreads();
                }
            }
        }
        CLUSTER_SYNC();
    }
}

// ---------------------------------------------------------------------------
// Kernel 2a: invert 16 diagonal 32x32 blocks of U = L^T. One warp per (g,d).
// ---------------------------------------------------------------------------
__global__ __launch_bounds__(128, 8)
void diaginv_kernel()
{
    __shared__ float su[4][NB][NB + 1];
    __shared__ float sx[4][NB][NB + 1];

    const int g = blockIdx.x;
    const int w = threadIdx.x >> 5;
    const int d = blockIdx.y * 4 + w;
    const int cc = threadIdx.x & 31;
    const float* U = g_L + (size_t)g * DD2;
    const int b0 = d * NB;

    for (int rr = 0; rr < NB; ++rr)
        su[w][rr][cc] = U[(size_t)(b0 + rr) * DD + (b0 + cc)];
    __syncwarp();

    for (int t = cc; t >= 0; --t) {
        float s = (t == cc) ? 1.f : 0.f;
        for (int ss = t + 1; ss <= cc; ++ss)
            s -= su[w][t][ss] * sx[w][ss][cc];
        sx[w][t][cc] = s / su[w][t][t];
    }
    __syncwarp();

    float* dst = g_Dinv + ((size_t)g * 16 + d) * NB * NB;
    for (int t = 0; t < NB; ++t)
        dst[t * NB + cc] = (t <= cc) ? sx[w][t][cc] : 0.f;
}

// ---------------------------------------------------------------------------
// Kernel 2b: blocked triangular inverse + fused u + fused transposed bf16
// split output. One CTA per (g, block-column j).
// ---------------------------------------------------------------------------
#define T2_SMEM ((512*36 + 32*36 + 32*33) * 4)

__global__ __launch_bounds__(256)
void trinv_col_kernel(const float* __restrict__ mus)
{
    extern __shared__ float sm2[];
    float (*Vs)[36] = (float(*)[36])sm2;
    float (*Us)[36] = (float(*)[36])(sm2 + 512 * 36);
    float (*Ts)[33] = (float(*)[33])(sm2 + 512 * 36 + 32 * 36);

    const int g = blockIdx.x;
    const int j = blockIdx.y;
    const float* U = g_L + (size_t)g * DD2;
    const int tid = threadIdx.x;
    const int cc  = tid & 31;
    const int q   = tid >> 5;

    {
        const float* din = g_Dinv + ((size_t)g * 16 + j) * NB * NB;
        #pragma unroll
        for (int t4 = 0; t4 < 4; ++t4) {
            int t = q * 4 + t4;
            Vs[j * NB + t][cc] = din[t * NB + cc];
        }
    }
    __syncthreads();

    for (int i = j - 1; i >= 0; --i) {
        float acc[4];
        #pragma unroll
        for (int r4 = 0; r4 < 4; ++r4) acc[r4] = 0.f;

        for (int k = i + 1; k <= j; ++k) {
            const float* ub = U + (size_t)(i * NB) * DD + k * NB;
            {
                const int rr = tid >> 3, t4 = tid & 7;
                *(float4*)&Us[rr][t4 * 4] = *(const float4*)&ub[(size_t)rr * DD + t4 * 4];
            }
            __syncthreads();
            #pragma unroll
            for (int t4 = 0; t4 < 8; ++t4) {
                float v0 = Vs[k * NB + t4 * 4 + 0][cc];
                float v1 = Vs[k * NB + t4 * 4 + 1][cc];
                float v2 = Vs[k * NB + t4 * 4 + 2][cc];
                float v3 = Vs[k * NB + t4 * 4 + 3][cc];
                #pragma unroll
                for (int r4 = 0; r4 < 4; ++r4) {
                    float4 u4 = *(const float4*)&Us[q * 4 + r4][t4 * 4];
                    acc[r4] += u4.x * v0 + u4.y * v1 + u4.z * v2 + u4.w * v3;
                }
            }
            __syncthreads();
        }

        #pragma unroll
        for (int r4 = 0; r4 < 4; ++r4) Ts[q * 4 + r4][cc] = acc[r4];
        {
            const float* din = g_Dinv + ((size_t)g * 16 + i) * NB * NB;
            const int rr = tid >> 3, t4 = tid & 7;
            *(float4*)&Us[rr][t4 * 4] = *(const float4*)&din[rr * NB + t4 * 4];
        }
        __syncthreads();

        float acc2[4];
        #pragma unroll
        for (int r4 = 0; r4 < 4; ++r4) acc2[r4] = 0.f;
        #pragma unroll
        for (int t4 = 0; t4 < 8; ++t4) {
            float v0 = Ts[t4 * 4 + 0][cc];
            float v1 = Ts[t4 * 4 + 1][cc];
            float v2 = Ts[t4 * 4 + 2][cc];
            float v3 = Ts[t4 * 4 + 3][cc];
            #pragma unroll
            for (int r4 = 0; r4 < 4; ++r4) {
                float4 u4 = *(const float4*)&Us[q * 4 + r4][t4 * 4];
                acc2[r4] += u4.x * v0 + u4.y * v1 + u4.z * v2 + u4.w * v3;
            }
        }
        #pragma unroll
        for (int r4 = 0; r4 < 4; ++r4) Vs[i * NB + q * 4 + r4][cc] = -acc2[r4];
        __syncthreads();
    }

    // ---- fused output: Wt[n][k] = V[k][n], bf16 hi/lo, zero-padded to the
    //      128-tile boundary the GEMM reads.
    {
        __nv_bfloat16* Whi = g_Wthi + (size_t)g * DD2;
        __nv_bfloat16* Wlo = g_Wtlo + (size_t)g * DD2;
        const int kmax  = (j + 1) * NB;
        const int kfill = 128 * ((j >> 2) + 1);
        for (int nl = q; nl < NB; nl += 8) {
            const size_t nbase = (size_t)(j * NB + nl) * DD;
            for (int k = cc; k < kmax; k += 32) {
                float f = Vs[k][nl];
                __nv_bfloat16 h = __float2bfloat16(f);
                __nv_bfloat16 l = __float2bfloat16(f - __bfloat162float(h));
                Whi[nbase + k] = h;
                Wlo[nbase + k] = l;
            }
            for (int k = kmax + cc; k < kfill; k += 32) {
                Whi[nbase + k] = __float2bfloat16(0.f);
                Wlo[nbase + k] = __float2bfloat16(0.f);
            }
        }
    }

    // ---- fused u
    {
        const float* mu = mus + (size_t)g * DD;
        float s = 0.f;
        for (int row = q; row < (j + 1) * NB; row += 8)
            s += mu[row] * Vs[row][cc];
        __syncthreads();
        Us[q][cc] = s;
        __syncthreads();
        if (q == 0) {
            float tot = 0.f;
            #pragma unroll
            for (int w8 = 0; w8 < 8; ++w8) tot += Us[w8][cc];
            g_u[(size_t)g * DD + j * NB + cc] = tot;
        }
    }
}

// ---------------------------------------------------------------------------
// Kernel 3: split X into bf16 hi/lo.
// ---------------------------------------------------------------------------
__global__ __launch_bounds__(256)
void split_x(const float* __restrict__ X)
{
    const int n = BSZ * DD / 4;
    for (int i = blockIdx.x * 256 + threadIdx.x; i < n; i += gridDim.x * 256) {
        float4 v = ((const float4*)X)[i];
        float f[4] = {v.x, v.y, v.z, v.w};
        __nv_bfloat16 h[4], l[4];
        #pragma unroll
        for (int j = 0; j < 4; ++j) {
            h[j] = __float2bfloat16(f[j]);
            l[j] = __float2bfloat16(f[j] - __bfloat162float(h[j]));
        }
        ((uint2*)g_Xhi)[i] = *(uint2*)h;
        ((uint2*)g_Xlo)[i] = *(uint2*)l;
    }
}

// ---------------------------------------------------------------------------
// Kernel 4: bf16-split GEMM via mma.sync + fused dist epilogue.
// 128 threads = 4 warps (2m x 2n), warp tile 64x64, cp.async double buffer.
// z = Xhi*Whi + Xhi*Wlo + Xlo*Whi, fp32 accum; triangular k per 128-col tile.
// ---------------------------------------------------------------------------
#define PITCH 40

__global__ __launch_bounds__(128)
void mma_dist_kernel()
{
    __shared__ __align__(16) __nv_bfloat16 As[2][128][PITCH];
    __shared__ __align__(16) __nv_bfloat16 Bs[2][128][PITCH];
    __shared__ float sU[512];
    __shared__ float red[128][2];

    const int tid  = threadIdx.x;
    const int lane = tid & 31;
    const int wid  = tid >> 5;
    const int wm   = wid >> 1;       // m64 band
    const int wn   = wid & 1;        // n64 band
    const int g    = blockIdx.y;
    const int b0   = blockIdx.x * 128;

    for (int c = tid; c < 512; c += 128) sU[c] = g_u[(size_t)g * DD + c];

    const __nv_bfloat16* Xh = g_Xhi + (size_t)b0 * DD;
    const __nv_bfloat16* Xl = g_Xlo + (size_t)b0 * DD;
    const __nv_bfloat16* Wh = g_Wthi + (size_t)g * DD2;
    const __nv_bfloat16* Wl = g_Wtlo + (size_t)g * DD2;

    const uint32_t aS = (uint32_t)__cvta_generic_to_shared(&As[0][0][0]);
    const uint32_t bS = (uint32_t)__cvta_generic_to_shared(&Bs[0][0][0]);
    const uint32_t BUFB = 128 * PITCH * 2;

    const int lrow = tid;            // each thread loads one A row + one B row
    const int brow = ((lane >> 4) << 3) + (lane & 7);
    const int bcol = ((lane >> 3) & 1) * 8;

    float distacc[8];
    #pragma unroll
    for (int i = 0; i < 8; ++i) distacc[i] = 0.f;

    for (int nt = 0; nt < 4; ++nt) {
        const int n0 = nt * 128;
        const int nsteps = (nt + 1) * 8;       // k16 stages, kend = n0+128

        float acc[4][8][4];
        #pragma unroll
        for (int mt = 0; mt < 4; ++mt)
            #pragma unroll
            for (int j = 0; j < 8; ++j)
                #pragma unroll
                for (int e = 0; e < 4; ++e) acc[mt][j][e] = 0.f;

        // prologue: stage 0 -> buf 0
        {
            const uint32_t ar = aS + lrow * (PITCH * 2);
            const __nv_bfloat16* xh = Xh + (size_t)lrow * DD;
            const __nv_bfloat16* xl = Xl + (size_t)lrow * DD;
            cp16(ar, xh);       cp16(ar + 16, xh + 8);
            cp16(ar + 32, xl);  cp16(ar + 48, xl + 8);
            const uint32_t br = bS + lrow * (PITCH * 2);
            const __nv_bfloat16* wh = Wh + (size_t)(n0 + lrow) * DD;
            const __nv_bfloat16* wl = Wl + (size_t)(n0 + lrow) * DD;
            cp16(br, wh);       cp16(br + 16, wh + 8);
            cp16(br + 32, wl);  cp16(br + 48, wl + 8);
            asm volatile("cp.async.commit_group;");
        }

        for (int s = 0; s < nsteps; ++s) {
            if (s + 1 < nsteps) {
                const int k0 = (s + 1) * 16;
                const uint32_t buf = (s + 1) & 1;
                const uint32_t ar = aS + buf * BUFB + lrow * (PITCH * 2);
                const __nv_bfloat16* xh = Xh + (size_t)lrow * DD + k0;
                const __nv_bfloat16* xl = Xl + (size_t)lrow * DD + k0;
                cp16(ar, xh);       cp16(ar + 16, xh + 8);
                cp16(ar + 32, xl);  cp16(ar + 48, xl + 8);
                const uint32_t br = bS + buf * BUFB + lrow * (PITCH * 2);
                const __nv_bfloat16* wh = Wh + (size_t)(n0 + lrow) * DD + k0;
                const __nv_bfloat16* wl = Wl + (size_t)(n0 + lrow) * DD + k0;
                cp16(br, wh);       cp16(br + 16, wh + 8);
                cp16(br + 32, wl);  cp16(br + 48, wl + 8);
                asm volatile("cp.async.commit_group;");
                asm volatile("cp.async.wait_group 1;");
            } else {
                asm volatile("cp.async.wait_group 0;");
            }
            __syncthreads();

            const uint32_t cur = s & 1;
            uint32_t ah[4][4], al[4][4];
            #pragma unroll
            for (int mt = 0; mt < 4; ++mt) {
                const uint32_t ad = aS + cur * BUFB
                    + (uint32_t)((wm * 64 + mt * 16 + (lane & 15)) * (PITCH * 2))
                    + (uint32_t)((lane >> 4) * 16);
                ldmx4(ah[mt], ad);
                ldmx4(al[mt], ad + 32);
            }
            #pragma unroll
            for (int nb = 0; nb < 4; ++nb) {
                uint32_t bh[4], bl[4];
                const uint32_t bd = bS + cur * BUFB
                    + (uint32_t)((wn * 64 + nb * 16 + brow) * (PITCH * 2))
                    + (uint32_t)(bcol * 2);
                ldmx4(bh, bd);
                ldmx4(bl, bd + 32);
                #pragma unroll
                for (int mt = 0; mt < 4; ++mt) {
                    #pragma unroll
                    for (int h = 0; h < 2; ++h) {
                        float* d = acc[mt][nb * 2 + h];
                        mma16816(d, ah[mt], &bh[h * 2]);
                        mma16816(d, ah[mt], &bl[h * 2]);
                        mma16816(d, al[mt], &bh[h * 2]);
                    }
                }
            }
            __syncthreads();
        }

        // fold (z-u)^2
        #pragma unroll
        for (int mt = 0; mt < 4; ++mt)
            #pragma unroll
            for (int j = 0; j < 8; ++j) {
                const int coln = n0 + wn * 64 + (j >> 1) * 16 + (j & 1) * 8 + (lane & 3) * 2;
                const float u0 = sU[coln], u1 = sU[coln + 1];
                float z0 = acc[mt][j][0] - u0, z1 = acc[mt][j][1] - u1;
                float z2 = acc[mt][j][2] - u0, z3 = acc[mt][j][3] - u1;
                distacc[mt * 2 + 0] += z0 * z0 + z1 * z1;
                distacc[mt * 2 + 1] += z2 * z2 + z3 * z3;
            }
    }

    // reduce: 4 lanes sharing a row, then across wn via smem
    #pragma unroll
    for (int i = 0; i < 8; ++i) {
        distacc[i] += __shfl_xor_sync(0xffffffff, distacc[i], 1);
        distacc[i] += __shfl_xor_sync(0xffffffff, distacc[i], 2);
    }
    if ((lane & 3) == 0) {
        const int r = lane >> 2;
        #pragma unroll
        for (int mt = 0; mt < 4; ++mt) {
            red[wm * 64 + mt * 16 + r][wn]     = distacc[mt * 2 + 0];
            red[wm * 64 + mt * 16 + r + 8][wn] = distacc[mt * 2 + 1];
        }
    }
    __syncthreads();
    g_dist[(size_t)(b0 + tid) * GG + g] = red[tid][0] + red[tid][1];
}

// ---------------------------------------------------------------------------
// Kernel 5: out = -mean_b( min_g relu(dist[b,g]) ) / 10000
// ---------------------------------------------------------------------------
__global__ __launch_bounds__(256, 1)
void reduce_kernel(float* __restrict__ out)
{
    __shared__ float sh[256];
    float s = 0.f;
    for (int b = threadIdx.x; b < BSZ; b += 256) {
        const float* row = g_dist + (size_t)b * GG;
        float m = fmaxf(row[0], 0.f);
        #pragma unroll 8
        for (int gi = 1; gi < GG; ++gi)
            m = fminf(m, fmaxf(row[gi], 0.f));
        s += m;
    }
    sh[threadIdx.x] = s;
    __syncthreads();
    for (int off = 128; off > 0; off >>= 1) {
        if (threadIdx.x < off) sh[threadIdx.x] += sh[threadIdx.x + off];
        __syncthreads();
    }
    if (threadIdx.x == 0)
        out[0] = -sh[0] / ((float)BSZ * 10000.0f);
}

// ---------------------------------------------------------------------------
extern "C" void kernel_launch(void* const* d_in, const int* in_sizes, int n_in,
                              void* d_out, int out_size)
{
    const float* X    = nullptr;
    const float* mus  = nullptr;
    const float* covs = nullptr;
    for (int i = 0; i < n_in; ++i) {
        if      (in_sizes[i] == BSZ * DD)      X    = (const float*)d_in[i];
        else if (in_sizes[i] == GG * DD)       mus  = (const float*)d_in[i];
        else if (in_sizes[i] == GG * DD * DD)  covs = (const float*)d_in[i];
    }

    static bool attr_done = false;
    if (!attr_done) {
        cudaFuncSetAttribute(trinv_col_kernel,
                             cudaFuncAttributeMaxDynamicSharedMemorySize, T2_SMEM);
        attr_done = true;
    }

    split_x<<<512, 256>>>(X);
    chol_fused<<<GG * 2, 256>>>(covs);
    diaginv_kernel<<<dim3(GG, 4), 128>>>();
    trinv_col_kernel<<<dim3(GG, 16), 256, T2_SMEM>>>(mus);
    mma_dist_kernel<<<dim3(BSZ / 128, GG), 128>>>();
    reduce_kernel<<<1, 256>>>((float*)d_out);
}

// round 9
// speedup vs baseline: 5.3231x; 1.1224x over previous
#include <cuda_runtime.h>
#include <cuda_fp16.h>
#include <math.h>
#include <stdint.h>

// Problem sizes (fixed by the reference)
#define BSZ 2048
#define GG  64
#define DD  512
#define DD2 (DD * DD)
#define NB  32

// ---------------------------------------------------------------------------
// Scratch (device globals)
// g_L : per-gaussian Cholesky factor L, COLUMN-major (i>=j at j*DD+i).
//       Row-major view is U = L^T (valid at a*DD+b, b>=a).
// g_Wt*: transposed fp16-split inverse: Wt[n][k] = V[k][n], V = U^{-1}.
// g_Xh : X rounded to fp16 (the GEMM computes dist of the rounded x exactly).
// ---------------------------------------------------------------------------
__device__ __align__(16) float g_L[GG * DD2];
__device__ __align__(16) float g_Dinv[GG * 16 * NB * NB];
__device__ __align__(16) float g_u[GG * DD];
__device__ __align__(16) float g_dist[BSZ * GG];
__device__ __align__(16) __half g_Xh[BSZ * DD];
__device__ __align__(16) __half g_Wthi[GG * DD2];
__device__ __align__(16) __half g_Wtlo[GG * DD2];

#define CLUSTER_SYNC() do { \
    asm volatile("barrier.cluster.arrive.aligned;" ::: "memory"); \
    asm volatile("barrier.cluster.wait.aligned;"   ::: "memory"); \
} while (0)

// ---------------------------------------------------------------------------
// mma.sync / cp.async helpers (portable sm_80+ path)
// ---------------------------------------------------------------------------
__device__ __forceinline__ void ldmx4(uint32_t* r, uint32_t addr) {
    asm volatile("ldmatrix.sync.aligned.m8n8.x4.shared.b16 {%0,%1,%2,%3}, [%4];"
                 : "=r"(r[0]), "=r"(r[1]), "=r"(r[2]), "=r"(r[3]) : "r"(addr));
}
__device__ __forceinline__ void mma16816h(float* d, const uint32_t* a, const uint32_t* b) {
    asm volatile(
        "mma.sync.aligned.m16n8k16.row.col.f32.f16.f16.f32 "
        "{%0,%1,%2,%3}, {%4,%5,%6,%7}, {%8,%9}, {%0,%1,%2,%3};"
        : "+f"(d[0]), "+f"(d[1]), "+f"(d[2]), "+f"(d[3])
        : "r"(a[0]), "r"(a[1]), "r"(a[2]), "r"(a[3]), "r"(b[0]), "r"(b[1]));
}
__device__ __forceinline__ void cp16(uint32_t s, const void* g) {
    asm volatile("cp.async.ca.shared.global [%0], [%1], 16;" :: "r"(s), "l"(g));
}

// ---------------------------------------------------------------------------
// Kernel 1: fused blocked Cholesky, cluster of 2 CTAs per gaussian,
// 512 threads. p=0 reads covs directly. SYRK: 64x64 tiles, micro 4x2.
// ---------------------------------------------------------------------------
__global__ __launch_bounds__(512) __cluster_dims__(2, 1, 1)
void chol_fused(const float* __restrict__ covs)
{
    __shared__ float s11[NB][NB + 1];
    __shared__ float rdiag[NB];
    __shared__ __align__(16) float Pi[NB][68];
    __shared__ __align__(16) float Pj[NB][68];

    const int g = blockIdx.x >> 1;
    unsigned crank;
    asm("mov.u32 %0, %%cluster_ctarank;" : "=r"(crank));
    float* a = g_L + (size_t)g * DD2;
    const float* cv = covs + (size_t)g * DD2;
    const int tid = threadIdx.x;

    for (int p = 0; p < DD / NB; ++p) {
        const int base = p * NB;
        const int r = DD - base - NB;
        const float* src = (p == 0) ? cv : a;

        for (int q = tid; q < NB * NB; q += 512) {
            int i = q & 31, j = q >> 5;
            s11[i][j] = src[(size_t)(base + j) * DD + (base + i)];
        }
        __syncthreads();

        if (tid < 32) {
            const int lane = tid;
            for (int k = 0; k < NB; ++k) {
                if (lane == k) {
                    float v = s11[k][k];
                    float rs = rsqrtf(v);
                    s11[k][k] = v * rs;
                    rdiag[k] = rs;
                }
                __syncwarp();
                float lik = 0.f;
                if (lane > k) {
                    lik = s11[lane][k] * rdiag[k];
                    s11[lane][k] = lik;
                }
                __syncwarp();
                if (lane > k) {
                    for (int j = k + 1; j <= lane; ++j)
                        s11[lane][j] -= lik * s11[j][k];
                }
                __syncwarp();
            }
        }
        __syncthreads();

        if (crank == 0) {
            for (int q = tid; q < NB * NB; q += 512) {
                int i = q & 31, j = q >> 5;
                if (i >= j) a[(size_t)(base + j) * DD + (base + i)] = s11[i][j];
            }
        }

        // panel solve: my half of rows, 1 reg-resident row per thread
        if (r > 0) {
            const int chunk = (r + 1) >> 1;
            const int row = (int)crank * chunk + tid;
            if (row < r && tid < chunk) {
                const int gr = base + NB + row;
                float x[NB];
                #pragma unroll
                for (int j = 0; j < NB; ++j)
                    x[j] = src[(size_t)(base + j) * DD + gr];
                #pragma unroll
                for (int j = 0; j < NB; ++j) {
                    float s = x[j];
                    #pragma unroll
                    for (int k = 0; k < j; ++k)
                        s -= x[k] * s11[j][k];
                    x[j] = s * rdiag[j];
                }
                #pragma unroll
                for (int j = 0; j < NB; ++j)
                    a[(size_t)(base + j) * DD + gr] = x[j];
            }
        }
        CLUSTER_SYNC();

        // SYRK: tile-rows by cluster parity; Pi staged once per tile row
        if (r > 0) {
            const int m = (r + 63) >> 6;
            for (int ti = (int)crank; ti < m; ti += 2) {
                const int gi = ti * 64;
                {
                    const int s   = tid;               // 512 covers 512 slots
                    const int col = s >> 4;
                    const int r4  = s & 15;
                    const int row = gi + r4 * 4;
                    float4 v = make_float4(0.f, 0.f, 0.f, 0.f);
                    if (row < r)
                        v = *(const float4*)(a + (size_t)(base + col) * DD + base + NB + row);
                    *(float4*)&Pi[col][r4 * 4] = v;
                }

                for (int tj = 0; tj <= ti; ++tj) {
                    const int gj = tj * 64;
                    {
                        const int s   = tid;
                        const int col = s >> 4;
                        const int r4  = s & 15;
                        const int row = gj + r4 * 4;
                        float4 v = make_float4(0.f, 0.f, 0.f, 0.f);
                        if (row < r)
                            v = *(const float4*)(a + (size_t)(base + col) * DD + base + NB + row);
                        *(float4*)&Pj[col][r4 * 4] = v;
                    }
                    __syncthreads();

                    const int tx = tid & 15;     // 4 rows
                    const int ty = tid >> 4;     // 0..31, 2 cols
                    float acc[4][2];
                    #pragma unroll
                    for (int ii = 0; ii < 4; ++ii) { acc[ii][0] = 0.f; acc[ii][1] = 0.f; }

                    #pragma unroll
                    for (int k = 0; k < NB; ++k) {
                        float4 pi = *(const float4*)&Pi[k][tx * 4];
                        float pj0 = Pj[k][ty * 2], pj1 = Pj[k][ty * 2 + 1];
                        float pr[4] = {pi.x, pi.y, pi.z, pi.w};
                        #pragma unroll
                        for (int ii = 0; ii < 4; ++ii) {
                            acc[ii][0] += pr[ii] * pj0;
                            acc[ii][1] += pr[ii] * pj1;
                        }
                    }

                    const int rowb = gi + tx * 4;
                    if (rowb < r) {
                        #pragma unroll
                        for (int jj = 0; jj < 2; ++jj) {
                            const int colg = gj + ty * 2 + jj;
                            if (colg < r) {
                                const size_t off = (size_t)(base + NB + colg) * DD + base + NB + rowb;
                                float4 cvv = *(const float4*)(src + off);
                                cvv.x -= acc[0][jj]; cvv.y -= acc[1][jj];
                                cvv.z -= acc[2][jj]; cvv.w -= acc[3][jj];
                                *(float4*)(a + off) = cvv;
                            }
                        }
                    }
                    __syncthreads();
                }
            }
        }
        CLUSTER_SYNC();
    }
}

// ---------------------------------------------------------------------------
// Kernel 2a: invert 16 diagonal 32x32 blocks of U = L^T. One warp per (g,d).
// ---------------------------------------------------------------------------
__global__ __launch_bounds__(128, 8)
void diaginv_kernel()
{
    __shared__ float su[4][NB][NB + 1];
    __shared__ float sx[4][NB][NB + 1];

    const int g = blockIdx.x;
    const int w = threadIdx.x >> 5;
    const int d = blockIdx.y * 4 + w;
    const int cc = threadIdx.x & 31;
    const float* U = g_L + (size_t)g * DD2;
    const int b0 = d * NB;

    for (int rr = 0; rr < NB; ++rr)
        su[w][rr][cc] = U[(size_t)(b0 + rr) * DD + (b0 + cc)];
    __syncwarp();

    for (int t = cc; t >= 0; --t) {
        float s = (t == cc) ? 1.f : 0.f;
        for (int ss = t + 1; ss <= cc; ++ss)
            s -= su[w][t][ss] * sx[w][ss][cc];
        sx[w][t][cc] = s / su[w][t][t];
    }
    __syncwarp();

    float* dst = g_Dinv + ((size_t)g * 16 + d) * NB * NB;
    for (int t = 0; t < NB; ++t)
        dst[t * NB + cc] = (t <= cc) ? sx[w][t][cc] : 0.f;
}

// ---------------------------------------------------------------------------
// Kernel 2b: blocked triangular inverse + fused u + fused transposed fp16
// split output. One CTA per (g, block-column j).
// k contraction staged 4 blocks per sync (Us[4][32][36]).
// ---------------------------------------------------------------------------
#define T2_SMEM ((512*36 + 4*32*36 + 32*33) * 4)

__global__ __launch_bounds__(256)
void trinv_col_kernel(const float* __restrict__ mus)
{
    extern __shared__ float sm2[];
    float (*Vs)[36] = (float(*)[36])sm2;
    float (*Us)[32][36] = (float(*)[32][36])(sm2 + 512 * 36);
    float (*Ts)[33] = (float(*)[33])(sm2 + 512 * 36 + 4 * 32 * 36);

    const int g = blockIdx.x;
    const int j = blockIdx.y;
    const float* U = g_L + (size_t)g * DD2;
    const int tid = threadIdx.x;
    const int cc  = tid & 31;
    const int q   = tid >> 5;

    {
        const float* din = g_Dinv + ((size_t)g * 16 + j) * NB * NB;
        #pragma unroll
        for (int t4 = 0; t4 < 4; ++t4) {
            int t = q * 4 + t4;
            Vs[j * NB + t][cc] = din[t * NB + cc];
        }
    }
    __syncthreads();

    for (int i = j - 1; i >= 0; --i) {
        float acc[4];
        #pragma unroll
        for (int r4 = 0; r4 < 4; ++r4) acc[r4] = 0.f;

        for (int kc = i + 1; kc <= j; kc += 4) {
            const int nk = (j - kc + 1 < 4) ? (j - kc + 1) : 4;
            // stage nk U blocks
            for (int b = 0; b < nk; ++b) {
                const float* ub = U + (size_t)(i * NB) * DD + (kc + b) * NB;
                const int rr = tid >> 3, t4 = tid & 7;
                *(float4*)&Us[b][rr][t4 * 4] = *(const float4*)&ub[(size_t)rr * DD + t4 * 4];
            }
            __syncthreads();
            for (int b = 0; b < nk; ++b) {
                const int k = kc + b;
                #pragma unroll
                for (int t4 = 0; t4 < 8; ++t4) {
                    float v0 = Vs[k * NB + t4 * 4 + 0][cc];
                    float v1 = Vs[k * NB + t4 * 4 + 1][cc];
                    float v2 = Vs[k * NB + t4 * 4 + 2][cc];
                    float v3 = Vs[k * NB + t4 * 4 + 3][cc];
                    #pragma unroll
                    for (int r4 = 0; r4 < 4; ++r4) {
                        float4 u4 = *(const float4*)&Us[b][q * 4 + r4][t4 * 4];
                        acc[r4] += u4.x * v0 + u4.y * v1 + u4.z * v2 + u4.w * v3;
                    }
                }
            }
            __syncthreads();
        }

        #pragma unroll
        for (int r4 = 0; r4 < 4; ++r4) Ts[q * 4 + r4][cc] = acc[r4];
        {
            const float* din = g_Dinv + ((size_t)g * 16 + i) * NB * NB;
            const int rr = tid >> 3, t4 = tid & 7;
            *(float4*)&Us[0][rr][t4 * 4] = *(const float4*)&din[rr * NB + t4 * 4];
        }
        __syncthreads();

        float acc2[4];
        #pragma unroll
        for (int r4 = 0; r4 < 4; ++r4) acc2[r4] = 0.f;
        #pragma unroll
        for (int t4 = 0; t4 < 8; ++t4) {
            float v0 = Ts[t4 * 4 + 0][cc];
            float v1 = Ts[t4 * 4 + 1][cc];
            float v2 = Ts[t4 * 4 + 2][cc];
            float v3 = Ts[t4 * 4 + 3][cc];
            #pragma unroll
            for (int r4 = 0; r4 < 4; ++r4) {
                float4 u4 = *(const float4*)&Us[0][q * 4 + r4][t4 * 4];
                acc2[r4] += u4.x * v0 + u4.y * v1 + u4.z * v2 + u4.w * v3;
            }
        }
        #pragma unroll
        for (int r4 = 0; r4 < 4; ++r4) Vs[i * NB + q * 4 + r4][cc] = -acc2[r4];
        __syncthreads();
    }

    // fused output: Wt[n][k] = V[k][n], fp16 hi/lo, zero-padded to 128-tile
    {
        __half* Whi = g_Wthi + (size_t)g * DD2;
        __half* Wlo = g_Wtlo + (size_t)g * DD2;
        const int kmax  = (j + 1) * NB;
        const int kfill = 128 * ((j >> 2) + 1);
        for (int nl = q; nl < NB; nl += 8) {
            const size_t nbase = (size_t)(j * NB + nl) * DD;
            for (int k = cc; k < kmax; k += 32) {
                float f = Vs[k][nl];
                __half h = __float2half(f);
                __half l = __float2half(f - __half2float(h));
                Whi[nbase + k] = h;
                Wlo[nbase + k] = l;
            }
            for (int k = kmax + cc; k < kfill; k += 32) {
                Whi[nbase + k] = __float2half(0.f);
                Wlo[nbase + k] = __float2half(0.f);
            }
        }
    }

    // fused u
    {
        const float* mu = mus + (size_t)g * DD;
        float s = 0.f;
        for (int row = q; row < (j + 1) * NB; row += 8)
            s += mu[row] * Vs[row][cc];
        __syncthreads();
        Ts[q][cc] = s;
        __syncthreads();
        if (q == 0) {
            float tot = 0.f;
            #pragma unroll
            for (int w8 = 0; w8 < 8; ++w8) tot += Ts[w8][cc];
            g_u[(size_t)g * DD + j * NB + cc] = tot;
        }
    }
}

// ---------------------------------------------------------------------------
// Kernel 3: round X to fp16.
// ---------------------------------------------------------------------------
__global__ __launch_bounds__(256)
void split_x(const float* __restrict__ X)
{
    const int n = BSZ * DD / 4;
    for (int i = blockIdx.x * 256 + threadIdx.x; i < n; i += gridDim.x * 256) {
        float4 v = ((const float4*)X)[i];
        __half h[4] = {__float2half(v.x), __float2half(v.y),
                       __float2half(v.z), __float2half(v.w)};
        ((uint2*)g_Xh)[i] = *(uint2*)h;
    }
}

// ---------------------------------------------------------------------------
// Kernel 4: fp16 2-product GEMM via mma.sync + fused dist epilogue.
// z = xh * (wh + wl): exactly dist of fp16-rounded x vs 22-bit V.
// 256 threads = 8 warps (wm = wid&1 -> m64 band, wn = wid>>1 -> n32 band).
// cp.async double buffer; triangular k per 128-col tile.
// ---------------------------------------------------------------------------
#define PITCH_A 24
#define PITCH_B 40

__global__ __launch_bounds__(256, 2)
void mma_dist_kernel()
{
    __shared__ __align__(16) __half As[2][128][PITCH_A];
    __shared__ __align__(16) __half Bs[2][128][PITCH_B];
    __shared__ float sU[512];
    __shared__ float red[128][4];

    const int tid  = threadIdx.x;
    const int lane = tid & 31;
    const int wid  = tid >> 5;
    const int wm   = wid & 1;        // m64 band
    const int wn   = wid >> 1;       // n32 band (0..3)
    const int g    = blockIdx.y;
    const int b0   = blockIdx.x * 128;

    for (int c = tid; c < 512; c += 256) sU[c] = g_u[(size_t)g * DD + c];

    const __half* Xh = g_Xh + (size_t)b0 * DD;
    const __half* Wh = g_Wthi + (size_t)g * DD2;
    const __half* Wl = g_Wtlo + (size_t)g * DD2;

    const uint32_t aS = (uint32_t)__cvta_generic_to_shared(&As[0][0][0]);
    const uint32_t bS = (uint32_t)__cvta_generic_to_shared(&Bs[0][0][0]);
    const uint32_t BUFA = 128 * PITCH_A * 2;
    const uint32_t BUFB = 128 * PITCH_B * 2;

    const int lrow = tid >> 1;       // 0..127
    const int hsel = tid & 1;        // 8-half chunk select
    const int brow = ((lane >> 4) << 3) + (lane & 7);
    const int bcol = ((lane >> 3) & 1) * 8;

    float distacc[8];
    #pragma unroll
    for (int i = 0; i < 8; ++i) distacc[i] = 0.f;

    for (int nt = 0; nt < 4; ++nt) {
        const int n0 = nt * 128;
        const int nsteps = (nt + 1) * 8;     // k16 stages, kend = n0+128

        float acc[4][4][4];
        #pragma unroll
        for (int mt = 0; mt < 4; ++mt)
            #pragma unroll
            for (int jc = 0; jc < 4; ++jc)
                #pragma unroll
                for (int e = 0; e < 4; ++e) acc[mt][jc][e] = 0.f;

        // prologue: stage 0 -> buf 0
        {
            cp16(aS + lrow * (PITCH_A * 2) + hsel * 16,
                 Xh + (size_t)lrow * DD + hsel * 8);
            const uint32_t br = bS + lrow * (PITCH_B * 2);
            const __half* wh = Wh + (size_t)(n0 + lrow) * DD;
            const __half* wl = Wl + (size_t)(n0 + lrow) * DD;
            cp16(br + hsel * 16, wh + hsel * 8);
            cp16(br + 32 + hsel * 16, wl + hsel * 8);
            asm volatile("cp.async.commit_group;");
        }

        for (int s = 0; s < nsteps; ++s) {
            if (s + 1 < nsteps) {
                const int k0 = (s + 1) * 16;
                const uint32_t buf = (s + 1) & 1;
                cp16(aS + buf * BUFA + lrow * (PITCH_A * 2) + hsel * 16,
                     Xh + (size_t)lrow * DD + k0 + hsel * 8);
                const uint32_t br = bS + buf * BUFB + lrow * (PITCH_B * 2);
                const __half* wh = Wh + (size_t)(n0 + lrow) * DD + k0;
                const __half* wl = Wl + (size_t)(n0 + lrow) * DD + k0;
                cp16(br + hsel * 16, wh + hsel * 8);
                cp16(br + 32 + hsel * 16, wl + hsel * 8);
                asm volatile("cp.async.commit_group;");
                asm volatile("cp.async.wait_group 1;");
            } else {
                asm volatile("cp.async.wait_group 0;");
            }
            __syncthreads();

            const uint32_t cur = s & 1;
            uint32_t ah[4][4];
            #pragma unroll
            for (int mt = 0; mt < 4; ++mt) {
                const uint32_t ad = aS + cur * BUFA
                    + (uint32_t)((wm * 64 + mt * 16 + (lane & 15)) * (PITCH_A * 2))
                    + (uint32_t)((lane >> 4) * 16);
                ldmx4(ah[mt], ad);
            }
            #pragma unroll
            for (int nb = 0; nb < 2; ++nb) {
                uint32_t bh[4], bl[4];
                const uint32_t bd = bS + cur * BUFB
                    + (uint32_t)((wn * 32 + nb * 16 + brow) * (PITCH_B * 2))
                    + (uint32_t)(bcol * 2);
                ldmx4(bh, bd);
                ldmx4(bl, bd + 32);
                #pragma unroll
                for (int mt = 0; mt < 4; ++mt) {
                    #pragma unroll
                    for (int h = 0; h < 2; ++h) {
                        float* d = acc[mt][nb * 2 + h];
                        mma16816h(d, ah[mt], &bh[h * 2]);
                        mma16816h(d, ah[mt], &bl[h * 2]);
                    }
                }
            }
            __syncthreads();
        }

        // fold (z-u)^2
        #pragma unroll
        for (int mt = 0; mt < 4; ++mt)
            #pragma unroll
            for (int jc = 0; jc < 4; ++jc) {
                const int coln = n0 + wn * 32 + (jc >> 1) * 16 + (jc & 1) * 8 + (lane & 3) * 2;
                const float u0 = sU[coln], u1 = sU[coln + 1];
                float z0 = acc[mt][jc][0] - u0, z1 = acc[mt][jc][1] - u1;
                float z2 = acc[mt][jc][2] - u0, z3 = acc[mt][jc][3] - u1;
                distacc[mt * 2 + 0] += z0 * z0 + z1 * z1;
                distacc[mt * 2 + 1] += z2 * z2 + z3 * z3;
            }
    }

    // reduce: 4 column-lanes, then across the 4 wn bands via smem
    #pragma unroll
    for (int i = 0; i < 8; ++i) {
        distacc[i] += __shfl_xor_sync(0xffffffff, distacc[i], 1);
        distacc[i] += __shfl_xor_sync(0xffffffff, distacc[i], 2);
    }
    if ((lane & 3) == 0) {
        const int r = lane >> 2;
        #pragma unroll
        for (int mt = 0; mt < 4; ++mt) {
            red[wm * 64 + mt * 16 + r][wn]     = distacc[mt * 2 + 0];
            red[wm * 64 + mt * 16 + r + 8][wn] = distacc[mt * 2 + 1];
        }
    }
    __syncthreads();
    if (tid < 128)
        g_dist[(size_t)(b0 + tid) * GG + g] =
            red[tid][0] + red[tid][1] + red[tid][2] + red[tid][3];
}

// ---------------------------------------------------------------------------
// Kernel 5: out = -mean_b( min_g relu(dist[b,g]) ) / 10000
// ---------------------------------------------------------------------------
__global__ __launch_bounds__(256, 1)
void reduce_kernel(float* __restrict__ out)
{
    __shared__ float sh[256];
    float s = 0.f;
    for (int b = threadIdx.x; b < BSZ; b += 256) {
        const float* row = g_dist + (size_t)b * GG;
        float m = fmaxf(row[0], 0.f);
        #pragma unroll 8
        for (int gi = 1; gi < GG; ++gi)
            m = fminf(m, fmaxf(row[gi], 0.f));
        s += m;
    }
    sh[threadIdx.x] = s;
    __syncthreads();
    for (int off = 128; off > 0; off >>= 1) {
        if (threadIdx.x < off) sh[threadIdx.x] += sh[threadIdx.x + off];
        __syncthreads();
    }
    if (threadIdx.x == 0)
        out[0] = -sh[0] / ((float)BSZ * 10000.0f);
}

// ---------------------------------------------------------------------------
extern "C" void kernel_launch(void* const* d_in, const int* in_sizes, int n_in,
                              void* d_out, int out_size)
{
    const float* X    = nullptr;
    const float* mus  = nullptr;
    const float* covs = nullptr;
    for (int i = 0; i < n_in; ++i) {
        if      (in_sizes[i] == BSZ * DD)      X    = (const float*)d_in[i];
        else if (in_sizes[i] == GG * DD)       mus  = (const float*)d_in[i];
        else if (in_sizes[i] == GG * DD * DD)  covs = (const float*)d_in[i];
    }

    static bool attr_done = false;
    if (!attr_done) {
        cudaFuncSetAttribute(trinv_col_kernel,
                             cudaFuncAttributeMaxDynamicSharedMemorySize, T2_SMEM);
        attr_done = true;
    }

    split_x<<<512, 256>>>(X);
    chol_fused<<<GG * 2, 512>>>(covs);
    diaginv_kernel<<<dim3(GG, 4), 128>>>();
    trinv_col_kernel<<<dim3(GG, 16), 256, T2_SMEM>>>(mus);
    mma_dist_kernel<<<dim3(BSZ / 128, GG), 256>>>();
    reduce_kernel<<<1, 256>>>((float*)d_out);
}

// round 10
// speedup vs baseline: 5.9764x; 1.1227x over previous
#include <cuda_runtime.h>
#include <cuda_fp16.h>
#include <math.h>
#include <stdint.h>

// Problem sizes (fixed by the reference)
#define BSZ 2048
#define GG  64
#define DD  512
#define DD2 (DD * DD)
#define NB  32
#define PNL 64

// ---------------------------------------------------------------------------
// Scratch (device globals)
// g_L : per-gaussian Cholesky factor L, COLUMN-major (i>=j at j*DD+i).
//       Row-major view is U = L^T (valid at a*DD+b, b>=a).
// g_Wt*: transposed fp16-split inverse: Wt[n][k] = V[k][n], V = U^{-1}.
// g_Xh : X rounded to fp16 (GEMM computes dist of the rounded x exactly).
// ---------------------------------------------------------------------------
__device__ __align__(16) float g_L[GG * DD2];
__device__ __align__(16) float g_Dinv[GG * 16 * NB * NB];
__device__ __align__(16) float g_u[GG * DD];
__device__ __align__(16) float g_dist[BSZ * GG];
__device__ __align__(16) __half g_Xh[BSZ * DD];
__device__ __align__(16) __half g_Wthi[GG * DD2];
__device__ __align__(16) __half g_Wtlo[GG * DD2];

#define CLUSTER_SYNC() do { \
    asm volatile("barrier.cluster.arrive.aligned;" ::: "memory"); \
    asm volatile("barrier.cluster.wait.aligned;"   ::: "memory"); \
} while (0)

// ---------------------------------------------------------------------------
// mma.sync / cp.async helpers (portable sm_80+ path)
// ---------------------------------------------------------------------------
__device__ __forceinline__ void ldmx4(uint32_t* r, uint32_t addr) {
    asm volatile("ldmatrix.sync.aligned.m8n8.x4.shared.b16 {%0,%1,%2,%3}, [%4];"
                 : "=r"(r[0]), "=r"(r[1]), "=r"(r[2]), "=r"(r[3]) : "r"(addr));
}
__device__ __forceinline__ void mma16816h(float* d, const uint32_t* a, const uint32_t* b) {
    asm volatile(
        "mma.sync.aligned.m16n8k16.row.col.f32.f16.f16.f32 "
        "{%0,%1,%2,%3}, {%4,%5,%6,%7}, {%8,%9}, {%0,%1,%2,%3};"
        : "+f"(d[0]), "+f"(d[1]), "+f"(d[2]), "+f"(d[3])
        : "r"(a[0]), "r"(a[1]), "r"(a[2]), "r"(a[3]), "r"(b[0]), "r"(b[1]));
}
__device__ __forceinline__ void cp16(uint32_t s, const void* g) {
    asm volatile("cp.async.ca.shared.global [%0], [%1], 16;" :: "r"(s), "l"(g));
}

// ---------------------------------------------------------------------------
// Kernel 1: fused blocked Cholesky, NB=64 panels (8 panels instead of 16),
// cluster of 2 CTAs per gaussian, 512 threads.
// Diag-64 factored hierarchically in smem (32-factor / row-solve / syrk /
// 32-factor). Panel solve: one 64-register row per thread. SYRK: 64x64 tiles,
// k=64, Pi staged once per tile-row, Pj aliases Pi on diagonal tiles.
// ---------------------------------------------------------------------------
__global__ __launch_bounds__(512) __cluster_dims__(2, 1, 1)
void chol_fused(const float* __restrict__ covs)
{
    __shared__ float s11[PNL][PNL + 1];
    __shared__ float rdiag[PNL];
    __shared__ __align__(16) float Pi[PNL][68];
    __shared__ __align__(16) float Pj[PNL][68];

    const int g = blockIdx.x >> 1;
    unsigned crank;
    asm("mov.u32 %0, %%cluster_ctarank;" : "=r"(crank));
    float* a = g_L + (size_t)g * DD2;
    const float* cv = covs + (size_t)g * DD2;
    const int tid = threadIdx.x;

    for (int p = 0; p < DD / PNL; ++p) {
        const int base = p * PNL;
        const int r = DD - base - PNL;
        const float* src = (p == 0) ? cv : a;

        // ---- load 64x64 diag block
        for (int q = tid; q < PNL * PNL; q += 512) {
            int i = q & 63, j = q >> 6;
            s11[i][j] = src[(size_t)(base + j) * DD + (base + i)];
        }
        __syncthreads();

        // ---- phase A: warp 0 factors top-left 32x32
        if (tid < 32) {
            const int lane = tid;
            for (int k = 0; k < 32; ++k) {
                if (lane == k) {
                    float v = s11[k][k];
                    float rs = rsqrtf(v);
                    s11[k][k] = v * rs;
                    rdiag[k] = rs;
                }
                __syncwarp();
                float lik = 0.f;
                if (lane > k) {
                    lik = s11[lane][k] * rdiag[k];
                    s11[lane][k] = lik;
                }
                __syncwarp();
                if (lane > k) {
                    for (int j = k + 1; j <= lane; ++j)
                        s11[lane][j] -= lik * s11[j][k];
                }
                __syncwarp();
            }
        }
        __syncthreads();

        // ---- phase B: solve rows 32..63 of the diag block vs L11a
        if (tid < 32) {
            const int row = 32 + tid;
            float x[32];
            #pragma unroll
            for (int j = 0; j < 32; ++j) x[j] = s11[row][j];
            #pragma unroll
            for (int j = 0; j < 32; ++j) {
                float s = x[j];
                #pragma unroll
                for (int k = 0; k < j; ++k)
                    s -= x[k] * s11[j][k];
                x[j] = s * rdiag[j];
            }
            #pragma unroll
            for (int j = 0; j < 32; ++j) s11[row][j] = x[j];
        }
        __syncthreads();

        // ---- phase C: inner SYRK s11[32:64][32:64] -= L21' L21'^T
        // (writes cols >=32, reads cols <32 -> no conflict)
        #pragma unroll
        for (int e = 0; e < 2; ++e) {
            const int idx = tid + e * 512;
            const int i2 = 32 + (idx >> 5);
            const int j2 = 32 + (idx & 31);
            float s = 0.f;
            #pragma unroll
            for (int k = 0; k < 32; ++k)
                s += s11[i2][k] * s11[j2][k];
            s11[i2][j2] -= s;
        }
        __syncthreads();

        // ---- phase D: warp 0 factors bottom-right 32x32
        if (tid < 32) {
            const int lane = tid;
            for (int k = 0; k < 32; ++k) {
                if (lane == k) {
                    float v = s11[32 + k][32 + k];
                    float rs = rsqrtf(v);
                    s11[32 + k][32 + k] = v * rs;
                    rdiag[32 + k] = rs;
                }
                __syncwarp();
                float lik = 0.f;
                if (lane > k) {
                    lik = s11[32 + lane][32 + k] * rdiag[32 + k];
                    s11[32 + lane][32 + k] = lik;
                }
                __syncwarp();
                if (lane > k) {
                    for (int j = k + 1; j <= lane; ++j)
                        s11[32 + lane][32 + j] -= lik * s11[32 + j][32 + k];
                }
                __syncwarp();
            }
        }
        __syncthreads();

        // ---- write factored diag back (lower incl diag)
        if (crank == 0) {
            for (int q = tid; q < PNL * PNL; q += 512) {
                int i = q & 63, j = q >> 6;
                if (i >= j) a[(size_t)(base + j) * DD + (base + i)] = s11[i][j];
            }
        }

        // ---- panel solve: my half of the rows, 1 reg-resident row/thread
        if (r > 0) {
            const int chunk = (r + 1) >> 1;
            const int row = (int)crank * chunk + tid;
            if (row < r && tid < chunk) {
                const int gr = base + PNL + row;
                float x[PNL];
                #pragma unroll
                for (int j = 0; j < PNL; ++j)
                    x[j] = src[(size_t)(base + j) * DD + gr];
                #pragma unroll
                for (int j = 0; j < PNL; ++j) {
                    float s = x[j];
                    #pragma unroll
                    for (int k = 0; k < j; ++k)
                        s -= x[k] * s11[j][k];
                    x[j] = s * rdiag[j];
                }
                #pragma unroll
                for (int j = 0; j < PNL; ++j)
                    a[(size_t)(base + j) * DD + gr] = x[j];
            }
        }
        CLUSTER_SYNC();

        // ---- SYRK trailing update, 64x64 tiles, k = 64
        if (r > 0) {
            const int m = (r + 63) >> 6;
            for (int ti = (int)crank; ti < m; ti += 2) {
                const int gi = ti * 64;
                // stage Pi (panel rows gi..gi+63, transposed)
                #pragma unroll
                for (int f = 0; f < 2; ++f) {
                    const int s   = tid + 512 * f;
                    const int col = s >> 4;          // 0..63
                    const int r4  = s & 15;
                    const int row = gi + r4 * 4;
                    float4 v = make_float4(0.f, 0.f, 0.f, 0.f);
                    if (row < r)
                        v = *(const float4*)(a + (size_t)(base + col) * DD + base + PNL + row);
                    *(float4*)&Pi[col][r4 * 4] = v;
                }

                for (int tj = 0; tj <= ti; ++tj) {
                    const int gj = tj * 64;
                    const bool same = (tj == ti);
                    if (!same) {
                        #pragma unroll
                        for (int f = 0; f < 2; ++f) {
                            const int s   = tid + 512 * f;
                            const int col = s >> 4;
                            const int r4  = s & 15;
                            const int row = gj + r4 * 4;
                            float4 v = make_float4(0.f, 0.f, 0.f, 0.f);
                            if (row < r)
                                v = *(const float4*)(a + (size_t)(base + col) * DD + base + PNL + row);
                            *(float4*)&Pj[col][r4 * 4] = v;
                        }
                    }
                    __syncthreads();

                    const float (*PJ)[68] = same ? Pi : Pj;
                    const int tx = tid & 15;     // 4 rows
                    const int ty = tid >> 4;     // 0..31, 2 cols
                    float acc[4][2];
                    #pragma unroll
                    for (int ii = 0; ii < 4; ++ii) { acc[ii][0] = 0.f; acc[ii][1] = 0.f; }

                    #pragma unroll
                    for (int k = 0; k < PNL; ++k) {
                        float4 pi = *(const float4*)&Pi[k][tx * 4];
                        float pj0 = PJ[k][ty * 2], pj1 = PJ[k][ty * 2 + 1];
                        float pr[4] = {pi.x, pi.y, pi.z, pi.w};
                        #pragma unroll
                        for (int ii = 0; ii < 4; ++ii) {
                            acc[ii][0] += pr[ii] * pj0;
                            acc[ii][1] += pr[ii] * pj1;
                        }
                    }

                    const int rowb = gi + tx * 4;
                    if (rowb < r) {
                        #pragma unroll
                        for (int jj = 0; jj < 2; ++jj) {
                            const int colg = gj + ty * 2 + jj;
                            if (colg < r) {
                                const size_t off = (size_t)(base + PNL + colg) * DD + base + PNL + rowb;
                                float4 cvv = *(const float4*)(src + off);
                                cvv.x -= acc[0][jj]; cvv.y -= acc[1][jj];
                                cvv.z -= acc[2][jj]; cvv.w -= acc[3][jj];
                                *(float4*)(a + off) = cvv;
                            }
                        }
                    }
                    __syncthreads();
                }
            }
        }
        CLUSTER_SYNC();
    }
}

// ---------------------------------------------------------------------------
// Kernel 2a: invert 16 diagonal 32x32 blocks of U = L^T. One warp per (g,d).
// ---------------------------------------------------------------------------
__global__ __launch_bounds__(128, 8)
void diaginv_kernel()
{
    __shared__ float su[4][NB][NB + 1];
    __shared__ float sx[4][NB][NB + 1];

    const int g = blockIdx.x;
    const int w = threadIdx.x >> 5;
    const int d = blockIdx.y * 4 + w;
    const int cc = threadIdx.x & 31;
    const float* U = g_L + (size_t)g * DD2;
    const int b0 = d * NB;

    for (int rr = 0; rr < NB; ++rr)
        su[w][rr][cc] = U[(size_t)(b0 + rr) * DD + (b0 + cc)];
    __syncwarp();

    for (int t = cc; t >= 0; --t) {
        float s = (t == cc) ? 1.f : 0.f;
        for (int ss = t + 1; ss <= cc; ++ss)
            s -= su[w][t][ss] * sx[w][ss][cc];
        sx[w][t][cc] = s / su[w][t][t];
    }
    __syncwarp();

    float* dst = g_Dinv + ((size_t)g * 16 + d) * NB * NB;
    for (int t = 0; t < NB; ++t)
        dst[t * NB + cc] = (t <= cc) ? sx[w][t][cc] : 0.f;
}

// ---------------------------------------------------------------------------
// Kernel 2b: blocked triangular inverse + fused u + fused transposed fp16
// split output. One CTA per (g, block-column j). j scheduled LARGEST FIRST
// (work ~ j^2; draining long poles early fixes the tail).
// ---------------------------------------------------------------------------
#define T2_SMEM ((512*36 + 4*32*36 + 32*33) * 4)

__global__ __launch_bounds__(256)
void trinv_col_kernel(const float* __restrict__ mus)
{
    extern __shared__ float sm2[];
    float (*Vs)[36] = (float(*)[36])sm2;
    float (*Us)[32][36] = (float(*)[32][36])(sm2 + 512 * 36);
    float (*Ts)[33] = (float(*)[33])(sm2 + 512 * 36 + 4 * 32 * 36);

    const int g = blockIdx.x;
    const int j = 15 - blockIdx.y;          // largest columns first
    const float* U = g_L + (size_t)g * DD2;
    const int tid = threadIdx.x;
    const int cc  = tid & 31;
    const int q   = tid >> 5;

    {
        const float* din = g_Dinv + ((size_t)g * 16 + j) * NB * NB;
        #pragma unroll
        for (int t4 = 0; t4 < 4; ++t4) {
            int t = q * 4 + t4;
            Vs[j * NB + t][cc] = din[t * NB + cc];
        }
    }
    __syncthreads();

    for (int i = j - 1; i >= 0; --i) {
        float acc[4];
        #pragma unroll
        for (int r4 = 0; r4 < 4; ++r4) acc[r4] = 0.f;

        for (int kc = i + 1; kc <= j; kc += 4) {
            const int nk = (j - kc + 1 < 4) ? (j - kc + 1) : 4;
            for (int b = 0; b < nk; ++b) {
                const float* ub = U + (size_t)(i * NB) * DD + (kc + b) * NB;
                const int rr = tid >> 3, t4 = tid & 7;
                *(float4*)&Us[b][rr][t4 * 4] = *(const float4*)&ub[(size_t)rr * DD + t4 * 4];
            }
            __syncthreads();
            for (int b = 0; b < nk; ++b) {
                const int k = kc + b;
                #pragma unroll
                for (int t4 = 0; t4 < 8; ++t4) {
                    float v0 = Vs[k * NB + t4 * 4 + 0][cc];
                    float v1 = Vs[k * NB + t4 * 4 + 1][cc];
                    float v2 = Vs[k * NB + t4 * 4 + 2][cc];
                    float v3 = Vs[k * NB + t4 * 4 + 3][cc];
                    #pragma unroll
                    for (int r4 = 0; r4 < 4; ++r4) {
                        float4 u4 = *(const float4*)&Us[b][q * 4 + r4][t4 * 4];
                        acc[r4] += u4.x * v0 + u4.y * v1 + u4.z * v2 + u4.w * v3;
                    }
                }
            }
            __syncthreads();
        }

        #pragma unroll
        for (int r4 = 0; r4 < 4; ++r4) Ts[q * 4 + r4][cc] = acc[r4];
        {
            const float* din = g_Dinv + ((size_t)g * 16 + i) * NB * NB;
            const int rr = tid >> 3, t4 = tid & 7;
            *(float4*)&Us[0][rr][t4 * 4] = *(const float4*)&din[rr * NB + t4 * 4];
        }
        __syncthreads();

        float acc2[4];
        #pragma unroll
        for (int r4 = 0; r4 < 4; ++r4) acc2[r4] = 0.f;
        #pragma unroll
        for (int t4 = 0; t4 < 8; ++t4) {
            float v0 = Ts[t4 * 4 + 0][cc];
            float v1 = Ts[t4 * 4 + 1][cc];
            float v2 = Ts[t4 * 4 + 2][cc];
            float v3 = Ts[t4 * 4 + 3][cc];
            #pragma unroll
            for (int r4 = 0; r4 < 4; ++r4) {
                float4 u4 = *(const float4*)&Us[0][q * 4 + r4][t4 * 4];
                acc2[r4] += u4.x * v0 + u4.y * v1 + u4.z * v2 + u4.w * v3;
            }
        }
        #pragma unroll
        for (int r4 = 0; r4 < 4; ++r4) Vs[i * NB + q * 4 + r4][cc] = -acc2[r4];
        __syncthreads();
    }

    // fused output: Wt[n][k] = V[k][n], fp16 hi/lo, zero-padded to 128-tile
    {
        __half* Whi = g_Wthi + (size_t)g * DD2;
        __half* Wlo = g_Wtlo + (size_t)g * DD2;
        const int kmax  = (j + 1) * NB;
        const int kfill = 128 * ((j >> 2) + 1);
        for (int nl = q; nl < NB; nl += 8) {
            const size_t nbase = (size_t)(j * NB + nl) * DD;
            for (int k = cc; k < kmax; k += 32) {
                float f = Vs[k][nl];
                __half h = __float2half(f);
                __half l = __float2half(f - __half2float(h));
                Whi[nbase + k] = h;
                Wlo[nbase + k] = l;
            }
            for (int k = kmax + cc; k < kfill; k += 32) {
                Whi[nbase + k] = __float2half(0.f);
                Wlo[nbase + k] = __float2half(0.f);
            }
        }
    }

    // fused u
    {
        const float* mu = mus + (size_t)g * DD;
        float s = 0.f;
        for (int row = q; row < (j + 1) * NB; row += 8)
            s += mu[row] * Vs[row][cc];
        __syncthreads();
        Ts[q][cc] = s;
        __syncthreads();
        if (q == 0) {
            float tot = 0.f;
            #pragma unroll
            for (int w8 = 0; w8 < 8; ++w8) tot += Ts[w8][cc];
            g_u[(size_t)g * DD + j * NB + cc] = tot;
        }
    }
}

// ---------------------------------------------------------------------------
// Kernel 3: round X to fp16.
// ---------------------------------------------------------------------------
__global__ __launch_bounds__(256)
void split_x(const float* __restrict__ X)
{
    const int n = BSZ * DD / 4;
    for (int i = blockIdx.x * 256 + threadIdx.x; i < n; i += gridDim.x * 256) {
        float4 v = ((const float4*)X)[i];
        __half h[4] = {__float2half(v.x), __float2half(v.y),
                       __float2half(v.z), __float2half(v.w)};
        ((uint2*)g_Xh)[i] = *(uint2*)h;
    }
}

// ---------------------------------------------------------------------------
// Kernel 4: fp16 2-product GEMM via mma.sync + fused dist epilogue.
// (unchanged from R9 — measured at its HMMA pipe floor)
// ---------------------------------------------------------------------------
#define PITCH_A 24
#define PITCH_B 40

__global__ __launch_bounds__(256, 2)
void mma_dist_kernel()
{
    __shared__ __align__(16) __half As[2][128][PITCH_A];
    __shared__ __align__(16) __half Bs[2][128][PITCH_B];
    __shared__ float sU[512];
    __shared__ float red[128][4];

    const int tid  = threadIdx.x;
    const int lane = tid & 31;
    const int wid  = tid >> 5;
    const int wm   = wid & 1;
    const int wn   = wid >> 1;
    const int g    = blockIdx.y;
    const int b0   = blockIdx.x * 128;

    for (int c = tid; c < 512; c += 256) sU[c] = g_u[(size_t)g * DD + c];

    const __half* Xh = g_Xh + (size_t)b0 * DD;
    const __half* Wh = g_Wthi + (size_t)g * DD2;
    const __half* Wl = g_Wtlo + (size_t)g * DD2;

    const uint32_t aS = (uint32_t)__cvta_generic_to_shared(&As[0][0][0]);
    const uint32_t bS = (uint32_t)__cvta_generic_to_shared(&Bs[0][0][0]);
    const uint32_t BUFA = 128 * PITCH_A * 2;
    const uint32_t BUFB = 128 * PITCH_B * 2;

    const int lrow = tid >> 1;
    const int hsel = tid & 1;
    const int brow = ((lane >> 4) << 3) + (lane & 7);
    const int bcol = ((lane >> 3) & 1) * 8;

    float distacc[8];
    #pragma unroll
    for (int i = 0; i < 8; ++i) distacc[i] = 0.f;

    for (int nt = 0; nt < 4; ++nt) {
        const int n0 = nt * 128;
        const int nsteps = (nt + 1) * 8;

        float acc[4][4][4];
        #pragma unroll
        for (int mt = 0; mt < 4; ++mt)
            #pragma unroll
            for (int jc = 0; jc < 4; ++jc)
                #pragma unroll
                for (int e = 0; e < 4; ++e) acc[mt][jc][e] = 0.f;

        {
            cp16(aS + lrow * (PITCH_A * 2) + hsel * 16,
                 Xh + (size_t)lrow * DD + hsel * 8);
            const uint32_t br = bS + lrow * (PITCH_B * 2);
            const __half* wh = Wh + (size_t)(n0 + lrow) * DD;
            const __half* wl = Wl + (size_t)(n0 + lrow) * DD;
            cp16(br + hsel * 16, wh + hsel * 8);
            cp16(br + 32 + hsel * 16, wl + hsel * 8);
            asm volatile("cp.async.commit_group;");
        }

        for (int s = 0; s < nsteps; ++s) {
            if (s + 1 < nsteps) {
                const int k0 = (s + 1) * 16;
                const uint32_t buf = (s + 1) & 1;
                cp16(aS + buf * BUFA + lrow * (PITCH_A * 2) + hsel * 16,
                     Xh + (size_t)lrow * DD + k0 + hsel * 8);
                const uint32_t br = bS + buf * BUFB + lrow * (PITCH_B * 2);
                const __half* wh = Wh + (size_t)(n0 + lrow) * DD + k0;
                const __half* wl = Wl + (size_t)(n0 + lrow) * DD + k0;
                cp16(br + hsel * 16, wh + hsel * 8);
                cp16(br + 32 + hsel * 16, wl + hsel * 8);
                asm volatile("cp.async.commit_group;");
                asm volatile("cp.async.wait_group 1;");
            } else {
                asm volatile("cp.async.wait_group 0;");
            }
            __syncthreads();

            const uint32_t cur = s & 1;
            uint32_t ah[4][4];
            #pragma unroll
            for (int mt = 0; mt < 4; ++mt) {
                const uint32_t ad = aS + cur * BUFA
                    + (uint32_t)((wm * 64 + mt * 16 + (lane & 15)) * (PITCH_A * 2))
                    + (uint32_t)((lane >> 4) * 16);
                ldmx4(ah[mt], ad);
            }
            #pragma unroll
            for (int nb = 0; nb < 2; ++nb) {
                uint32_t bh[4], bl[4];
                const uint32_t bd = bS + cur * BUFB
                    + (uint32_t)((wn * 32 + nb * 16 + brow) * (PITCH_B * 2))
                    + (uint32_t)(bcol * 2);
                ldmx4(bh, bd);
                ldmx4(bl, bd + 32);
                #pragma unroll
                for (int mt = 0; mt < 4; ++mt) {
                    #pragma unroll
                    for (int h = 0; h < 2; ++h) {
                        float* d = acc[mt][nb * 2 + h];
                        mma16816h(d, ah[mt], &bh[h * 2]);
                        mma16816h(d, ah[mt], &bl[h * 2]);
                    }
                }
            }
            __syncthreads();
        }

        #pragma unroll
        for (int mt = 0; mt < 4; ++mt)
            #pragma unroll
            for (int jc = 0; jc < 4; ++jc) {
                const int coln = n0 + wn * 32 + (jc >> 1) * 16 + (jc & 1) * 8 + (lane & 3) * 2;
                const float u0 = sU[coln], u1 = sU[coln + 1];
                float z0 = acc[mt][jc][0] - u0, z1 = acc[mt][jc][1] - u1;
                float z2 = acc[mt][jc][2] - u0, z3 = acc[mt][jc][3] - u1;
                distacc[mt * 2 + 0] += z0 * z0 + z1 * z1;
                distacc[mt * 2 + 1] += z2 * z2 + z3 * z3;
            }
    }

    #pragma unroll
    for (int i = 0; i < 8; ++i) {
        distacc[i] += __shfl_xor_sync(0xffffffff, distacc[i], 1);
        distacc[i] += __shfl_xor_sync(0xffffffff, distacc[i], 2);
    }
    if ((lane & 3) == 0) {
        const int r = lane >> 2;
        #pragma unroll
        for (int mt = 0; mt < 4; ++mt) {
            red[wm * 64 + mt * 16 + r][wn]     = distacc[mt * 2 + 0];
            red[wm * 64 + mt * 16 + r + 8][wn] = distacc[mt * 2 + 1];
        }
    }
    __syncthreads();
    if (tid < 128)
        g_dist[(size_t)(b0 + tid) * GG + g] =
            red[tid][0] + red[tid][1] + red[tid][2] + red[tid][3];
}

// ---------------------------------------------------------------------------
// Kernel 5: out = -mean_b( min_g relu(dist[b,g]) ) / 10000
// ---------------------------------------------------------------------------
__global__ __launch_bounds__(256, 1)
void reduce_kernel(float* __restrict__ out)
{
    __shared__ float sh[256];
    float s = 0.f;
    for (int b = threadIdx.x; b < BSZ; b += 256) {
        const float* row = g_dist + (size_t)b * GG;
        float m = fmaxf(row[0], 0.f);
        #pragma unroll 8
        for (int gi = 1; gi < GG; ++gi)
            m = fminf(m, fmaxf(row[gi], 0.f));
        s += m;
    }
    sh[threadIdx.x] = s;
    __syncthreads();
    for (int off = 128; off > 0; off >>= 1) {
        if (threadIdx.x < off) sh[threadIdx.x] += sh[threadIdx.x + off];
        __syncthreads();
    }
    if (threadIdx.x == 0)
        out[0] = -sh[0] / ((float)BSZ * 10000.0f);
}

// ---------------------------------------------------------------------------
extern "C" void kernel_launch(void* const* d_in, const int* in_sizes, int n_in,
                              void* d_out, int out_size)
{
    const float* X    = nullptr;
    const float* mus  = nullptr;
    const float* covs = nullptr;
    for (int i = 0; i < n_in; ++i) {
        if      (in_sizes[i] == BSZ * DD)      X    = (const float*)d_in[i];
        else if (in_sizes[i] == GG * DD)       mus  = (const float*)d_in[i];
        else if (in_sizes[i] == GG * DD * DD)  covs = (const float*)d_in[i];
    }

    static bool attr_done = false;
    if (!attr_done) {
        cudaFuncSetAttribute(trinv_col_kernel,
                             cudaFuncAttributeMaxDynamicSharedMemorySize, T2_SMEM);
        attr_done = true;
    }

    split_x<<<512, 256>>>(X);
    chol_fused<<<GG * 2, 512>>>(covs);
    diaginv_kernel<<<dim3(GG, 4), 128>>>();
    trinv_col_kernel<<<dim3(GG, 16), 256, T2_SMEM>>>(mus);
    mma_dist_kernel<<<dim3(BSZ / 128, GG), 256>>>();
    reduce_kernel<<<1, 256>>>((float*)d_out);
}

// round 11
// speedup vs baseline: 7.6800x; 1.2851x over previous
#include <cuda_runtime.h>
#include <cuda_fp16.h>
#include <math.h>
#include <stdint.h>

// Problem sizes (fixed by the reference)
#define BSZ 2048
#define GG  64
#define DD  512
#define DD2 (DD * DD)
#define NB  32
#define PNL 64

// ---------------------------------------------------------------------------
// Scratch (device globals)
// g_L : per-gaussian Cholesky factor L, COLUMN-major (i>=j at j*DD+i).
//       Row-major view is U = L^T (valid at a*DD+b, b>=a).
// g_Wt*: transposed fp16-split inverse: Wt[n][k] = V[k][n], V = U^{-1}.
// g_Xh : X rounded to fp16 (GEMM computes dist of the rounded x exactly).
// ---------------------------------------------------------------------------
__device__ __align__(16) float g_L[GG * DD2];
__device__ __align__(16) float g_Dinv[GG * 16 * NB * NB];
__device__ __align__(16) float g_u[GG * DD];
__device__ __align__(16) float g_dist[BSZ * GG];
__device__ __align__(16) __half g_Xh[BSZ * DD];
__device__ __align__(16) __half g_Wthi[GG * DD2];
__device__ __align__(16) __half g_Wtlo[GG * DD2];

#define CLUSTER_SYNC() do { \
    asm volatile("barrier.cluster.arrive.aligned;" ::: "memory"); \
    asm volatile("barrier.cluster.wait.aligned;"   ::: "memory"); \
} while (0)

// ---------------------------------------------------------------------------
// mma.sync / cp.async helpers (portable sm_80+ path)
// ---------------------------------------------------------------------------
__device__ __forceinline__ void ldmx4(uint32_t* r, uint32_t addr) {
    asm volatile("ldmatrix.sync.aligned.m8n8.x4.shared.b16 {%0,%1,%2,%3}, [%4];"
                 : "=r"(r[0]), "=r"(r[1]), "=r"(r[2]), "=r"(r[3]) : "r"(addr));
}
__device__ __forceinline__ void mma16816h(float* d, const uint32_t* a, const uint32_t* b) {
    asm volatile(
        "mma.sync.aligned.m16n8k16.row.col.f32.f16.f16.f32 "
        "{%0,%1,%2,%3}, {%4,%5,%6,%7}, {%8,%9}, {%0,%1,%2,%3};"
        : "+f"(d[0]), "+f"(d[1]), "+f"(d[2]), "+f"(d[3])
        : "r"(a[0]), "r"(a[1]), "r"(a[2]), "r"(a[3]), "r"(b[0]), "r"(b[1]));
}
__device__ __forceinline__ void cp16(uint32_t s, const void* g) {
    asm volatile("cp.async.ca.shared.global [%0], [%1], 16;" :: "r"(s), "l"(g));
}

// ---------------------------------------------------------------------------
// Warp-level 32x32 Cholesky in REGISTERS (lane = row, shfl column broadcast).
// Replaces the smem read-modify-write chain (~18k cyc) with a pipelined
// shfl+FFMA sequence (~3k cyc). Reads/writes s[roff+lane][coff+j]; also
// writes rdiag[roff+lane] = 1/L_kk. Called by warp 0 only.
// ---------------------------------------------------------------------------
__device__ __forceinline__ void warp_chol32(float (*s)[PNL + 1], int roff, int coff,
                                            float* rdiag)
{
    const int lane = threadIdx.x;   // caller guarantees tid < 32
    float x[32];
    #pragma unroll
    for (int j = 0; j < 32; ++j) x[j] = s[roff + lane][coff + j];

    float myrs = 0.f;
    #pragma unroll
    for (int k = 0; k < 32; ++k) {
        float dval = __shfl_sync(0xffffffffu, x[k], k);
        float rs = rsqrtf(dval);
        if (lane == k) { x[k] = dval * rs; myrs = rs; }
        float lik = (lane > k) ? x[k] * rs : 0.f;
        if (lane > k) x[k] = lik;
        #pragma unroll
        for (int j = k + 1; j < 32; ++j) {
            float ljk = __shfl_sync(0xffffffffu, lik, j);
            x[j] -= lik * ljk;
        }
    }
    #pragma unroll
    for (int j = 0; j < 32; ++j) s[roff + lane][coff + j] = x[j];
    rdiag[roff + lane] = myrs;
}

// ---------------------------------------------------------------------------
// Kernel 1: fused blocked Cholesky, NB=64 panels, cluster of 2 CTAs per
// gaussian, 512 threads. Diag-64 factored hierarchically (reg-shfl 32-factor /
// reg row-solve / inner syrk / reg-shfl 32-factor). Panel solve: one
// 64-register row per thread. SYRK: 64x64 tiles, k=64.
// ---------------------------------------------------------------------------
__global__ __launch_bounds__(512) __cluster_dims__(2, 1, 1)
void chol_fused(const float* __restrict__ covs)
{
    __shared__ float s11[PNL][PNL + 1];
    __shared__ float rdiag[PNL];
    __shared__ __align__(16) float Pi[PNL][68];
    __shared__ __align__(16) float Pj[PNL][68];

    const int g = blockIdx.x >> 1;
    unsigned crank;
    asm("mov.u32 %0, %%cluster_ctarank;" : "=r"(crank));
    float* a = g_L + (size_t)g * DD2;
    const float* cv = covs + (size_t)g * DD2;
    const int tid = threadIdx.x;

    for (int p = 0; p < DD / PNL; ++p) {
        const int base = p * PNL;
        const int r = DD - base - PNL;
        const float* src = (p == 0) ? cv : a;

        // ---- load 64x64 diag block
        for (int q = tid; q < PNL * PNL; q += 512) {
            int i = q & 63, j = q >> 6;
            s11[i][j] = src[(size_t)(base + j) * DD + (base + i)];
        }
        __syncthreads();

        // ---- phase A: warp 0 factors top-left 32x32 (registers + shfl)
        if (tid < 32) warp_chol32(s11, 0, 0, rdiag);
        __syncthreads();

        // ---- phase B: solve rows 32..63 of the diag block vs L11a
        if (tid < 32) {
            const int row = 32 + tid;
            float x[32];
            #pragma unroll
            for (int j = 0; j < 32; ++j) x[j] = s11[row][j];
            #pragma unroll
            for (int j = 0; j < 32; ++j) {
                float s = x[j];
                #pragma unroll
                for (int k = 0; k < j; ++k)
                    s -= x[k] * s11[j][k];
                x[j] = s * rdiag[j];
            }
            #pragma unroll
            for (int j = 0; j < 32; ++j) s11[row][j] = x[j];
        }
        __syncthreads();

        // ---- phase C: inner SYRK s11[32:64][32:64] -= L21' L21'^T
        #pragma unroll
        for (int e = 0; e < 2; ++e) {
            const int idx = tid + e * 512;
            const int i2 = 32 + (idx >> 5);
            const int j2 = 32 + (idx & 31);
            float s = 0.f;
            #pragma unroll
            for (int k = 0; k < 32; ++k)
                s += s11[i2][k] * s11[j2][k];
            s11[i2][j2] -= s;
        }
        __syncthreads();

        // ---- phase D: warp 0 factors bottom-right 32x32 (registers + shfl)
        if (tid < 32) warp_chol32(s11, 32, 32, rdiag);
        __syncthreads();

        // ---- write factored diag back (lower incl diag)
        if (crank == 0) {
            for (int q = tid; q < PNL * PNL; q += 512) {
                int i = q & 63, j = q >> 6;
                if (i >= j) a[(size_t)(base + j) * DD + (base + i)] = s11[i][j];
            }
        }

        // ---- panel solve: my half of the rows, 1 reg-resident row/thread
        if (r > 0) {
            const int chunk = (r + 1) >> 1;
            const int row = (int)crank * chunk + tid;
            if (row < r && tid < chunk) {
                const int gr = base + PNL + row;
                float x[PNL];
                #pragma unroll
                for (int j = 0; j < PNL; ++j)
                    x[j] = src[(size_t)(base + j) * DD + gr];
                #pragma unroll
                for (int j = 0; j < PNL; ++j) {
                    float s = x[j];
                    #pragma unroll
                    for (int k = 0; k < j; ++k)
                        s -= x[k] * s11[j][k];
                    x[j] = s * rdiag[j];
                }
                #pragma unroll
                for (int j = 0; j < PNL; ++j)
                    a[(size_t)(base + j) * DD + gr] = x[j];
            }
        }
        CLUSTER_SYNC();

        // ---- SYRK trailing update, 64x64 tiles, k = 64
        if (r > 0) {
            const int m = (r + 63) >> 6;
            for (int ti = (int)crank; ti < m; ti += 2) {
                const int gi = ti * 64;
                #pragma unroll
                for (int f = 0; f < 2; ++f) {
                    const int s   = tid + 512 * f;
                    const int col = s >> 4;
                    const int r4  = s & 15;
                    const int row = gi + r4 * 4;
                    float4 v = make_float4(0.f, 0.f, 0.f, 0.f);
                    if (row < r)
                        v = *(const float4*)(a + (size_t)(base + col) * DD + base + PNL + row);
                    *(float4*)&Pi[col][r4 * 4] = v;
                }

                for (int tj = 0; tj <= ti; ++tj) {
                    const int gj = tj * 64;
                    const bool same = (tj == ti);
                    if (!same) {
                        #pragma unroll
                        for (int f = 0; f < 2; ++f) {
                            const int s   = tid + 512 * f;
                            const int col = s >> 4;
                            const int r4  = s & 15;
                            const int row = gj + r4 * 4;
                            float4 v = make_float4(0.f, 0.f, 0.f, 0.f);
                            if (row < r)
                                v = *(const float4*)(a + (size_t)(base + col) * DD + base + PNL + row);
                            *(float4*)&Pj[col][r4 * 4] = v;
                        }
                    }
                    __syncthreads();

                    const float (*PJ)[68] = same ? Pi : Pj;
                    const int tx = tid & 15;
                    const int ty = tid >> 4;
                    float acc[4][2];
                    #pragma unroll
                    for (int ii = 0; ii < 4; ++ii) { acc[ii][0] = 0.f; acc[ii][1] = 0.f; }

                    #pragma unroll
                    for (int k = 0; k < PNL; ++k) {
                        float4 pi = *(const float4*)&Pi[k][tx * 4];
                        float pj0 = PJ[k][ty * 2], pj1 = PJ[k][ty * 2 + 1];
                        float pr[4] = {pi.x, pi.y, pi.z, pi.w};
                        #pragma unroll
                        for (int ii = 0; ii < 4; ++ii) {
                            acc[ii][0] += pr[ii] * pj0;
                            acc[ii][1] += pr[ii] * pj1;
                        }
                    }

                    const int rowb = gi + tx * 4;
                    if (rowb < r) {
                        #pragma unroll
                        for (int jj = 0; jj < 2; ++jj) {
                            const int colg = gj + ty * 2 + jj;
                            if (colg < r) {
                                const size_t off = (size_t)(base + PNL + colg) * DD + base + PNL + rowb;
                                float4 cvv = *(const float4*)(src + off);
                                cvv.x -= acc[0][jj]; cvv.y -= acc[1][jj];
                                cvv.z -= acc[2][jj]; cvv.w -= acc[3][jj];
                                *(float4*)(a + off) = cvv;
                            }
                        }
                    }
                    __syncthreads();
                }
            }
        }
        CLUSTER_SYNC();
    }
}

// ---------------------------------------------------------------------------
// Kernel 2a: invert 16 diagonal 32x32 blocks of U = L^T. One warp per (g,d).
// ---------------------------------------------------------------------------
__global__ __launch_bounds__(128, 8)
void diaginv_kernel()
{
    __shared__ float su[4][NB][NB + 1];
    __shared__ float sx[4][NB][NB + 1];

    const int g = blockIdx.x;
    const int w = threadIdx.x >> 5;
    const int d = blockIdx.y * 4 + w;
    const int cc = threadIdx.x & 31;
    const float* U = g_L + (size_t)g * DD2;
    const int b0 = d * NB;

    for (int rr = 0; rr < NB; ++rr)
        su[w][rr][cc] = U[(size_t)(b0 + rr) * DD + (b0 + cc)];
    __syncwarp();

    for (int t = cc; t >= 0; --t) {
        float s = (t == cc) ? 1.f : 0.f;
        for (int ss = t + 1; ss <= cc; ++ss)
            s -= su[w][t][ss] * sx[w][ss][cc];
        sx[w][t][cc] = s / su[w][t][t];
    }
    __syncwarp();

    float* dst = g_Dinv + ((size_t)g * 16 + d) * NB * NB;
    for (int t = 0; t < NB; ++t)
        dst[t * NB + cc] = (t <= cc) ? sx[w][t][cc] : 0.f;
}

// ---------------------------------------------------------------------------
// Kernel 2b: blocked triangular inverse + fused u + fused transposed fp16
// split output. One CTA per (g, block-column j), largest j first.
// ---------------------------------------------------------------------------
#define T2_SMEM ((512*36 + 4*32*36 + 32*33) * 4)

__global__ __launch_bounds__(256)
void trinv_col_kernel(const float* __restrict__ mus)
{
    extern __shared__ float sm2[];
    float (*Vs)[36] = (float(*)[36])sm2;
    float (*Us)[32][36] = (float(*)[32][36])(sm2 + 512 * 36);
    float (*Ts)[33] = (float(*)[33])(sm2 + 512 * 36 + 4 * 32 * 36);

    const int g = blockIdx.x;
    const int j = 15 - blockIdx.y;
    const float* U = g_L + (size_t)g * DD2;
    const int tid = threadIdx.x;
    const int cc  = tid & 31;
    const int q   = tid >> 5;

    {
        const float* din = g_Dinv + ((size_t)g * 16 + j) * NB * NB;
        #pragma unroll
        for (int t4 = 0; t4 < 4; ++t4) {
            int t = q * 4 + t4;
            Vs[j * NB + t][cc] = din[t * NB + cc];
        }
    }
    __syncthreads();

    for (int i = j - 1; i >= 0; --i) {
        float acc[4];
        #pragma unroll
        for (int r4 = 0; r4 < 4; ++r4) acc[r4] = 0.f;

        for (int kc = i + 1; kc <= j; kc += 4) {
            const int nk = (j - kc + 1 < 4) ? (j - kc + 1) : 4;
            for (int b = 0; b < nk; ++b) {
                const float* ub = U + (size_t)(i * NB) * DD + (kc + b) * NB;
                const int rr = tid >> 3, t4 = tid & 7;
                *(float4*)&Us[b][rr][t4 * 4] = *(const float4*)&ub[(size_t)rr * DD + t4 * 4];
            }
            __syncthreads();
            for (int b = 0; b < nk; ++b) {
                const int k = kc + b;
                #pragma unroll
                for (int t4 = 0; t4 < 8; ++t4) {
                    float v0 = Vs[k * NB + t4 * 4 + 0][cc];
                    float v1 = Vs[k * NB + t4 * 4 + 1][cc];
                    float v2 = Vs[k * NB + t4 * 4 + 2][cc];
                    float v3 = Vs[k * NB + t4 * 4 + 3][cc];
                    #pragma unroll
                    for (int r4 = 0; r4 < 4; ++r4) {
                        float4 u4 = *(const float4*)&Us[b][q * 4 + r4][t4 * 4];
                        acc[r4] += u4.x * v0 + u4.y * v1 + u4.z * v2 + u4.w * v3;
                    }
                }
            }
            __syncthreads();
        }

        #pragma unroll
        for (int r4 = 0; r4 < 4; ++r4) Ts[q * 4 + r4][cc] = acc[r4];
        {
            const float* din = g_Dinv + ((size_t)g * 16 + i) * NB * NB;
            const int rr = tid >> 3, t4 = tid & 7;
            *(float4*)&Us[0][rr][t4 * 4] = *(const float4*)&din[rr * NB + t4 * 4];
        }
        __syncthreads();

        float acc2[4];
        #pragma unroll
        for (int r4 = 0; r4 < 4; ++r4) acc2[r4] = 0.f;
        #pragma unroll
        for (int t4 = 0; t4 < 8; ++t4) {
            float v0 = Ts[t4 * 4 + 0][cc];
            float v1 = Ts[t4 * 4 + 1][cc];
            float v2 = Ts[t4 * 4 + 2][cc];
            float v3 = Ts[t4 * 4 + 3][cc];
            #pragma unroll
            for (int r4 = 0; r4 < 4; ++r4) {
                float4 u4 = *(const float4*)&Us[0][q * 4 + r4][t4 * 4];
                acc2[r4] += u4.x * v0 + u4.y * v1 + u4.z * v2 + u4.w * v3;
            }
        }
        #pragma unroll
        for (int r4 = 0; r4 < 4; ++r4) Vs[i * NB + q * 4 + r4][cc] = -acc2[r4];
        __syncthreads();
    }

    // fused output: Wt[n][k] = V[k][n], fp16 hi/lo, zero-padded to 128-tile
    {
        __half* Whi = g_Wthi + (size_t)g * DD2;
        __half* Wlo = g_Wtlo + (size_t)g * DD2;
        const int kmax  = (j + 1) * NB;
        const int kfill = 128 * ((j >> 2) + 1);
        for (int nl = q; nl < NB; nl += 8) {
            const size_t nbase = (size_t)(j * NB + nl) * DD;
            for (int k = cc; k < kmax; k += 32) {
                float f = Vs[k][nl];
                __half h = __float2half(f);
                __half l = __float2half(f - __half2float(h));
                Whi[nbase + k] = h;
                Wlo[nbase + k] = l;
            }
            for (int k = kmax + cc; k < kfill; k += 32) {
                Whi[nbase + k] = __float2half(0.f);
                Wlo[nbase + k] = __float2half(0.f);
            }
        }
    }

    // fused u
    {
        const float* mu = mus + (size_t)g * DD;
        float s = 0.f;
        for (int row = q; row < (j + 1) * NB; row += 8)
            s += mu[row] * Vs[row][cc];
        __syncthreads();
        Ts[q][cc] = s;
        __syncthreads();
        if (q == 0) {
            float tot = 0.f;
            #pragma unroll
            for (int w8 = 0; w8 < 8; ++w8) tot += Ts[w8][cc];
            g_u[(size_t)g * DD + j * NB + cc] = tot;
        }
    }
}

// ---------------------------------------------------------------------------
// Kernel 3: round X to fp16.
// ---------------------------------------------------------------------------
__global__ __launch_bounds__(256)
void split_x(const float* __restrict__ X)
{
    const int n = BSZ * DD / 4;
    for (int i = blockIdx.x * 256 + threadIdx.x; i < n; i += gridDim.x * 256) {
        float4 v = ((const float4*)X)[i];
        __half h[4] = {__float2half(v.x), __float2half(v.y),
                       __float2half(v.z), __float2half(v.w)};
        ((uint2*)g_Xh)[i] = *(uint2*)h;
    }
}

// ---------------------------------------------------------------------------
// Kernel 4: fp16 2-product GEMM via mma.sync + fused dist epilogue.
// (unchanged — measured at its HMMA pipe floor)
// ---------------------------------------------------------------------------
#define PITCH_A 24
#define PITCH_B 40

__global__ __launch_bounds__(256, 2)
void mma_dist_kernel()
{
    __shared__ __align__(16) __half As[2][128][PITCH_A];
    __shared__ __align__(16) __half Bs[2][128][PITCH_B];
    __shared__ float sU[512];
    __shared__ float red[128][4];

    const int tid  = threadIdx.x;
    const int lane = tid & 31;
    const int wid  = tid >> 5;
    const int wm   = wid & 1;
    const int wn   = wid >> 1;
    const int g    = blockIdx.y;
    const int b0   = blockIdx.x * 128;

    for (int c = tid; c < 512; c += 256) sU[c] = g_u[(size_t)g * DD + c];

    const __half* Xh = g_Xh + (size_t)b0 * DD;
    const __half* Wh = g_Wthi + (size_t)g * DD2;
    const __half* Wl = g_Wtlo + (size_t)g * DD2;

    const uint32_t aS = (uint32_t)__cvta_generic_to_shared(&As[0][0][0]);
    const uint32_t bS = (uint32_t)__cvta_generic_to_shared(&Bs[0][0][0]);
    const uint32_t BUFA = 128 * PITCH_A * 2;
    const uint32_t BUFB = 128 * PITCH_B * 2;

    const int lrow = tid >> 1;
    const int hsel = tid & 1;
    const int brow = ((lane >> 4) << 3) + (lane & 7);
    const int bcol = ((lane >> 3) & 1) * 8;

    float distacc[8];
    #pragma unroll
    for (int i = 0; i < 8; ++i) distacc[i] = 0.f;

    for (int nt = 0; nt < 4; ++nt) {
        const int n0 = nt * 128;
        const int nsteps = (nt + 1) * 8;

        float acc[4][4][4];
        #pragma unroll
        for (int mt = 0; mt < 4; ++mt)
            #pragma unroll
            for (int jc = 0; jc < 4; ++jc)
                #pragma unroll
                for (int e = 0; e < 4; ++e) acc[mt][jc][e] = 0.f;

        {
            cp16(aS + lrow * (PITCH_A * 2) + hsel * 16,
                 Xh + (size_t)lrow * DD + hsel * 8);
            const uint32_t br = bS + lrow * (PITCH_B * 2);
            const __half* wh = Wh + (size_t)(n0 + lrow) * DD;
            const __half* wl = Wl + (size_t)(n0 + lrow) * DD;
            cp16(br + hsel * 16, wh + hsel * 8);
            cp16(br + 32 + hsel * 16, wl + hsel * 8);
            asm volatile("cp.async.commit_group;");
        }

        for (int s = 0; s < nsteps; ++s) {
            if (s + 1 < nsteps) {
                const int k0 = (s + 1) * 16;
                const uint32_t buf = (s + 1) & 1;
                cp16(aS + buf * BUFA + lrow * (PITCH_A * 2) + hsel * 16,
                     Xh + (size_t)lrow * DD + k0 + hsel * 8);
                const uint32_t br = bS + buf * BUFB + lrow * (PITCH_B * 2);
                const __half* wh = Wh + (size_t)(n0 + lrow) * DD + k0;
                const __half* wl = Wl + (size_t)(n0 + lrow) * DD + k0;
                cp16(br + hsel * 16, wh + hsel * 8);
                cp16(br + 32 + hsel * 16, wl + hsel * 8);
                asm volatile("cp.async.commit_group;");
                asm volatile("cp.async.wait_group 1;");
            } else {
                asm volatile("cp.async.wait_group 0;");
            }
            __syncthreads();

            const uint32_t cur = s & 1;
            uint32_t ah[4][4];
            #pragma unroll
            for (int mt = 0; mt < 4; ++mt) {
                const uint32_t ad = aS + cur * BUFA
                    + (uint32_t)((wm * 64 + mt * 16 + (lane & 15)) * (PITCH_A * 2))
                    + (uint32_t)((lane >> 4) * 16);
                ldmx4(ah[mt], ad);
            }
            #pragma unroll
            for (int nb = 0; nb < 2; ++nb) {
                uint32_t bh[4], bl[4];
                const uint32_t bd = bS + cur * BUFB
                    + (uint32_t)((wn * 32 + nb * 16 + brow) * (PITCH_B * 2))
                    + (uint32_t)(bcol * 2);
                ldmx4(bh, bd);
                ldmx4(bl, bd + 32);
                #pragma unroll
                for (int mt = 0; mt < 4; ++mt) {
                    #pragma unroll
                    for (int h = 0; h < 2; ++h) {
                        float* d = acc[mt][nb * 2 + h];
                        mma16816h(d, ah[mt], &bh[h * 2]);
                        mma16816h(d, ah[mt], &bl[h * 2]);
                    }
                }
            }
            __syncthreads();
        }

        #pragma unroll
        for (int mt = 0; mt < 4; ++mt)
            #pragma unroll
            for (int jc = 0; jc < 4; ++jc) {
                const int coln = n0 + wn * 32 + (jc >> 1) * 16 + (jc & 1) * 8 + (lane & 3) * 2;
                const float u0 = sU[coln], u1 = sU[coln + 1];
                float z0 = acc[mt][jc][0] - u0, z1 = acc[mt][jc][1] - u1;
                float z2 = acc[mt][jc][2] - u0, z3 = acc[mt][jc][3] - u1;
                distacc[mt * 2 + 0] += z0 * z0 + z1 * z1;
                distacc[mt * 2 + 1] += z2 * z2 + z3 * z3;
            }
    }

    #pragma unroll
    for (int i = 0; i < 8; ++i) {
        distacc[i] += __shfl_xor_sync(0xffffffff, distacc[i], 1);
        distacc[i] += __shfl_xor_sync(0xffffffff, distacc[i], 2);
    }
    if ((lane & 3) == 0) {
        const int r = lane >> 2;
        #pragma unroll
        for (int mt = 0; mt < 4; ++mt) {
            red[wm * 64 + mt * 16 + r][wn]     = distacc[mt * 2 + 0];
            red[wm * 64 + mt * 16 + r + 8][wn] = distacc[mt * 2 + 1];
        }
    }
    __syncthreads();
    if (tid < 128)
        g_dist[(size_t)(b0 + tid) * GG + g] =
            red[tid][0] + red[tid][1] + red[tid][2] + red[tid][3];
}

// ---------------------------------------------------------------------------
// Kernel 5: out = -mean_b( min_g relu(dist[b,g]) ) / 10000
// ---------------------------------------------------------------------------
__global__ __launch_bounds__(256, 1)
void reduce_kernel(float* __restrict__ out)
{
    __shared__ float sh[256];
    float s = 0.f;
    for (int b = threadIdx.x; b < BSZ; b += 256) {
        const float* row = g_dist + (size_t)b * GG;
        float m = fmaxf(row[0], 0.f);
        #pragma unroll 8
        for (int gi = 1; gi < GG; ++gi)
            m = fminf(m, fmaxf(row[gi], 0.f));
        s += m;
    }
    sh[threadIdx.x] = s;
    __syncthreads();
    for (int off = 128; off > 0; off >>= 1) {
        if (threadIdx.x < off) sh[threadIdx.x] += sh[threadIdx.x + off];
        __syncthreads();
    }
    if (threadIdx.x == 0)
        out[0] = -sh[0] / ((float)BSZ * 10000.0f);
}

// ---------------------------------------------------------------------------
extern "C" void kernel_launch(void* const* d_in, const int* in_sizes, int n_in,
                              void* d_out, int out_size)
{
    const float* X    = nullptr;
    const float* mus  = nullptr;
    const float* covs = nullptr;
    for (int i = 0; i < n_in; ++i) {
        if      (in_sizes[i] == BSZ * DD)      X    = (const float*)d_in[i];
        else if (in_sizes[i] == GG * DD)       mus  = (const float*)d_in[i];
        else if (in_sizes[i] == GG * DD * DD)  covs = (const float*)d_in[i];
    }

    static bool attr_done = false;
    if (!attr_done) {
        cudaFuncSetAttribute(trinv_col_kernel,
                             cudaFuncAttributeMaxDynamicSharedMemorySize, T2_SMEM);
        attr_done = true;
    }

    split_x<<<512, 256>>>(X);
    chol_fused<<<GG * 2, 512>>>(covs);
    diaginv_kernel<<<dim3(GG, 4), 128>>>();
    trinv_col_kernel<<<dim3(GG, 16), 256, T2_SMEM>>>(mus);
    mma_dist_kernel<<<dim3(BSZ / 128, GG), 256>>>();
    reduce_kernel<<<1, 256>>>((float*)d_out);
}

// round 12
// speedup vs baseline: 7.8660x; 1.0242x over previous
#include <cuda_runtime.h>
#include <cuda_fp16.h>
#include <math.h>
#include <stdint.h>

// Problem sizes (fixed by the reference)
#define BSZ 2048
#define GG  64
#define DD  512
#define DD2 (DD * DD)
#define NB  32
#define PNL 64

// ---------------------------------------------------------------------------
// Scratch (device globals)
// g_L : per-gaussian Cholesky factor L, COLUMN-major (i>=j at j*DD+i).
//       Row-major view is U = L^T (valid at a*DD+b, b>=a).
// g_Wt*: transposed fp16-split inverse: Wt[n][k] = V[k][n], V = U^{-1}.
// g_Xh : X rounded to fp16 (GEMM computes dist of the rounded x exactly).
// ---------------------------------------------------------------------------
__device__ __align__(16) float g_L[GG * DD2];
__device__ __align__(16) float g_Dinv[GG * 16 * NB * NB];
__device__ __align__(16) float g_u[GG * DD];
__device__ __align__(16) float g_dist[BSZ * GG];
__device__ __align__(16) __half g_Xh[BSZ * DD];
__device__ __align__(16) __half g_Wthi[GG * DD2];
__device__ __align__(16) __half g_Wtlo[GG * DD2];

#define CLUSTER_SYNC() do { \
    asm volatile("barrier.cluster.arrive.aligned;" ::: "memory"); \
    asm volatile("barrier.cluster.wait.aligned;"   ::: "memory"); \
} while (0)

// ---------------------------------------------------------------------------
// mma.sync / cp.async helpers (portable sm_80+ path)
// ---------------------------------------------------------------------------
__device__ __forceinline__ void ldmx4(uint32_t* r, uint32_t addr) {
    asm volatile("ldmatrix.sync.aligned.m8n8.x4.shared.b16 {%0,%1,%2,%3}, [%4];"
                 : "=r"(r[0]), "=r"(r[1]), "=r"(r[2]), "=r"(r[3]) : "r"(addr));
}
__device__ __forceinline__ void mma16816h(float* d, const uint32_t* a, const uint32_t* b) {
    asm volatile(
        "mma.sync.aligned.m16n8k16.row.col.f32.f16.f16.f32 "
        "{%0,%1,%2,%3}, {%4,%5,%6,%7}, {%8,%9}, {%0,%1,%2,%3};"
        : "+f"(d[0]), "+f"(d[1]), "+f"(d[2]), "+f"(d[3])
        : "r"(a[0]), "r"(a[1]), "r"(a[2]), "r"(a[3]), "r"(b[0]), "r"(b[1]));
}
__device__ __forceinline__ void cp16(uint32_t s, const void* g) {
    asm volatile("cp.async.ca.shared.global [%0], [%1], 16;" :: "r"(s), "l"(g));
}

// ---------------------------------------------------------------------------
// Warp-level 32x32 Cholesky in REGISTERS (lane = row, shfl column broadcast).
// ---------------------------------------------------------------------------
__device__ __forceinline__ void warp_chol32(float (*s)[PNL + 1], int roff, int coff,
                                            float* rdiag)
{
    const int lane = threadIdx.x;   // caller guarantees tid < 32
    float x[32];
    #pragma unroll
    for (int j = 0; j < 32; ++j) x[j] = s[roff + lane][coff + j];

    float myrs = 0.f;
    #pragma unroll
    for (int k = 0; k < 32; ++k) {
        float dval = __shfl_sync(0xffffffffu, x[k], k);
        float rs = rsqrtf(dval);
        if (lane == k) { x[k] = dval * rs; myrs = rs; }
        float lik = (lane > k) ? x[k] * rs : 0.f;
        if (lane > k) x[k] = lik;
        #pragma unroll
        for (int j = k + 1; j < 32; ++j) {
            float ljk = __shfl_sync(0xffffffffu, lik, j);
            x[j] -= lik * ljk;
        }
    }
    #pragma unroll
    for (int j = 0; j < 32; ++j) s[roff + lane][coff + j] = x[j];
    rdiag[roff + lane] = myrs;
}

// ---------------------------------------------------------------------------
// Kernel 1: fused blocked Cholesky, NB=64 panels, cluster of 2 CTAs per
// gaussian, 512 threads, dynamic smem. SYRK uses cp.async double-buffered
// Pj (1 sync/tile). r is always a multiple of 64 -> no bounds guards.
// smem: s11[64][65] + rdiag[64] + Pi[64][68] + Pj0[64][68] + Pj1[64][68]
// ---------------------------------------------------------------------------
#define CHOL_SMEM ((64*65 + 64 + 3*64*68) * 4)

__global__ __launch_bounds__(512) __cluster_dims__(2, 1, 1)
void chol_fused(const float* __restrict__ covs)
{
    extern __shared__ float smc[];
    float (*s11)[PNL + 1] = (float(*)[PNL + 1])smc;
    float* rdiag          = smc + 64 * 65;
    float (*Pi)[68]       = (float(*)[68])(smc + 64 * 65 + 64);
    float (*Pj0)[68]      = (float(*)[68])(smc + 64 * 65 + 64 + 64 * 68);
    float (*Pj1)[68]      = (float(*)[68])(smc + 64 * 65 + 64 + 2 * 64 * 68);

    const int g = blockIdx.x >> 1;
    unsigned crank;
    asm("mov.u32 %0, %%cluster_ctarank;" : "=r"(crank));
    float* a = g_L + (size_t)g * DD2;
    const float* cv = covs + (size_t)g * DD2;
    const int tid = threadIdx.x;

    const uint32_t sPi  = (uint32_t)__cvta_generic_to_shared(&Pi[0][0]);
    const uint32_t sPj0 = (uint32_t)__cvta_generic_to_shared(&Pj0[0][0]);
    const uint32_t sPj1 = (uint32_t)__cvta_generic_to_shared(&Pj1[0][0]);

    for (int p = 0; p < DD / PNL; ++p) {
        const int base = p * PNL;
        const int r = DD - base - PNL;
        const float* src = (p == 0) ? cv : a;

        // ---- load 64x64 diag block
        for (int q = tid; q < PNL * PNL; q += 512) {
            int i = q & 63, j = q >> 6;
            s11[i][j] = src[(size_t)(base + j) * DD + (base + i)];
        }
        __syncthreads();

        // ---- hierarchical diag factorization (reg-shfl)
        if (tid < 32) warp_chol32(s11, 0, 0, rdiag);
        __syncthreads();

        if (tid < 32) {
            const int row = 32 + tid;
            float x[32];
            #pragma unroll
            for (int j = 0; j < 32; ++j) x[j] = s11[row][j];
            #pragma unroll
            for (int j = 0; j < 32; ++j) {
                float s = x[j];
                #pragma unroll
                for (int k = 0; k < j; ++k)
                    s -= x[k] * s11[j][k];
                x[j] = s * rdiag[j];
            }
            #pragma unroll
            for (int j = 0; j < 32; ++j) s11[row][j] = x[j];
        }
        __syncthreads();

        #pragma unroll
        for (int e = 0; e < 2; ++e) {
            const int idx = tid + e * 512;
            const int i2 = 32 + (idx >> 5);
            const int j2 = 32 + (idx & 31);
            float s = 0.f;
            #pragma unroll
            for (int k = 0; k < 32; ++k)
                s += s11[i2][k] * s11[j2][k];
            s11[i2][j2] -= s;
        }
        __syncthreads();

        if (tid < 32) warp_chol32(s11, 32, 32, rdiag);
        __syncthreads();

        // ---- write factored diag back (lower incl diag)
        if (crank == 0) {
            for (int q = tid; q < PNL * PNL; q += 512) {
                int i = q & 63, j = q >> 6;
                if (i >= j) a[(size_t)(base + j) * DD + (base + i)] = s11[i][j];
            }
        }

        // ---- panel solve: my half of the rows, 1 reg-resident row/thread
        if (r > 0) {
            const int chunk = r >> 1;
            const int row = (int)crank * chunk + tid;
            if (row < r && tid < chunk) {
                const int gr = base + PNL + row;
                float x[PNL];
                #pragma unroll
                for (int j = 0; j < PNL; ++j)
                    x[j] = src[(size_t)(base + j) * DD + gr];
                #pragma unroll
                for (int j = 0; j < PNL; ++j) {
                    float s = x[j];
                    #pragma unroll
                    for (int k = 0; k < j; ++k)
                        s -= x[k] * s11[j][k];
                    x[j] = s * rdiag[j];
                }
                #pragma unroll
                for (int j = 0; j < PNL; ++j)
                    a[(size_t)(base + j) * DD + gr] = x[j];
            }
        }
        CLUSTER_SYNC();

        // ---- SYRK trailing update, 64x64 tiles, cp.async double-buffered
        if (r > 0) {
            const int m = r >> 6;
            for (int ti = (int)crank; ti < m; ti += 2) {
                const int gi = ti * 64;

                // prologue: stage Pi (+ Pj[0] if off-diag tiles exist)
                #pragma unroll
                for (int e = 0; e < 2; ++e) {
                    const int f = tid * 2 + e;
                    const int col = f >> 4, r4 = f & 15;
                    cp16(sPi + (uint32_t)((col * 68 + r4 * 4) * 4),
                         a + (size_t)(base + col) * DD + base + PNL + gi + r4 * 4);
                }
                if (ti > 0) {
                    #pragma unroll
                    for (int e = 0; e < 2; ++e) {
                        const int f = tid * 2 + e;
                        const int col = f >> 4, r4 = f & 15;
                        cp16(sPj0 + (uint32_t)((col * 68 + r4 * 4) * 4),
                             a + (size_t)(base + col) * DD + base + PNL + r4 * 4);
                    }
                }
                asm volatile("cp.async.commit_group;");
                asm volatile("cp.async.wait_group 0;");
                __syncthreads();

                for (int tj = 0; tj <= ti; ++tj) {
                    // prefetch tj+1 (if it's an off-diag tile)
                    if (tj + 1 < ti) {
                        const int gjn = (tj + 1) * 64;
                        const uint32_t dstb = ((tj + 1) & 1) ? sPj1 : sPj0;
                        #pragma unroll
                        for (int e = 0; e < 2; ++e) {
                            const int f = tid * 2 + e;
                            const int col = f >> 4, r4 = f & 15;
                            cp16(dstb + (uint32_t)((col * 68 + r4 * 4) * 4),
                                 a + (size_t)(base + col) * DD + base + PNL + gjn + r4 * 4);
                        }
                        asm volatile("cp.async.commit_group;");
                    }

                    const int gj = tj * 64;
                    const float (*PJ)[68] = (tj == ti) ? Pi
                                           : ((tj & 1) ? Pj1 : Pj0);
                    const int tx = tid & 15;     // 4 rows
                    const int ty = tid >> 4;     // 0..31, 2 cols
                    float acc[4][2];
                    #pragma unroll
                    for (int ii = 0; ii < 4; ++ii) { acc[ii][0] = 0.f; acc[ii][1] = 0.f; }

                    #pragma unroll
                    for (int k = 0; k < PNL; ++k) {
                        float4 pi = *(const float4*)&Pi[k][tx * 4];
                        float pj0 = PJ[k][ty * 2], pj1 = PJ[k][ty * 2 + 1];
                        float pr[4] = {pi.x, pi.y, pi.z, pi.w};
                        #pragma unroll
                        for (int ii = 0; ii < 4; ++ii) {
                            acc[ii][0] += pr[ii] * pj0;
                            acc[ii][1] += pr[ii] * pj1;
                        }
                    }

                    const int rowb = gi + tx * 4;
                    #pragma unroll
                    for (int jj = 0; jj < 2; ++jj) {
                        const int colg = gj + ty * 2 + jj;
                        const size_t off = (size_t)(base + PNL + colg) * DD + base + PNL + rowb;
                        float4 cvv = *(const float4*)(src + off);
                        cvv.x -= acc[0][jj]; cvv.y -= acc[1][jj];
                        cvv.z -= acc[2][jj]; cvv.w -= acc[3][jj];
                        *(float4*)(a + off) = cvv;
                    }

                    if (tj + 1 < ti) {
                        asm volatile("cp.async.wait_group 0;");
                        __syncthreads();
                    }
                }
            }
        }
        CLUSTER_SYNC();
    }
}

// ---------------------------------------------------------------------------
// Kernel 2a: invert 16 diagonal 32x32 blocks of U = L^T. One warp per (g,d).
// ---------------------------------------------------------------------------
__global__ __launch_bounds__(128, 8)
void diaginv_kernel()
{
    __shared__ float su[4][NB][NB + 1];
    __shared__ float sx[4][NB][NB + 1];

    const int g = blockIdx.x;
    const int w = threadIdx.x >> 5;
    const int d = blockIdx.y * 4 + w;
    const int cc = threadIdx.x & 31;
    const float* U = g_L + (size_t)g * DD2;
    const int b0 = d * NB;

    for (int rr = 0; rr < NB; ++rr)
        su[w][rr][cc] = U[(size_t)(b0 + rr) * DD + (b0 + cc)];
    __syncwarp();

    for (int t = cc; t >= 0; --t) {
        float s = (t == cc) ? 1.f : 0.f;
        for (int ss = t + 1; ss <= cc; ++ss)
            s -= su[w][t][ss] * sx[w][ss][cc];
        sx[w][t][cc] = s / su[w][t][t];
    }
    __syncwarp();

    float* dst = g_Dinv + ((size_t)g * 16 + d) * NB * NB;
    for (int t = 0; t < NB; ++t)
        dst[t * NB + cc] = (t <= cc) ? sx[w][t][cc] : 0.f;
}

// ---------------------------------------------------------------------------
// Kernel 2b: blocked triangular inverse + fused u + fused transposed fp16
// output. One CTA per (g, block-column j), largest j first, 512 threads.
// V kept TRANSPOSED in smem: Vst[col][k] = V[k][j*32+col] -> all V accesses
// are float4 on the k axis. T matrix also transposed for vectorized apply.
// smem: Vst[32][516] + Us[4][32][36] + Tst[32][36] + red[16][36]
// ---------------------------------------------------------------------------
#define T2_SMEM ((32*516 + 4*32*36 + 32*36 + 16*36) * 4)

__global__ __launch_bounds__(512)
void trinv_col_kernel(const float* __restrict__ mus)
{
    extern __shared__ float sm2[];
    float (*Vst)[516]   = (float(*)[516])sm2;
    float (*Us)[32][36] = (float(*)[32][36])(sm2 + 32 * 516);
    float (*Tst)[36]    = (float(*)[36])(sm2 + 32 * 516 + 4 * 32 * 36);
    float (*red)[36]    = (float(*)[36])(sm2 + 32 * 516 + 4 * 32 * 36 + 32 * 36);

    const int g = blockIdx.x;
    const int j = 15 - blockIdx.y;          // largest columns first
    const float* U = g_L + (size_t)g * DD2;
    const int tid = threadIdx.x;
    const int cc  = tid & 31;
    const int q   = tid >> 5;               // warp 0..15: rows q*2, q*2+1

    // diag block: Vst[cc][j*32+t] = Dinv[j][t][cc]
    {
        const float* din = g_Dinv + ((size_t)g * 16 + j) * NB * NB;
        #pragma unroll
        for (int r2 = 0; r2 < 2; ++r2) {
            const int t = q * 2 + r2;
            Vst[cc][j * NB + t] = din[t * NB + cc];
        }
    }
    __syncthreads();

    for (int i = j - 1; i >= 0; --i) {
        float acc0 = 0.f, acc1 = 0.f;

        for (int kc = i + 1; kc <= j; kc += 4) {
            const int nk = (j - kc + 1 < 4) ? (j - kc + 1) : 4;
            // stage nk U blocks (float4 per thread x2)
            #pragma unroll
            for (int e = 0; e < 2; ++e) {
                const int f = tid * 2 + e;           // 0..1023
                const int b = f >> 8;
                if (b < nk) {
                    const int rem = f & 255, rr = rem >> 3, t4 = rem & 7;
                    *(float4*)&Us[b][rr][t4 * 4] =
                        *(const float4*)&U[(size_t)(i * NB + rr) * DD + (kc + b) * NB + t4 * 4];
                }
            }
            __syncthreads();
            for (int b = 0; b < nk; ++b) {
                const int k = kc + b;
                #pragma unroll
                for (int t4 = 0; t4 < 8; ++t4) {
                    float4 vv = *(const float4*)&Vst[cc][k * NB + t4 * 4];
                    float4 u0 = *(const float4*)&Us[b][q * 2 + 0][t4 * 4];
                    float4 u1 = *(const float4*)&Us[b][q * 2 + 1][t4 * 4];
                    acc0 += u0.x * vv.x + u0.y * vv.y + u0.z * vv.z + u0.w * vv.w;
                    acc1 += u1.x * vv.x + u1.y * vv.y + u1.z * vv.z + u1.w * vv.w;
                }
            }
            __syncthreads();
        }

        // Tst[col][row] = T[row][col]
        Tst[cc][q * 2 + 0] = acc0;
        Tst[cc][q * 2 + 1] = acc1;
        if (tid < 256) {
            const int rr = tid >> 3, t4 = tid & 7;
            *(float4*)&Us[0][rr][t4 * 4] =
                *(const float4*)&g_Dinv[((size_t)g * 16 + i) * NB * NB + rr * NB + t4 * 4];
        }
        __syncthreads();

        float a20 = 0.f, a21 = 0.f;
        #pragma unroll
        for (int t4 = 0; t4 < 8; ++t4) {
            float4 tv = *(const float4*)&Tst[cc][t4 * 4];
            float4 u0 = *(const float4*)&Us[0][q * 2 + 0][t4 * 4];
            float4 u1 = *(const float4*)&Us[0][q * 2 + 1][t4 * 4];
            a20 += u0.x * tv.x + u0.y * tv.y + u0.z * tv.z + u0.w * tv.w;
            a21 += u1.x * tv.x + u1.y * tv.y + u1.z * tv.z + u1.w * tv.w;
        }
        Vst[cc][i * NB + q * 2 + 0] = -a20;
        Vst[cc][i * NB + q * 2 + 1] = -a21;
        __syncthreads();
    }

    // fused output: Wt[n][k] = V[k][j*32+n] = Vst[n][k], fp16 hi/lo,
    // zero-padded to the 128-tile boundary the GEMM reads.
    {
        __half* Whi = g_Wthi + (size_t)g * DD2;
        __half* Wlo = g_Wtlo + (size_t)g * DD2;
        const int kmax  = (j + 1) * NB;
        const int kfill = 128 * ((j >> 2) + 1);
        for (int nl = q; nl < NB; nl += 16) {
            const size_t nbase = (size_t)(j * NB + nl) * DD;
            for (int k = cc; k < kmax; k += 32) {
                float f = Vst[nl][k];
                __half h = __float2half(f);
                __half l = __float2half(f - __half2float(h));
                Whi[nbase + k] = h;
                Wlo[nbase + k] = l;
            }
            for (int k = kmax + cc; k < kfill; k += 32) {
                Whi[nbase + k] = __float2half(0.f);
                Wlo[nbase + k] = __float2half(0.f);
            }
        }
    }

    // fused u: u[j*32+cc] = sum_row mu[row] * V[row][j*32+cc]
    {
        const float* mu = mus + (size_t)g * DD;
        float s = 0.f;
        for (int row = q; row < (j + 1) * NB; row += 16)
            s += mu[row] * Vst[cc][row];
        red[q][cc] = s;
        __syncthreads();
        if (q == 0) {
            float tot = 0.f;
            #pragma unroll
            for (int w16 = 0; w16 < 16; ++w16) tot += red[w16][cc];
            g_u[(size_t)g * DD + j * NB + cc] = tot;
        }
    }
}

// ---------------------------------------------------------------------------
// Kernel 3: round X to fp16.
// ---------------------------------------------------------------------------
__global__ __launch_bounds__(256)
void split_x(const float* __restrict__ X)
{
    const int n = BSZ * DD / 4;
    for (int i = blockIdx.x * 256 + threadIdx.x; i < n; i += gridDim.x * 256) {
        float4 v = ((const float4*)X)[i];
        __half h[4] = {__float2half(v.x), __float2half(v.y),
                       __float2half(v.z), __float2half(v.w)};
        ((uint2*)g_Xh)[i] = *(uint2*)h;
    }
}

// ---------------------------------------------------------------------------
// Kernel 4: fp16 2-product GEMM via mma.sync + fused dist epilogue.
// NEW: per-warp triangular k-bound (stage s active iff s < nt*8 + 2*wn + 2);
// skipped products are exactly zero by Wt's 128-boundary zero padding.
// ---------------------------------------------------------------------------
#define PITCH_A 24
#define PITCH_B 40

__global__ __launch_bounds__(256, 2)
void mma_dist_kernel()
{
    __shared__ __align__(16) __half As[2][128][PITCH_A];
    __shared__ __align__(16) __half Bs[2][128][PITCH_B];
    __shared__ float sU[512];
    __shared__ float red[128][4];

    const int tid  = threadIdx.x;
    const int lane = tid & 31;
    const int wid  = tid >> 5;
    const int wm   = wid & 1;
    const int wn   = wid >> 1;
    const int g    = blockIdx.y;
    const int b0   = blockIdx.x * 128;

    for (int c = tid; c < 512; c += 256) sU[c] = g_u[(size_t)g * DD + c];

    const __half* Xh = g_Xh + (size_t)b0 * DD;
    const __half* Wh = g_Wthi + (size_t)g * DD2;
    const __half* Wl = g_Wtlo + (size_t)g * DD2;

    const uint32_t aS = (uint32_t)__cvta_generic_to_shared(&As[0][0][0]);
    const uint32_t bS = (uint32_t)__cvta_generic_to_shared(&Bs[0][0][0]);
    const uint32_t BUFA = 128 * PITCH_A * 2;
    const uint32_t BUFB = 128 * PITCH_B * 2;

    const int lrow = tid >> 1;
    const int hsel = tid & 1;
    const int brow = ((lane >> 4) << 3) + (lane & 7);
    const int bcol = ((lane >> 3) & 1) * 8;

    float distacc[8];
    #pragma unroll
    for (int i = 0; i < 8; ++i) distacc[i] = 0.f;

    for (int nt = 0; nt < 4; ++nt) {
        const int n0 = nt * 128;
        const int nsteps = (nt + 1) * 8;
        const int sbound = nt * 8 + 2 * wn + 2;   // triangular per-warp bound

        float acc[4][4][4];
        #pragma unroll
        for (int mt = 0; mt < 4; ++mt)
            #pragma unroll
            for (int jc = 0; jc < 4; ++jc)
                #pragma unroll
                for (int e = 0; e < 4; ++e) acc[mt][jc][e] = 0.f;

        {
            cp16(aS + lrow * (PITCH_A * 2) + hsel * 16,
                 Xh + (size_t)lrow * DD + hsel * 8);
            const uint32_t br = bS + lrow * (PITCH_B * 2);
            const __half* wh = Wh + (size_t)(n0 + lrow) * DD;
            const __half* wl = Wl + (size_t)(n0 + lrow) * DD;
            cp16(br + hsel * 16, wh + hsel * 8);
            cp16(br + 32 + hsel * 16, wl + hsel * 8);
            asm volatile("cp.async.commit_group;");
        }

        for (int s = 0; s < nsteps; ++s) {
            if (s + 1 < nsteps) {
                const int k0 = (s + 1) * 16;
                const uint32_t buf = (s + 1) & 1;
                cp16(aS + buf * BUFA + lrow * (PITCH_A * 2) + hsel * 16,
                     Xh + (size_t)lrow * DD + k0 + hsel * 8);
                const uint32_t br = bS + buf * BUFB + lrow * (PITCH_B * 2);
                const __half* wh = Wh + (size_t)(n0 + lrow) * DD + k0;
                const __half* wl = Wl + (size_t)(n0 + lrow) * DD + k0;
                cp16(br + hsel * 16, wh + hsel * 8);
                cp16(br + 32 + hsel * 16, wl + hsel * 8);
                asm volatile("cp.async.commit_group;");
                asm volatile("cp.async.wait_group 1;");
            } else {
                asm volatile("cp.async.wait_group 0;");
            }
            __syncthreads();

            if (s < sbound) {
                const uint32_t cur = s & 1;
                uint32_t ah[4][4];
                #pragma unroll
                for (int mt = 0; mt < 4; ++mt) {
                    const uint32_t ad = aS + cur * BUFA
                        + (uint32_t)((wm * 64 + mt * 16 + (lane & 15)) * (PITCH_A * 2))
                        + (uint32_t)((lane >> 4) * 16);
                    ldmx4(ah[mt], ad);
                }
                #pragma unroll
                for (int nb = 0; nb < 2; ++nb) {
                    uint32_t bh[4], bl[4];
                    const uint32_t bd = bS + cur * BUFB
                        + (uint32_t)((wn * 32 + nb * 16 + brow) * (PITCH_B * 2))
                        + (uint32_t)(bcol * 2);
                    ldmx4(bh, bd);
                    ldmx4(bl, bd + 32);
                    #pragma unroll
                    for (int mt = 0; mt < 4; ++mt) {
                        #pragma unroll
                        for (int h = 0; h < 2; ++h) {
                            float* d = acc[mt][nb * 2 + h];
                            mma16816h(d, ah[mt], &bh[h * 2]);
                            mma16816h(d, ah[mt], &bl[h * 2]);
                        }
                    }
                }
            }
            __syncthreads();
        }

        #pragma unroll
        for (int mt = 0; mt < 4; ++mt)
            #pragma unroll
            for (int jc = 0; jc < 4; ++jc) {
                const int coln = n0 + wn * 32 + (jc >> 1) * 16 + (jc & 1) * 8 + (lane & 3) * 2;
                const float u0 = sU[coln], u1 = sU[coln + 1];
                float z0 = acc[mt][jc][0] - u0, z1 = acc[mt][jc][1] - u1;
                float z2 = acc[mt][jc][2] - u0, z3 = acc[mt][jc][3] - u1;
                distacc[mt * 2 + 0] += z0 * z0 + z1 * z1;
                distacc[mt * 2 + 1] += z2 * z2 + z3 * z3;
            }
    }

    #pragma unroll
    for (int i = 0; i < 8; ++i) {
        distacc[i] += __shfl_xor_sync(0xffffffff, distacc[i], 1);
        distacc[i] += __shfl_xor_sync(0xffffffff, distacc[i], 2);
    }
    if ((lane & 3) == 0) {
        const int r = lane >> 2;
        #pragma unroll
        for (int mt = 0; mt < 4; ++mt) {
            red[wm * 64 + mt * 16 + r][wn]     = distacc[mt * 2 + 0];
            red[wm * 64 + mt * 16 + r + 8][wn] = distacc[mt * 2 + 1];
        }
    }
    __syncthreads();
    if (tid < 128)
        g_dist[(size_t)(b0 + tid) * GG + g] =
            red[tid][0] + red[tid][1] + red[tid][2] + red[tid][3];
}

// ---------------------------------------------------------------------------
// Kernel 5: out = -mean_b( min_g relu(dist[b,g]) ) / 10000
// ---------------------------------------------------------------------------
__global__ __launch_bounds__(256, 1)
void reduce_kernel(float* __restrict__ out)
{
    __shared__ float sh[256];
    float s = 0.f;
    for (int b = threadIdx.x; b < BSZ; b += 256) {
        const float* row = g_dist + (size_t)b * GG;
        float m = fmaxf(row[0], 0.f);
        #pragma unroll 8
        for (int gi = 1; gi < GG; ++gi)
            m = fminf(m, fmaxf(row[gi], 0.f));
        s += m;
    }
    sh[threadIdx.x] = s;
    __syncthreads();
    for (int off = 128; off > 0; off >>= 1) {
        if (threadIdx.x < off) sh[threadIdx.x] += sh[threadIdx.x + off];
        __syncthreads();
    }
    if (threadIdx.x == 0)
        out[0] = -sh[0] / ((float)BSZ * 10000.0f);
}

// ---------------------------------------------------------------------------
extern "C" void kernel_launch(void* const* d_in, const int* in_sizes, int n_in,
                              void* d_out, int out_size)
{
    const float* X    = nullptr;
    const float* mus  = nullptr;
    const float* covs = nullptr;
    for (int i = 0; i < n_in; ++i) {
        if      (in_sizes[i] == BSZ * DD)      X    = (const float*)d_in[i];
        else if (in_sizes[i] == GG * DD)       mus  = (const float*)d_in[i];
        else if (in_sizes[i] == GG * DD * DD)  covs = (const float*)d_in[i];
    }

    static bool attr_done = false;
    if (!attr_done) {
        cudaFuncSetAttribute(trinv_col_kernel,
                             cudaFuncAttributeMaxDynamicSharedMemorySize, T2_SMEM);
        cudaFuncSetAttribute(chol_fused,
                             cudaFuncAttributeMaxDynamicSharedMemorySize, CHOL_SMEM);
        attr_done = true;
    }

    split_x<<<512, 256>>>(X);
    chol_fused<<<GG * 2, 512, CHOL_SMEM>>>(covs);
    diaginv_kernel<<<dim3(GG, 4), 128>>>();
    trinv_col_kernel<<<dim3(GG, 16), 512, T2_SMEM>>>(mus);
    mma_dist_kernel<<<dim3(BSZ / 128, GG), 256>>>();
    reduce_kernel<<<1, 256>>>((float*)d_out);
}

// round 13
// speedup vs baseline: 8.1029x; 1.0301x over previous
#include <cuda_runtime.h>
#include <cuda_fp16.h>
#include <math.h>
#include <stdint.h>

// Problem sizes (fixed by the reference)
#define BSZ 2048
#define GG  64
#define DD  512
#define DD2 (DD * DD)
#define NB  32
#define PNL 64

// ---------------------------------------------------------------------------
// Scratch (device globals)
// g_L : per-gaussian Cholesky factor L, COLUMN-major (i>=j at j*DD+i).
//       Row-major view is U = L^T (valid at a*DD+b, b>=a).
// g_Wt*: transposed fp16-split inverse: Wt[n][k] = V[k][n], V = U^{-1}.
// g_Xh : X rounded to fp16 (GEMM computes dist of the rounded x exactly).
// ---------------------------------------------------------------------------
__device__ __align__(16) float g_L[GG * DD2];
__device__ __align__(16) float g_Dinv[GG * 16 * NB * NB];
__device__ __align__(16) float g_u[GG * DD];
__device__ __align__(16) float g_dist[BSZ * GG];
__device__ __align__(16) __half g_Xh[BSZ * DD];
__device__ __align__(16) __half g_Wthi[GG * DD2];
__device__ __align__(16) __half g_Wtlo[GG * DD2];

#define CLUSTER_SYNC() do { \
    asm volatile("barrier.cluster.arrive.aligned;" ::: "memory"); \
    asm volatile("barrier.cluster.wait.aligned;"   ::: "memory"); \
} while (0)

// ---------------------------------------------------------------------------
// mma.sync / cp.async helpers (portable sm_80+ path)
// ---------------------------------------------------------------------------
__device__ __forceinline__ void ldmx4(uint32_t* r, uint32_t addr) {
    asm volatile("ldmatrix.sync.aligned.m8n8.x4.shared.b16 {%0,%1,%2,%3}, [%4];"
                 : "=r"(r[0]), "=r"(r[1]), "=r"(r[2]), "=r"(r[3]) : "r"(addr));
}
__device__ __forceinline__ void mma16816h(float* d, const uint32_t* a, const uint32_t* b) {
    asm volatile(
        "mma.sync.aligned.m16n8k16.row.col.f32.f16.f16.f32 "
        "{%0,%1,%2,%3}, {%4,%5,%6,%7}, {%8,%9}, {%0,%1,%2,%3};"
        : "+f"(d[0]), "+f"(d[1]), "+f"(d[2]), "+f"(d[3])
        : "r"(a[0]), "r"(a[1]), "r"(a[2]), "r"(a[3]), "r"(b[0]), "r"(b[1]));
}
__device__ __forceinline__ void cp16(uint32_t s, const void* g) {
    asm volatile("cp.async.ca.shared.global [%0], [%1], 16;" :: "r"(s), "l"(g));
}

// ---------------------------------------------------------------------------
// Warp-level 32x32 Cholesky in REGISTERS (lane = row, shfl column broadcast).
// ---------------------------------------------------------------------------
__device__ __forceinline__ void warp_chol32(float (*s)[PNL + 1], int roff, int coff,
                                            float* rdiag)
{
    const int lane = threadIdx.x;   // caller guarantees tid < 32
    float x[32];
    #pragma unroll
    for (int j = 0; j < 32; ++j) x[j] = s[roff + lane][coff + j];

    float myrs = 0.f;
    #pragma unroll
    for (int k = 0; k < 32; ++k) {
        float dval = __shfl_sync(0xffffffffu, x[k], k);
        float rs = rsqrtf(dval);
        if (lane == k) { x[k] = dval * rs; myrs = rs; }
        float lik = (lane > k) ? x[k] * rs : 0.f;
        if (lane > k) x[k] = lik;
        #pragma unroll
        for (int j = k + 1; j < 32; ++j) {
            float ljk = __shfl_sync(0xffffffffu, lik, j);
            x[j] -= lik * ljk;
        }
    }
    #pragma unroll
    for (int j = 0; j < 32; ++j) s[roff + lane][coff + j] = x[j];
    rdiag[roff + lane] = myrs;
}

// ---------------------------------------------------------------------------
// Kernel 1: fused blocked Cholesky, NB=64 panels, cluster of 2 CTAs per
// gaussian, 512 threads, dynamic smem. SYRK uses cp.async double-buffered
// Pj (1 sync/tile), Pj column pairs loaded as float2.
// ---------------------------------------------------------------------------
#define CHOL_SMEM ((64*65 + 64 + 3*64*68) * 4)

__global__ __launch_bounds__(512) __cluster_dims__(2, 1, 1)
void chol_fused(const float* __restrict__ covs)
{
    extern __shared__ float smc[];
    float (*s11)[PNL + 1] = (float(*)[PNL + 1])smc;
    float* rdiag          = smc + 64 * 65;
    float (*Pi)[68]       = (float(*)[68])(smc + 64 * 65 + 64);
    float (*Pj0)[68]      = (float(*)[68])(smc + 64 * 65 + 64 + 64 * 68);
    float (*Pj1)[68]      = (float(*)[68])(smc + 64 * 65 + 64 + 2 * 64 * 68);

    const int g = blockIdx.x >> 1;
    unsigned crank;
    asm("mov.u32 %0, %%cluster_ctarank;" : "=r"(crank));
    float* a = g_L + (size_t)g * DD2;
    const float* cv = covs + (size_t)g * DD2;
    const int tid = threadIdx.x;

    const uint32_t sPi  = (uint32_t)__cvta_generic_to_shared(&Pi[0][0]);
    const uint32_t sPj0 = (uint32_t)__cvta_generic_to_shared(&Pj0[0][0]);
    const uint32_t sPj1 = (uint32_t)__cvta_generic_to_shared(&Pj1[0][0]);

    for (int p = 0; p < DD / PNL; ++p) {
        const int base = p * PNL;
        const int r = DD - base - PNL;
        const float* src = (p == 0) ? cv : a;

        // ---- load 64x64 diag block
        for (int q = tid; q < PNL * PNL; q += 512) {
            int i = q & 63, j = q >> 6;
            s11[i][j] = src[(size_t)(base + j) * DD + (base + i)];
        }
        __syncthreads();

        // ---- hierarchical diag factorization (reg-shfl)
        if (tid < 32) warp_chol32(s11, 0, 0, rdiag);
        __syncthreads();

        if (tid < 32) {
            const int row = 32 + tid;
            float x[32];
            #pragma unroll
            for (int j = 0; j < 32; ++j) x[j] = s11[row][j];
            #pragma unroll
            for (int j = 0; j < 32; ++j) {
                float s = x[j];
                #pragma unroll
                for (int k = 0; k < j; ++k)
                    s -= x[k] * s11[j][k];
                x[j] = s * rdiag[j];
            }
            #pragma unroll
            for (int j = 0; j < 32; ++j) s11[row][j] = x[j];
        }
        __syncthreads();

        #pragma unroll
        for (int e = 0; e < 2; ++e) {
            const int idx = tid + e * 512;
            const int i2 = 32 + (idx >> 5);
            const int j2 = 32 + (idx & 31);
            float s = 0.f;
            #pragma unroll
            for (int k = 0; k < 32; ++k)
                s += s11[i2][k] * s11[j2][k];
            s11[i2][j2] -= s;
        }
        __syncthreads();

        if (tid < 32) warp_chol32(s11, 32, 32, rdiag);
        __syncthreads();

        // ---- write factored diag back (lower incl diag)
        if (crank == 0) {
            for (int q = tid; q < PNL * PNL; q += 512) {
                int i = q & 63, j = q >> 6;
                if (i >= j) a[(size_t)(base + j) * DD + (base + i)] = s11[i][j];
            }
        }

        // ---- panel solve: my half of the rows, 1 reg-resident row/thread
        if (r > 0) {
            const int chunk = r >> 1;
            const int row = (int)crank * chunk + tid;
            if (row < r && tid < chunk) {
                const int gr = base + PNL + row;
                float x[PNL];
                #pragma unroll
                for (int j = 0; j < PNL; ++j)
                    x[j] = src[(size_t)(base + j) * DD + gr];
                #pragma unroll
                for (int j = 0; j < PNL; ++j) {
                    float s = x[j];
                    #pragma unroll
                    for (int k = 0; k < j; ++k)
                        s -= x[k] * s11[j][k];
                    x[j] = s * rdiag[j];
                }
                #pragma unroll
                for (int j = 0; j < PNL; ++j)
                    a[(size_t)(base + j) * DD + gr] = x[j];
            }
        }
        CLUSTER_SYNC();

        // ---- SYRK trailing update, 64x64 tiles, cp.async double-buffered
        if (r > 0) {
            const int m = r >> 6;
            for (int ti = (int)crank; ti < m; ti += 2) {
                const int gi = ti * 64;

                #pragma unroll
                for (int e = 0; e < 2; ++e) {
                    const int f = tid * 2 + e;
                    const int col = f >> 4, r4 = f & 15;
                    cp16(sPi + (uint32_t)((col * 68 + r4 * 4) * 4),
                         a + (size_t)(base + col) * DD + base + PNL + gi + r4 * 4);
                }
                if (ti > 0) {
                    #pragma unroll
                    for (int e = 0; e < 2; ++e) {
                        const int f = tid * 2 + e;
                        const int col = f >> 4, r4 = f & 15;
                        cp16(sPj0 + (uint32_t)((col * 68 + r4 * 4) * 4),
                             a + (size_t)(base + col) * DD + base + PNL + r4 * 4);
                    }
                }
                asm volatile("cp.async.commit_group;");
                asm volatile("cp.async.wait_group 0;");
                __syncthreads();

                for (int tj = 0; tj <= ti; ++tj) {
                    if (tj + 1 < ti) {
                        const int gjn = (tj + 1) * 64;
                        const uint32_t dstb = ((tj + 1) & 1) ? sPj1 : sPj0;
                        #pragma unroll
                        for (int e = 0; e < 2; ++e) {
                            const int f = tid * 2 + e;
                            const int col = f >> 4, r4 = f & 15;
                            cp16(dstb + (uint32_t)((col * 68 + r4 * 4) * 4),
                                 a + (size_t)(base + col) * DD + base + PNL + gjn + r4 * 4);
                        }
                        asm volatile("cp.async.commit_group;");
                    }

                    const int gj = tj * 64;
                    const float (*PJ)[68] = (tj == ti) ? Pi
                                           : ((tj & 1) ? Pj1 : Pj0);
                    const int tx = tid & 15;     // 4 rows
                    const int ty = tid >> 4;     // 0..31, 2 cols
                    float acc[4][2];
                    #pragma unroll
                    for (int ii = 0; ii < 4; ++ii) { acc[ii][0] = 0.f; acc[ii][1] = 0.f; }

                    #pragma unroll
                    for (int k = 0; k < PNL; ++k) {
                        float4 pi = *(const float4*)&Pi[k][tx * 4];
                        float2 pj = *(const float2*)&PJ[k][ty * 2];
                        float pr[4] = {pi.x, pi.y, pi.z, pi.w};
                        #pragma unroll
                        for (int ii = 0; ii < 4; ++ii) {
                            acc[ii][0] += pr[ii] * pj.x;
                            acc[ii][1] += pr[ii] * pj.y;
                        }
                    }

                    const int rowb = gi + tx * 4;
                    #pragma unroll
                    for (int jj = 0; jj < 2; ++jj) {
                        const int colg = gj + ty * 2 + jj;
                        const size_t off = (size_t)(base + PNL + colg) * DD + base + PNL + rowb;
                        float4 cvv = *(const float4*)(src + off);
                        cvv.x -= acc[0][jj]; cvv.y -= acc[1][jj];
                        cvv.z -= acc[2][jj]; cvv.w -= acc[3][jj];
                        *(float4*)(a + off) = cvv;
                    }

                    if (tj + 1 < ti) {
                        asm volatile("cp.async.wait_group 0;");
                        __syncthreads();
                    }
                }
            }
        }
        CLUSTER_SYNC();
    }
}

// ---------------------------------------------------------------------------
// Kernel 2a: invert 16 diagonal 32x32 blocks of U = L^T. One warp per (g,d).
// ---------------------------------------------------------------------------
__global__ __launch_bounds__(128, 8)
void diaginv_kernel()
{
    __shared__ float su[4][NB][NB + 1];
    __shared__ float sx[4][NB][NB + 1];

    const int g = blockIdx.x;
    const int w = threadIdx.x >> 5;
    const int d = blockIdx.y * 4 + w;
    const int cc = threadIdx.x & 31;
    const float* U = g_L + (size_t)g * DD2;
    const int b0 = d * NB;

    for (int rr = 0; rr < NB; ++rr)
        su[w][rr][cc] = U[(size_t)(b0 + rr) * DD + (b0 + cc)];
    __syncwarp();

    for (int t = cc; t >= 0; --t) {
        float s = (t == cc) ? 1.f : 0.f;
        for (int ss = t + 1; ss <= cc; ++ss)
            s -= su[w][t][ss] * sx[w][ss][cc];
        sx[w][t][cc] = s / su[w][t][t];
    }
    __syncwarp();

    float* dst = g_Dinv + ((size_t)g * 16 + d) * NB * NB;
    for (int t = 0; t < NB; ++t)
        dst[t * NB + cc] = (t <= cc) ? sx[w][t][cc] : 0.f;
}

// ---------------------------------------------------------------------------
// Kernel 2b: blocked triangular inverse + fused u + fused transposed fp16
// split output. One CTA per (g, block-column j), largest j first.
// (R11 version — measured best at 202us; R12 transposed layout regressed.)
// ---------------------------------------------------------------------------
#define T2_SMEM ((512*36 + 4*32*36 + 32*33) * 4)

__global__ __launch_bounds__(256)
void trinv_col_kernel(const float* __restrict__ mus)
{
    extern __shared__ float sm2[];
    float (*Vs)[36] = (float(*)[36])sm2;
    float (*Us)[32][36] = (float(*)[32][36])(sm2 + 512 * 36);
    float (*Ts)[33] = (float(*)[33])(sm2 + 512 * 36 + 4 * 32 * 36);

    const int g = blockIdx.x;
    const int j = 15 - blockIdx.y;
    const float* U = g_L + (size_t)g * DD2;
    const int tid = threadIdx.x;
    const int cc  = tid & 31;
    const int q   = tid >> 5;

    {
        const float* din = g_Dinv + ((size_t)g * 16 + j) * NB * NB;
        #pragma unroll
        for (int t4 = 0; t4 < 4; ++t4) {
            int t = q * 4 + t4;
            Vs[j * NB + t][cc] = din[t * NB + cc];
        }
    }
    __syncthreads();

    for (int i = j - 1; i >= 0; --i) {
        float acc[4];
        #pragma unroll
        for (int r4 = 0; r4 < 4; ++r4) acc[r4] = 0.f;

        for (int kc = i + 1; kc <= j; kc += 4) {
            const int nk = (j - kc + 1 < 4) ? (j - kc + 1) : 4;
            for (int b = 0; b < nk; ++b) {
                const float* ub = U + (size_t)(i * NB) * DD + (kc + b) * NB;
                const int rr = tid >> 3, t4 = tid & 7;
                *(float4*)&Us[b][rr][t4 * 4] = *(const float4*)&ub[(size_t)rr * DD + t4 * 4];
            }
            __syncthreads();
            for (int b = 0; b < nk; ++b) {
                const int k = kc + b;
                #pragma unroll
                for (int t4 = 0; t4 < 8; ++t4) {
                    float v0 = Vs[k * NB + t4 * 4 + 0][cc];
                    float v1 = Vs[k * NB + t4 * 4 + 1][cc];
                    float v2 = Vs[k * NB + t4 * 4 + 2][cc];
                    float v3 = Vs[k * NB + t4 * 4 + 3][cc];
                    #pragma unroll
                    for (int r4 = 0; r4 < 4; ++r4) {
                        float4 u4 = *(const float4*)&Us[b][q * 4 + r4][t4 * 4];
                        acc[r4] += u4.x * v0 + u4.y * v1 + u4.z * v2 + u4.w * v3;
                    }
                }
            }
            __syncthreads();
        }

        #pragma unroll
        for (int r4 = 0; r4 < 4; ++r4) Ts[q * 4 + r4][cc] = acc[r4];
        {
            const float* din = g_Dinv + ((size_t)g * 16 + i) * NB * NB;
            const int rr = tid >> 3, t4 = tid & 7;
            *(float4*)&Us[0][rr][t4 * 4] = *(const float4*)&din[rr * NB + t4 * 4];
        }
        __syncthreads();

        float acc2[4];
        #pragma unroll
        for (int r4 = 0; r4 < 4; ++r4) acc2[r4] = 0.f;
        #pragma unroll
        for (int t4 = 0; t4 < 8; ++t4) {
            float v0 = Ts[t4 * 4 + 0][cc];
            float v1 = Ts[t4 * 4 + 1][cc];
            float v2 = Ts[t4 * 4 + 2][cc];
            float v3 = Ts[t4 * 4 + 3][cc];
            #pragma unroll
            for (int r4 = 0; r4 < 4; ++r4) {
                float4 u4 = *(const float4*)&Us[0][q * 4 + r4][t4 * 4];
                acc2[r4] += u4.x * v0 + u4.y * v1 + u4.z * v2 + u4.w * v3;
            }
        }
        #pragma unroll
        for (int r4 = 0; r4 < 4; ++r4) Vs[i * NB + q * 4 + r4][cc] = -acc2[r4];
        __syncthreads();
    }

    // fused output: Wt[n][k] = V[k][n], fp16 hi/lo, zero-padded to 128-tile
    {
        __half* Whi = g_Wthi + (size_t)g * DD2;
        __half* Wlo = g_Wtlo + (size_t)g * DD2;
        const int kmax  = (j + 1) * NB;
        const int kfill = 128 * ((j >> 2) + 1);
        for (int nl = q; nl < NB; nl += 8) {
            const size_t nbase = (size_t)(j * NB + nl) * DD;
            for (int k = cc; k < kmax; k += 32) {
                float f = Vs[k][nl];
                __half h = __float2half(f);
                __half l = __float2half(f - __half2float(h));
                Whi[nbase + k] = h;
                Wlo[nbase + k] = l;
            }
            for (int k = kmax + cc; k < kfill; k += 32) {
                Whi[nbase + k] = __float2half(0.f);
                Wlo[nbase + k] = __float2half(0.f);
            }
        }
    }

    // fused u
    {
        const float* mu = mus + (size_t)g * DD;
        float s = 0.f;
        for (int row = q; row < (j + 1) * NB; row += 8)
            s += mu[row] * Vs[row][cc];
        __syncthreads();
        Ts[q][cc] = s;
        __syncthreads();
        if (q == 0) {
            float tot = 0.f;
            #pragma unroll
            for (int w8 = 0; w8 < 8; ++w8) tot += Ts[w8][cc];
            g_u[(size_t)g * DD + j * NB + cc] = tot;
        }
    }
}

// ---------------------------------------------------------------------------
// Kernel 3: round X to fp16.
// ---------------------------------------------------------------------------
__global__ __launch_bounds__(256)
void split_x(const float* __restrict__ X)
{
    const int n = BSZ * DD / 4;
    for (int i = blockIdx.x * 256 + threadIdx.x; i < n; i += gridDim.x * 256) {
        float4 v = ((const float4*)X)[i];
        __half h[4] = {__float2half(v.x), __float2half(v.y),
                       __float2half(v.z), __float2half(v.w)};
        ((uint2*)g_Xh)[i] = *(uint2*)h;
    }
}

// ---------------------------------------------------------------------------
// Kernel 4: fp16 2-product GEMM via mma.sync + fused dist epilogue.
// Per-warp triangular k-bound (skipped products exactly zero by padding).
// ---------------------------------------------------------------------------
#define PITCH_A 24
#define PITCH_B 40

__global__ __launch_bounds__(256, 2)
void mma_dist_kernel()
{
    __shared__ __align__(16) __half As[2][128][PITCH_A];
    __shared__ __align__(16) __half Bs[2][128][PITCH_B];
    __shared__ float sU[512];
    __shared__ float red[128][4];

    const int tid  = threadIdx.x;
    const int lane = tid & 31;
    const int wid  = tid >> 5;
    const int wm   = wid & 1;
    const int wn   = wid >> 1;
    const int g    = blockIdx.y;
    const int b0   = blockIdx.x * 128;

    for (int c = tid; c < 512; c += 256) sU[c] = g_u[(size_t)g * DD + c];

    const __half* Xh = g_Xh + (size_t)b0 * DD;
    const __half* Wh = g_Wthi + (size_t)g * DD2;
    const __half* Wl = g_Wtlo + (size_t)g * DD2;

    const uint32_t aS = (uint32_t)__cvta_generic_to_shared(&As[0][0][0]);
    const uint32_t bS = (uint32_t)__cvta_generic_to_shared(&Bs[0][0][0]);
    const uint32_t BUFA = 128 * PITCH_A * 2;
    const uint32_t BUFB = 128 * PITCH_B * 2;

    const int lrow = tid >> 1;
    const int hsel = tid & 1;
    const int brow = ((lane >> 4) << 3) + (lane & 7);
    const int bcol = ((lane >> 3) & 1) * 8;

    float distacc[8];
    #pragma unroll
    for (int i = 0; i < 8; ++i) distacc[i] = 0.f;

    for (int nt = 0; nt < 4; ++nt) {
        const int n0 = nt * 128;
        const int nsteps = (nt + 1) * 8;
        const int sbound = nt * 8 + 2 * wn + 2;

        float acc[4][4][4];
        #pragma unroll
        for (int mt = 0; mt < 4; ++mt)
            #pragma unroll
            for (int jc = 0; jc < 4; ++jc)
                #pragma unroll
                for (int e = 0; e < 4; ++e) acc[mt][jc][e] = 0.f;

        {
            cp16(aS + lrow * (PITCH_A * 2) + hsel * 16,
                 Xh + (size_t)lrow * DD + hsel * 8);
            const uint32_t br = bS + lrow * (PITCH_B * 2);
            const __half* wh = Wh + (size_t)(n0 + lrow) * DD;
            const __half* wl = Wl + (size_t)(n0 + lrow) * DD;
            cp16(br + hsel * 16, wh + hsel * 8);
            cp16(br + 32 + hsel * 16, wl + hsel * 8);
            asm volatile("cp.async.commit_group;");
        }

        for (int s = 0; s < nsteps; ++s) {
            if (s + 1 < nsteps) {
                const int k0 = (s + 1) * 16;
                const uint32_t buf = (s + 1) & 1;
                cp16(aS + buf * BUFA + lrow * (PITCH_A * 2) + hsel * 16,
                     Xh + (size_t)lrow * DD + k0 + hsel * 8);
                const uint32_t br = bS + buf * BUFB + lrow * (PITCH_B * 2);
                const __half* wh = Wh + (size_t)(n0 + lrow) * DD + k0;
                const __half* wl = Wl + (size_t)(n0 + lrow) * DD + k0;
                cp16(br + hsel * 16, wh + hsel * 8);
                cp16(br + 32 + hsel * 16, wl + hsel * 8);
                asm volatile("cp.async.commit_group;");
                asm volatile("cp.async.wait_group 1;");
            } else {
                asm volatile("cp.async.wait_group 0;");
            }
            __syncthreads();

            if (s < sbound) {
                const uint32_t cur = s & 1;
                uint32_t ah[4][4];
                #pragma unroll
                for (int mt = 0; mt < 4; ++mt) {
                    const uint32_t ad = aS + cur * BUFA
                        + (uint32_t)((wm * 64 + mt * 16 + (lane & 15)) * (PITCH_A * 2))
                        + (uint32_t)((lane >> 4) * 16);
                    ldmx4(ah[mt], ad);
                }
                #pragma unroll
                for (int nb = 0; nb < 2; ++nb) {
                    uint32_t bh[4], bl[4];
                    const uint32_t bd = bS + cur * BUFB
                        + (uint32_t)((wn * 32 + nb * 16 + brow) * (PITCH_B * 2))
                        + (uint32_t)(bcol * 2);
                    ldmx4(bh, bd);
                    ldmx4(bl, bd + 32);
                    #pragma unroll
                    for (int mt = 0; mt < 4; ++mt) {
                        #pragma unroll
                        for (int h = 0; h < 2; ++h) {
                            float* d = acc[mt][nb * 2 + h];
                            mma16816h(d, ah[mt], &bh[h * 2]);
                            mma16816h(d, ah[mt], &bl[h * 2]);
                        }
                    }
                }
            }
            __syncthreads();
        }

        #pragma unroll
        for (int mt = 0; mt < 4; ++mt)
            #pragma unroll
            for (int jc = 0; jc < 4; ++jc) {
                const int coln = n0 + wn * 32 + (jc >> 1) * 16 + (jc & 1) * 8 + (lane & 3) * 2;
                const float u0 = sU[coln], u1 = sU[coln + 1];
                float z0 = acc[mt][jc][0] - u0, z1 = acc[mt][jc][1] - u1;
                float z2 = acc[mt][jc][2] - u0, z3 = acc[mt][jc][3] - u1;
                distacc[mt * 2 + 0] += z0 * z0 + z1 * z1;
                distacc[mt * 2 + 1] += z2 * z2 + z3 * z3;
            }
    }

    #pragma unroll
    for (int i = 0; i < 8; ++i) {
        distacc[i] += __shfl_xor_sync(0xffffffff, distacc[i], 1);
        distacc[i] += __shfl_xor_sync(0xffffffff, distacc[i], 2);
    }
    if ((lane & 3) == 0) {
        const int r = lane >> 2;
        #pragma unroll
        for (int mt = 0; mt < 4; ++mt) {
            red[wm * 64 + mt * 16 + r][wn]     = distacc[mt * 2 + 0];
            red[wm * 64 + mt * 16 + r + 8][wn] = distacc[mt * 2 + 1];
        }
    }
    __syncthreads();
    if (tid < 128)
        g_dist[(size_t)(b0 + tid) * GG + g] =
            red[tid][0] + red[tid][1] + red[tid][2] + red[tid][3];
}

// ---------------------------------------------------------------------------
// Kernel 5: out = -mean_b( min_g relu(dist[b,g]) ) / 10000
// ---------------------------------------------------------------------------
__global__ __launch_bounds__(256, 1)
void reduce_kernel(float* __restrict__ out)
{
    __shared__ float sh[256];
    float s = 0.f;
    for (int b = threadIdx.x; b < BSZ; b += 256) {
        const float* row = g_dist + (size_t)b * GG;
        float m = fmaxf(row[0], 0.f);
        #pragma unroll 8
        for (int gi = 1; gi < GG; ++gi)
            m = fminf(m, fmaxf(row[gi], 0.f));
        s += m;
    }
    sh[threadIdx.x] = s;
    __syncthreads();
    for (int off = 128; off > 0; off >>= 1) {
        if (threadIdx.x < off) sh[threadIdx.x] += sh[threadIdx.x + off];
        __syncthreads();
    }
    if (threadIdx.x == 0)
        out[0] = -sh[0] / ((float)BSZ * 10000.0f);
}

// ---------------------------------------------------------------------------
extern "C" void kernel_launch(void* const* d_in, const int* in_sizes, int n_in,
                              void* d_out, int out_size)
{
    const float* X    = nullptr;
    const float* mus  = nullptr;
    const float* covs = nullptr;
    for (int i = 0; i < n_in; ++i) {
        if      (in_sizes[i] == BSZ * DD)      X    = (const float*)d_in[i];
        else if (in_sizes[i] == GG * DD)       mus  = (const float*)d_in[i];
        else if (in_sizes[i] == GG * DD * DD)  covs = (const float*)d_in[i];
    }

    static bool attr_done = false;
    if (!attr_done) {
        cudaFuncSetAttribute(trinv_col_kernel,
                             cudaFuncAttributeMaxDynamicSharedMemorySize, T2_SMEM);
        cudaFuncSetAttribute(chol_fused,
                             cudaFuncAttributeMaxDynamicSharedMemorySize, CHOL_SMEM);
        attr_done = true;
    }

    split_x<<<512, 256>>>(X);
    chol_fused<<<GG * 2, 512, CHOL_SMEM>>>(covs);
    diaginv_kernel<<<dim3(GG, 4), 128>>>();
    trinv_col_kernel<<<dim3(GG, 16), 256, T2_SMEM>>>(mus);
    mma_dist_kernel<<<dim3(BSZ / 128, GG), 256>>>();
    reduce_kernel<<<1, 256>>>((float*)d_out);
}